// round 1
// baseline (speedup 1.0000x reference)
#include <cuda_runtime.h>
#include <cuda_bf16.h>
#include <math_constants.h>

// ---------------------------------------------------------------------------
// Problem constants
// ---------------------------------------------------------------------------
#define Dm   512
#define Sm   64
#define Lm   256
#define Fm   2048
#define Hh   64
#define Cc   8
#define Pp   (Sm * Lm)          // 16384 spatial positions
#define EPS  1e-5f

// ---------------------------------------------------------------------------
// Scratch buffers (static device globals -- allocation-free)
// ---------------------------------------------------------------------------
__device__ float g_qkv   [3L * Dm * Pp];       // 1536 x 16384  (row qkv, then col qkv)
__device__ float g_scores[(long)Hh * Lm * Lm]; // 64 x 256 x 256 row-attn scores
__device__ float g_tmp   [(long)Dm * Pp];      // row_out / col_out / ff2_out
__device__ float g_out1  [(long)Dm * Pp];      // out1, later reused for h
__device__ float g_attn  [(long)Dm * Pp];      // attn_out
__device__ float g_ff    [(long)Fm * Pp];      // ff1 output (relu'd)

// ---------------------------------------------------------------------------
// Generic tiled SGEMM: C[M,N] = op(A) * op(B) (+bias[m]) (+relu), batched.
//   TA=false: A is [M,K] row-major.  TA=true: A is [K,M] row-major.
//   TB=false: B is [K,N] row-major.  TB=true: B is [N,K] row-major.
// Tile 128x128, BK=16, 256 threads, 8x8 per thread.
// ---------------------------------------------------------------------------
template<bool TA, bool TB, bool RELU, bool BIAS>
__global__ __launch_bounds__(256)
void sgemm_kernel(const float* __restrict__ Ag, const float* __restrict__ Bg,
                  const float* __restrict__ bias, float* __restrict__ Cg,
                  int M, int N, int K,
                  long sA, long sB, long sC)
{
    __shared__ float As[16][132];
    __shared__ float Bs[16][132];

    const int bm = blockIdx.y * 128;
    const int bn = blockIdx.x * 128;
    const float* A = Ag + (long)blockIdx.z * sA;
    const float* B = Bg + (long)blockIdx.z * sB;
    float*       C = Cg + (long)blockIdx.z * sC;

    const int tid = threadIdx.x;
    const int tx  = tid & 15;    // n
    const int ty  = tid >> 4;    // m

    const int lda = TA ? M : K;
    const int ldb = TB ? K : N;

    float acc[8][8];
#pragma unroll
    for (int i = 0; i < 8; i++)
#pragma unroll
        for (int j = 0; j < 8; j++) acc[i][j] = 0.f;

    for (int k0 = 0; k0 < K; k0 += 16) {
        if (TA) {
#pragma unroll
            for (int r = 0; r < 2; r++) {
                int id = tid + r * 256;            // 0..511
                int k  = id >> 5;                  // 0..15
                int m4 = (id & 31) << 2;           // 0..124
                float4 v = *reinterpret_cast<const float4*>(&A[(long)(k0 + k) * lda + bm + m4]);
                *reinterpret_cast<float4*>(&As[k][m4]) = v;
            }
        } else {
#pragma unroll
            for (int r = 0; r < 2; r++) {
                int id = tid + r * 256;
                int m  = id >> 2;                  // 0..127
                int k4 = (id & 3) << 2;            // 0,4,8,12
                float4 v = *reinterpret_cast<const float4*>(&A[(long)(bm + m) * lda + k0 + k4]);
                As[k4 + 0][m] = v.x; As[k4 + 1][m] = v.y;
                As[k4 + 2][m] = v.z; As[k4 + 3][m] = v.w;
            }
        }
        if (TB) {
#pragma unroll
            for (int r = 0; r < 2; r++) {
                int id = tid + r * 256;
                int n  = id >> 2;
                int k4 = (id & 3) << 2;
                float4 v = *reinterpret_cast<const float4*>(&B[(long)(bn + n) * ldb + k0 + k4]);
                Bs[k4 + 0][n] = v.x; Bs[k4 + 1][n] = v.y;
                Bs[k4 + 2][n] = v.z; Bs[k4 + 3][n] = v.w;
            }
        } else {
#pragma unroll
            for (int r = 0; r < 2; r++) {
                int id = tid + r * 256;
                int k  = id >> 5;
                int n4 = (id & 31) << 2;
                float4 v = *reinterpret_cast<const float4*>(&B[(long)(k0 + k) * ldb + bn + n4]);
                *reinterpret_cast<float4*>(&Bs[k][n4]) = v;
            }
        }
        __syncthreads();

#pragma unroll
        for (int kk = 0; kk < 16; kk++) {
            float ra[8], rb[8];
#pragma unroll
            for (int w = 0; w < 4; w++) {
                ra[w]     = As[kk][ty * 4 + w];
                ra[4 + w] = As[kk][64 + ty * 4 + w];
                rb[w]     = Bs[kk][tx * 4 + w];
                rb[4 + w] = Bs[kk][64 + tx * 4 + w];
            }
#pragma unroll
            for (int i = 0; i < 8; i++)
#pragma unroll
                for (int j = 0; j < 8; j++)
                    acc[i][j] = fmaf(ra[i], rb[j], acc[i][j]);
        }
        __syncthreads();
    }

#pragma unroll
    for (int i = 0; i < 8; i++) {
        int m = bm + ((i < 4) ? (ty * 4 + i) : (64 + ty * 4 + (i - 4)));
        float bv = BIAS ? bias[m] : 0.f;
#pragma unroll
        for (int jh = 0; jh < 2; jh++) {
            float4 v;
            v.x = acc[i][jh * 4 + 0] + bv;
            v.y = acc[i][jh * 4 + 1] + bv;
            v.z = acc[i][jh * 4 + 2] + bv;
            v.w = acc[i][jh * 4 + 3] + bv;
            if (RELU) {
                v.x = fmaxf(v.x, 0.f); v.y = fmaxf(v.y, 0.f);
                v.z = fmaxf(v.z, 0.f); v.w = fmaxf(v.w, 0.f);
            }
            *reinterpret_cast<float4*>(&C[(long)m * N + bn + jh * 64 + tx * 4]) = v;
        }
    }
}

// ---------------------------------------------------------------------------
// Row softmax over last axis: 16384 rows of 256 (g_scores)
// ---------------------------------------------------------------------------
__global__ __launch_bounds__(256)
void softmax_kernel(float* __restrict__ S)
{
    __shared__ float red[8];
    const long row = blockIdx.x;
    float* p = S + row * 256;
    const int t = threadIdx.x;
    const int lane = t & 31, warp = t >> 5;

    float v = p[t];
    float m = v;
#pragma unroll
    for (int o = 16; o; o >>= 1) m = fmaxf(m, __shfl_xor_sync(0xffffffffu, m, o));
    if (lane == 0) red[warp] = m;
    __syncthreads();
    float mm = red[0];
#pragma unroll
    for (int i = 1; i < 8; i++) mm = fmaxf(mm, red[i]);
    __syncthreads();

    float e = __expf(v - mm);
    float s = e;
#pragma unroll
    for (int o = 16; o; o >>= 1) s += __shfl_xor_sync(0xffffffffu, s, o);
    if (lane == 0) red[warp] = s;
    __syncthreads();
    float tot = 0.f;
#pragma unroll
    for (int i = 0; i < 8; i++) tot += red[i];

    p[t] = e / tot;
}

// ---------------------------------------------------------------------------
// Channel LayerNorm over D=512 at each of 16384 positions (optional residual)
//   y[c,pos] = ((in+res)[c,pos] - mean)*rsqrt(var+eps)*w[c] + b[c]
// ---------------------------------------------------------------------------
__global__ __launch_bounds__(128)
void ln_kernel(const float* __restrict__ in, const float* __restrict__ res,
               const float* __restrict__ w, const float* __restrict__ b,
               float* __restrict__ out)
{
    const int pos = blockIdx.x * 128 + threadIdx.x;
    float s = 0.f, s2 = 0.f;
    if (res) {
        for (int c = 0; c < Dm; c++) {
            float v = in[(long)c * Pp + pos] + res[(long)c * Pp + pos];
            s += v; s2 += v * v;
        }
    } else {
        for (int c = 0; c < Dm; c++) {
            float v = in[(long)c * Pp + pos];
            s += v; s2 += v * v;
        }
    }
    const float mean = s * (1.f / Dm);
    const float var  = s2 * (1.f / Dm) - mean * mean;
    const float rstd = rsqrtf(var + EPS);
    if (res) {
        for (int c = 0; c < Dm; c++) {
            float v = in[(long)c * Pp + pos] + res[(long)c * Pp + pos];
            out[(long)c * Pp + pos] = (v - mean) * rstd * w[c] + b[c];
        }
    } else {
        for (int c = 0; c < Dm; c++) {
            float v = in[(long)c * Pp + pos];
            out[(long)c * Pp + pos] = (v - mean) * rstd * w[c] + b[c];
        }
    }
}

// ---------------------------------------------------------------------------
// Column attention: per (h,l), tiny 64x64 attention over 8 channels.
// Online softmax, one thread per (i, l) pair (2 i's per thread).
// grid: (L/32, 1, H), block: (32 l, 32 y)
// ---------------------------------------------------------------------------
__global__ __launch_bounds__(1024)
void colattn_kernel(const float* __restrict__ qkv, float* __restrict__ out)
{
    const int h = blockIdx.z;
    const int l = blockIdx.x * 32 + threadIdx.x;
    const float* Q  = qkv + (long)h * Cc * Pp;
    const float* Kp = Q + (long)Dm * Pp;
    const float* V  = Q + 2L * Dm * Pp;

#pragma unroll
    for (int ii = 0; ii < 2; ii++) {
        const int i = threadIdx.y + 32 * ii;
        float q[Cc];
#pragma unroll
        for (int c = 0; c < Cc; c++) q[c] = Q[(long)c * Pp + i * Lm + l];

        float m = -CUDART_INF_F, d = 0.f;
        float acc[Cc];
#pragma unroll
        for (int c = 0; c < Cc; c++) acc[c] = 0.f;

        for (int j = 0; j < Sm; j++) {
            float sc = 0.f;
#pragma unroll
            for (int c = 0; c < Cc; c++)
                sc = fmaf(q[c], Kp[(long)c * Pp + j * Lm + l], sc);
            const float mn = fmaxf(m, sc);
            const float scale = __expf(m - mn);
            const float pj = __expf(sc - mn);
            d = d * scale + pj;
#pragma unroll
            for (int c = 0; c < Cc; c++)
                acc[c] = fmaf(acc[c], scale, pj * V[(long)c * Pp + j * Lm + l]);
            m = mn;
        }
        const float inv = 1.f / d;
#pragma unroll
        for (int c = 0; c < Cc; c++)
            out[(long)(h * Cc + c) * Pp + i * Lm + l] = acc[c] * inv;
    }
}

// ---------------------------------------------------------------------------
// Launch sequence
// ---------------------------------------------------------------------------
extern "C" void kernel_launch(void* const* d_in, const int* in_sizes, int n_in,
                              void* d_out, int out_size)
{
    const float* x     = (const float*)d_in[0];
    const float* w_row = (const float*)d_in[1];
    const float* b_row = (const float*)d_in[2];
    const float* w_col = (const float*)d_in[3];
    const float* b_col = (const float*)d_in[4];
    const float* w_an1 = (const float*)d_in[5];
    const float* b_an1 = (const float*)d_in[6];
    const float* w_an2 = (const float*)d_in[7];
    const float* b_an2 = (const float*)d_in[8];
    const float* w_ff1 = (const float*)d_in[9];
    const float* b_ff1 = (const float*)d_in[10];
    const float* w_ff2 = (const float*)d_in[11];
    const float* b_ff2 = (const float*)d_in[12];
    const float* w_ln1 = (const float*)d_in[13];
    const float* b_ln1 = (const float*)d_in[14];
    const float* w_ln2 = (const float*)d_in[15];
    const float* b_ln2 = (const float*)d_in[16];
    float* outp = (float*)d_out;

    float *qkv, *scores, *tmp, *out1, *attn, *ff;
    cudaGetSymbolAddress((void**)&qkv,    g_qkv);
    cudaGetSymbolAddress((void**)&scores, g_scores);
    cudaGetSymbolAddress((void**)&tmp,    g_tmp);
    cudaGetSymbolAddress((void**)&out1,   g_out1);
    cudaGetSymbolAddress((void**)&attn,   g_attn);
    cudaGetSymbolAddress((void**)&ff,     g_ff);

    const long headQK = (long)Cc * Pp;     // per-head stride within q/k/v blocks

    // 1) row qkv = w_row @ x + b_row     [1536 x 16384]
    sgemm_kernel<false,false,false,true><<<dim3(Pp/128, (3*Dm)/128, 1), 256>>>(
        w_row, x, b_row, qkv, 3*Dm, Pp, Dm, 0, 0, 0);

    // 2) row scores = Q_h^T K_h per head  [64 x 256 x 256]
    sgemm_kernel<true,false,false,false><<<dim3(Lm/128, Lm/128, Hh), 256>>>(
        qkv, qkv + (long)Dm * Pp, nullptr, scores,
        Lm, Lm, Cc*Sm, headQK, headQK, (long)Lm*Lm);

    // 3) softmax over j
    softmax_kernel<<<Hh * Lm, 256>>>(scores);

    // 4) row_out_h = V_h * P_h^T   [per head 512 x 256]
    sgemm_kernel<false,true,false,false><<<dim3(Lm/128, (Cc*Sm)/128, Hh), 256>>>(
        qkv + 2L * Dm * Pp, scores, nullptr, tmp,
        Cc*Sm, Lm, Lm, headQK, (long)Lm*Lm, headQK);

    // 5) out1 = LN(x + row_out; an1)
    ln_kernel<<<Pp/128, 128>>>(x, tmp, w_an1, b_an1, out1);

    // 6) col qkv = w_col @ out1 + b_col
    sgemm_kernel<false,false,false,true><<<dim3(Pp/128, (3*Dm)/128, 1), 256>>>(
        w_col, out1, b_col, qkv, 3*Dm, Pp, Dm, 0, 0, 0);

    // 7) column attention -> tmp
    colattn_kernel<<<dim3(Lm/32, 1, Hh), dim3(32, 32)>>>(qkv, tmp);

    // 8) attn_out = LN(out1 + col_out; an2)
    ln_kernel<<<Pp/128, 128>>>(out1, tmp, w_an2, b_an2, attn);

    // 9) h = LN(attn_out; ln1)   (out1 reused as h)
    ln_kernel<<<Pp/128, 128>>>(attn, nullptr, w_ln1, b_ln1, out1);

    // 10) ff1 = relu(w_ff1 @ h + b_ff1)   [2048 x 16384]
    sgemm_kernel<false,false,true,true><<<dim3(Pp/128, Fm/128, 1), 256>>>(
        w_ff1, out1, b_ff1, ff, Fm, Pp, Dm, 0, 0, 0);

    // 11) ff2 = w_ff2 @ ff1 + b_ff2       [512 x 16384]
    sgemm_kernel<false,false,false,true><<<dim3(Pp/128, Dm/128, 1), 256>>>(
        w_ff2, ff, b_ff2, tmp, Dm, Pp, Fm, 0, 0, 0);

    // 12) out = LN(h + ff2; ln2)
    ln_kernel<<<Pp/128, 128>>>(out1, tmp, w_ln2, b_ln2, outp);
}

// round 3
// speedup vs baseline: 1.6107x; 1.6107x over previous
#include <cuda_runtime.h>
#include <cuda_bf16.h>
#include <math_constants.h>
#include <cstdint>
#include <cstddef>

// ---------------------------------------------------------------------------
// Problem constants
// ---------------------------------------------------------------------------
#define Dm   512
#define Sm   64
#define Lm   256
#define Fm   2048
#define Hh   64
#define Cc   8
#define Pp   (Sm * Lm)          // 16384 spatial positions
#define EPS  1e-5f

// ---------------------------------------------------------------------------
// Scratch buffers (static device globals -- allocation-free)
// ---------------------------------------------------------------------------
__device__ __align__(256) float g_qkv   [3L * Dm * Pp];       // 1536 x 16384
__device__ __align__(256) float g_scores[(long)Hh * Lm * Lm]; // 64 x 256 x 256
__device__ __align__(256) float g_tmp   [(long)Dm * Pp];
__device__ __align__(256) float g_out1  [(long)Dm * Pp];
__device__ __align__(256) float g_attn  [(long)Dm * Pp];

// bf16 hi/lo operands for tensor-core GEMMs
__device__ __align__(256) __nv_bfloat16 g_bth[(long)Pp * Dm], g_btl[(long)Pp * Dm]; // act^T [Pp,512]
__device__ __align__(256) __nv_bfloat16 g_ffh[(long)Pp * Fm], g_ffl[(long)Pp * Fm]; // ff1^T [Pp,2048]
__device__ __align__(256) __nv_bfloat16 g_wrh[3 * Dm * Dm],  g_wrl[3 * Dm * Dm];
__device__ __align__(256) __nv_bfloat16 g_wch[3 * Dm * Dm],  g_wcl[3 * Dm * Dm];
__device__ __align__(256) __nv_bfloat16 g_f1h[Fm * Dm],      g_f1l[Fm * Dm];
__device__ __align__(256) __nv_bfloat16 g_f2h[Dm * Fm],      g_f2l[Dm * Fm];

// ---------------------------------------------------------------------------
// PTX helpers (baseline ISA only: cp.async / ldmatrix / mma.sync)
// ---------------------------------------------------------------------------
__device__ __forceinline__ uint32_t smem_u32(const void* p) {
    uint32_t a;
    asm("{ .reg .u64 t; cvta.to.shared.u64 t, %1; cvt.u32.u64 %0, t; }" : "=r"(a) : "l"(p));
    return a;
}
__device__ __forceinline__ void cpasync16(uint32_t dst, const void* src) {
    asm volatile("cp.async.cg.shared.global [%0], [%1], 16;" :: "r"(dst), "l"(src));
}
__device__ __forceinline__ void cp_commit() {
    asm volatile("cp.async.commit_group;" ::: "memory");
}
template<int N>
__device__ __forceinline__ void cp_wait() {
    asm volatile("cp.async.wait_group %0;" :: "n"(N) : "memory");
}
__device__ __forceinline__ void ldsm4(uint32_t* r, uint32_t addr) {
    asm volatile("ldmatrix.sync.aligned.m8n8.x4.shared.b16 {%0,%1,%2,%3}, [%4];"
                 : "=r"(r[0]), "=r"(r[1]), "=r"(r[2]), "=r"(r[3]) : "r"(addr));
}
__device__ __forceinline__ void mma16816(float* d, const uint32_t* a, uint32_t b0, uint32_t b1) {
    asm volatile("mma.sync.aligned.m16n8k16.row.col.f32.bf16.bf16.f32 "
                 "{%0,%1,%2,%3}, {%4,%5,%6,%7}, {%8,%9}, {%0,%1,%2,%3};"
                 : "+f"(d[0]), "+f"(d[1]), "+f"(d[2]), "+f"(d[3])
                 : "r"(a[0]), "r"(a[1]), "r"(a[2]), "r"(a[3]), "r"(b0), "r"(b1));
}

// ---------------------------------------------------------------------------
// bf16 hi/lo tensor-core GEMM: C[M,N] = A[M,K] * Bt[N,K]^T (+bias)
//   MODE 0: C fp32 [M,N], += bias[m]
//   MODE 1: relu(+bias) -> bf16 hi/lo, TRANSPOSED [N,M] (smem-staged)
// CTA tile 128x128, BK=64, 3-stage cp.async ring, 8 warps (4m x 2n), warp 32x64.
// SMEM per stage: Ah,Al,Bh,Bl each 128x64 bf16 (16KB), SW128 swizzled.
// ---------------------------------------------------------------------------
#define MM_STAGES 3
#define MM_STAGE_BYTES 65536
#define MM_SMEM (MM_STAGES * MM_STAGE_BYTES)

template<int MODE>
__global__ void __launch_bounds__(256, 1)
gemm_mma(const __nv_bfloat16* __restrict__ Ah, const __nv_bfloat16* __restrict__ Al,
         const __nv_bfloat16* __restrict__ Bh, const __nv_bfloat16* __restrict__ Bl,
         const float* __restrict__ bias,
         float* __restrict__ C,
         __nv_bfloat16* __restrict__ oH, __nv_bfloat16* __restrict__ oL,
         int M, int N, int K)
{
    extern __shared__ char smem[];
    const uint32_t sb = smem_u32(smem);

    const int tid  = threadIdx.x;
    const int wid  = tid >> 5;
    const int lane = tid & 31;
    const int warpM = wid & 3;          // 4 row-warps, 32 rows each
    const int warpN = wid >> 2;         // 2 col-warps, 64 cols each
    const int bm = blockIdx.x * 128;
    const int bn = blockIdx.y * 128;

    // ---- stage loader: 16 x cp.async(16B) per thread ----
    auto load_stage = [&](int st, int it) {
        const uint32_t sbase = sb + st * MM_STAGE_BYTES;
        const int k0 = it << 6;
#pragma unroll
        for (int j = 0; j < 4; j++) {
            const int idx = tid + j * 256;          // 0..1023
            const int row = idx >> 3;               // 0..127
            const int c   = idx & 7;                // 16B chunk in 128B row
            const uint32_t soff = row * 128 + ((c * 16) ^ ((row & 7) << 4));
            const size_t ga = (size_t)(bm + row) * K + k0 + c * 8;
            const size_t gb = (size_t)(bn + row) * K + k0 + c * 8;
            cpasync16(sbase +         soff, Ah + ga);
            cpasync16(sbase + 16384 + soff, Al + ga);
            cpasync16(sbase + 32768 + soff, Bh + gb);
            cpasync16(sbase + 49152 + soff, Bl + gb);
        }
    };

    float acc[2][8][4];
#pragma unroll
    for (int i = 0; i < 2; i++)
#pragma unroll
        for (int j = 0; j < 8; j++)
#pragma unroll
            for (int v = 0; v < 4; v++) acc[i][j][v] = 0.f;

    const int nIter = K >> 6;

    load_stage(0, 0); cp_commit();
    load_stage(1, 1); cp_commit();

    // per-thread ldmatrix addressing (same formula for A and B tiles)
    const int rsub  = lane & 15;                  // row within 16-row tile
    const int khalf = ((lane >> 4) & 1) * 16;     // 16B half of the k16 slab
    const int rA = warpM * 32 + rsub;             // A row in [0,128)
    const int rB = warpN * 64 + rsub;             // B row in [0,128)
    const uint32_t xA = (rA & 7) << 4;            // swizzle XOR (row low bits)
    const uint32_t xB = (rB & 7) << 4;

    for (int it = 0; it < nIter; it++) {
        cp_wait<1>();
        __syncthreads();
        const uint32_t sbase = sb + (it % MM_STAGES) * MM_STAGE_BYTES;
        const uint32_t pA = sbase +         rA * 128;
        const uint32_t pB = sbase + 32768 + rB * 128;

#pragma unroll
        for (int q = 0; q < 4; q++) {
            const uint32_t kb = q * 32 + khalf;
            uint32_t ah[2][4], al[2][4], bh[4][4], bl[4][4];
#pragma unroll
            for (int mt = 0; mt < 2; mt++) {
                ldsm4(ah[mt], pA         + mt * 2048 + (kb ^ xA));
                ldsm4(al[mt], pA + 16384 + mt * 2048 + (kb ^ xA));
            }
#pragma unroll
            for (int g = 0; g < 4; g++) {
                ldsm4(bh[g], pB         + g * 2048 + (kb ^ xB));
                ldsm4(bl[g], pB + 16384 + g * 2048 + (kb ^ xB));
            }
#pragma unroll
            for (int mt = 0; mt < 2; mt++)
#pragma unroll
                for (int nt = 0; nt < 8; nt++) {
                    const int g = nt >> 1, o = nt & 1;
                    mma16816(acc[mt][nt], ah[mt], bh[g][o], bh[g][o + 2]); // Ah*Bh
                    mma16816(acc[mt][nt], ah[mt], bl[g][o], bl[g][o + 2]); // Ah*Bl
                    mma16816(acc[mt][nt], al[mt], bh[g][o], bh[g][o + 2]); // Al*Bh
                }
        }
        __syncthreads();
        if (it + 2 < nIter) load_stage((it + 2) % MM_STAGES, it + 2);
        cp_commit();
    }
    cp_wait<0>();
    __syncthreads();

    if (MODE == 0) {
#pragma unroll
        for (int mt = 0; mt < 2; mt++) {
            const int r0 = bm + warpM * 32 + mt * 16 + (lane >> 2);
            const float bv0 = bias[r0], bv1 = bias[r0 + 8];
#pragma unroll
            for (int nt = 0; nt < 8; nt++) {
                const int c0 = bn + warpN * 64 + nt * 8 + (lane & 3) * 2;
                float* d = acc[mt][nt];
                float2 v0 = make_float2(d[0] + bv0, d[1] + bv0);
                float2 v1 = make_float2(d[2] + bv1, d[3] + bv1);
                *reinterpret_cast<float2*>(&C[(size_t)r0 * N + c0]) = v0;
                *reinterpret_cast<float2*>(&C[(size_t)(r0 + 8) * N + c0]) = v1;
            }
        }
    } else {
        // bias + relu, stage through smem, emit transposed bf16 hi/lo [N,M]
        float* T = reinterpret_cast<float*>(smem);   // [128][130]
#pragma unroll
        for (int mt = 0; mt < 2; mt++) {
            const int lr0 = warpM * 32 + mt * 16 + (lane >> 2);
            const float bv0 = bias[bm + lr0], bv1 = bias[bm + lr0 + 8];
#pragma unroll
            for (int nt = 0; nt < 8; nt++) {
                const int lc0 = warpN * 64 + nt * 8 + (lane & 3) * 2;
                float* d = acc[mt][nt];
                T[lr0 * 130 + lc0]           = fmaxf(d[0] + bv0, 0.f);
                T[lr0 * 130 + lc0 + 1]       = fmaxf(d[1] + bv0, 0.f);
                T[(lr0 + 8) * 130 + lc0]     = fmaxf(d[2] + bv1, 0.f);
                T[(lr0 + 8) * 130 + lc0 + 1] = fmaxf(d[3] + bv1, 0.f);
            }
        }
        __syncthreads();
        const int mloc = tid & 127;
#pragma unroll 4
        for (int rep = 0; rep < 64; rep++) {
            const int nl = rep * 2 + (tid >> 7);
            const float v = T[mloc * 130 + nl];
            const __nv_bfloat16 h = __float2bfloat16(v);
            const float lo = v - __bfloat162float(h);
            const size_t o = (size_t)(bn + nl) * M + bm + mloc;
            oH[o] = h;
            oL[o] = __float2bfloat16(lo);
        }
    }
}

// ---------------------------------------------------------------------------
// fp32 -> bf16 hi/lo conversions
// ---------------------------------------------------------------------------
__global__ void convw_kernel(const float* __restrict__ w,
                             __nv_bfloat16* __restrict__ oh, __nv_bfloat16* __restrict__ ol, int n)
{
    int i = blockIdx.x * 256 + threadIdx.x;
    if (i < n) {
        float v = w[i];
        __nv_bfloat16 h = __float2bfloat16(v);
        oh[i] = h;
        ol[i] = __float2bfloat16(v - __bfloat162float(h));
    }
}

// transpose-convert: in fp32 [K, N] -> out bf16 hi/lo [N, K]
__global__ void __launch_bounds__(256)
convt_kernel(const float* __restrict__ in,
             __nv_bfloat16* __restrict__ oh, __nv_bfloat16* __restrict__ ol,
             int K, int N)
{
    __shared__ float t[32][33];
    const int n0 = blockIdx.x * 32, k0 = blockIdx.y * 32;
    const int tx = threadIdx.x, ty = threadIdx.y;  // 32 x 8
#pragma unroll
    for (int i = 0; i < 4; i++)
        t[ty + 8 * i][tx] = in[(size_t)(k0 + ty + 8 * i) * N + n0 + tx];
    __syncthreads();
#pragma unroll
    for (int i = 0; i < 4; i++) {
        const int r = ty + 8 * i;           // local n
        float v = t[tx][r];                 // in[k0+tx][n0+r]
        __nv_bfloat16 h = __float2bfloat16(v);
        size_t o = (size_t)(n0 + r) * K + k0 + tx;
        oh[o] = h;
        ol[o] = __float2bfloat16(v - __bfloat162float(h));
    }
}

// ---------------------------------------------------------------------------
// SGEMM for the attention GEMMs
// ---------------------------------------------------------------------------
template<bool TA, bool TB>
__global__ __launch_bounds__(256)
void sgemm_kernel(const float* __restrict__ Ag, const float* __restrict__ Bg,
                  float* __restrict__ Cg, int M, int N, int K,
                  long sA, long sB, long sC)
{
    __shared__ float As[16][132];
    __shared__ float Bs[16][132];

    const int bm = blockIdx.y * 128;
    const int bn = blockIdx.x * 128;
    const float* A = Ag + (long)blockIdx.z * sA;
    const float* B = Bg + (long)blockIdx.z * sB;
    float*       C = Cg + (long)blockIdx.z * sC;

    const int tid = threadIdx.x;
    const int tx  = tid & 15;
    const int ty  = tid >> 4;

    const int lda = TA ? M : K;
    const int ldb = TB ? K : N;

    float acc[8][8];
#pragma unroll
    for (int i = 0; i < 8; i++)
#pragma unroll
        for (int j = 0; j < 8; j++) acc[i][j] = 0.f;

    for (int k0 = 0; k0 < K; k0 += 16) {
        if (TA) {
#pragma unroll
            for (int r = 0; r < 2; r++) {
                int id = tid + r * 256;
                int k  = id >> 5;
                int m4 = (id & 31) << 2;
                float4 v = *reinterpret_cast<const float4*>(&A[(long)(k0 + k) * lda + bm + m4]);
                *reinterpret_cast<float4*>(&As[k][m4]) = v;
            }
        } else {
#pragma unroll
            for (int r = 0; r < 2; r++) {
                int id = tid + r * 256;
                int m  = id >> 2;
                int k4 = (id & 3) << 2;
                float4 v = *reinterpret_cast<const float4*>(&A[(long)(bm + m) * lda + k0 + k4]);
                As[k4 + 0][m] = v.x; As[k4 + 1][m] = v.y;
                As[k4 + 2][m] = v.z; As[k4 + 3][m] = v.w;
            }
        }
        if (TB) {
#pragma unroll
            for (int r = 0; r < 2; r++) {
                int id = tid + r * 256;
                int n  = id >> 2;
                int k4 = (id & 3) << 2;
                float4 v = *reinterpret_cast<const float4*>(&B[(long)(bn + n) * ldb + k0 + k4]);
                Bs[k4 + 0][n] = v.x; Bs[k4 + 1][n] = v.y;
                Bs[k4 + 2][n] = v.z; Bs[k4 + 3][n] = v.w;
            }
        } else {
#pragma unroll
            for (int r = 0; r < 2; r++) {
                int id = tid + r * 256;
                int k  = id >> 5;
                int n4 = (id & 31) << 2;
                float4 v = *reinterpret_cast<const float4*>(&B[(long)(k0 + k) * ldb + bn + n4]);
                *reinterpret_cast<float4*>(&Bs[k][n4]) = v;
            }
        }
        __syncthreads();

#pragma unroll
        for (int kk = 0; kk < 16; kk++) {
            float ra[8], rb[8];
#pragma unroll
            for (int w = 0; w < 4; w++) {
                ra[w]     = As[kk][ty * 4 + w];
                ra[4 + w] = As[kk][64 + ty * 4 + w];
                rb[w]     = Bs[kk][tx * 4 + w];
                rb[4 + w] = Bs[kk][64 + tx * 4 + w];
            }
#pragma unroll
            for (int i = 0; i < 8; i++)
#pragma unroll
                for (int j = 0; j < 8; j++)
                    acc[i][j] = fmaf(ra[i], rb[j], acc[i][j]);
        }
        __syncthreads();
    }

#pragma unroll
    for (int i = 0; i < 8; i++) {
        int m = bm + ((i < 4) ? (ty * 4 + i) : (64 + ty * 4 + (i - 4)));
#pragma unroll
        for (int jh = 0; jh < 2; jh++) {
            float4 v;
            v.x = acc[i][jh * 4 + 0];
            v.y = acc[i][jh * 4 + 1];
            v.z = acc[i][jh * 4 + 2];
            v.w = acc[i][jh * 4 + 3];
            *reinterpret_cast<float4*>(&C[(long)m * N + bn + jh * 64 + tx * 4]) = v;
        }
    }
}

// ---------------------------------------------------------------------------
// Row softmax over last axis (16384 rows of 256)
// ---------------------------------------------------------------------------
__global__ __launch_bounds__(256)
void softmax_kernel(float* __restrict__ S)
{
    __shared__ float red[8];
    const long row = blockIdx.x;
    float* p = S + row * 256;
    const int t = threadIdx.x;
    const int lane = t & 31, warp = t >> 5;

    float v = p[t];
    float m = v;
#pragma unroll
    for (int o = 16; o; o >>= 1) m = fmaxf(m, __shfl_xor_sync(0xffffffffu, m, o));
    if (lane == 0) red[warp] = m;
    __syncthreads();
    float mm = red[0];
#pragma unroll
    for (int i = 1; i < 8; i++) mm = fmaxf(mm, red[i]);
    __syncthreads();

    float e = __expf(v - mm);
    float s = e;
#pragma unroll
    for (int o = 16; o; o >>= 1) s += __shfl_xor_sync(0xffffffffu, s, o);
    if (lane == 0) red[warp] = s;
    __syncthreads();
    float tot = 0.f;
#pragma unroll
    for (int i = 0; i < 8; i++) tot += red[i];

    p[t] = e / tot;
}

// ---------------------------------------------------------------------------
// Channel LayerNorm over D=512 (optional residual)
// ---------------------------------------------------------------------------
__global__ __launch_bounds__(128)
void ln_kernel(const float* __restrict__ in, const float* __restrict__ res,
               const float* __restrict__ w, const float* __restrict__ b,
               float* __restrict__ out)
{
    const int pos = blockIdx.x * 128 + threadIdx.x;
    float s = 0.f, s2 = 0.f;
    if (res) {
        for (int c = 0; c < Dm; c++) {
            float v = in[(long)c * Pp + pos] + res[(long)c * Pp + pos];
            s += v; s2 += v * v;
        }
    } else {
        for (int c = 0; c < Dm; c++) {
            float v = in[(long)c * Pp + pos];
            s += v; s2 += v * v;
        }
    }
    const float mean = s * (1.f / Dm);
    const float var  = s2 * (1.f / Dm) - mean * mean;
    const float rstd = rsqrtf(var + EPS);
    if (res) {
        for (int c = 0; c < Dm; c++) {
            float v = in[(long)c * Pp + pos] + res[(long)c * Pp + pos];
            out[(long)c * Pp + pos] = (v - mean) * rstd * w[c] + b[c];
        }
    } else {
        for (int c = 0; c < Dm; c++) {
            float v = in[(long)c * Pp + pos];
            out[(long)c * Pp + pos] = (v - mean) * rstd * w[c] + b[c];
        }
    }
}

// ---------------------------------------------------------------------------
// Column attention (online softmax; 1 thread per (i,l), 2 i's per thread)
// ---------------------------------------------------------------------------
__global__ __launch_bounds__(1024)
void colattn_kernel(const float* __restrict__ qkv, float* __restrict__ out)
{
    const int h = blockIdx.z;
    const int l = blockIdx.x * 32 + threadIdx.x;
    const float* Q  = qkv + (long)h * Cc * Pp;
    const float* Kp = Q + (long)Dm * Pp;
    const float* V  = Q + 2L * Dm * Pp;

#pragma unroll
    for (int ii = 0; ii < 2; ii++) {
        const int i = threadIdx.y + 32 * ii;
        float q[Cc];
#pragma unroll
        for (int c = 0; c < Cc; c++) q[c] = Q[(long)c * Pp + i * Lm + l];

        float m = -CUDART_INF_F, d = 0.f;
        float acc[Cc];
#pragma unroll
        for (int c = 0; c < Cc; c++) acc[c] = 0.f;

        for (int j = 0; j < Sm; j++) {
            float sc = 0.f;
#pragma unroll
            for (int c = 0; c < Cc; c++)
                sc = fmaf(q[c], Kp[(long)c * Pp + j * Lm + l], sc);
            const float mn = fmaxf(m, sc);
            const float scale = __expf(m - mn);
            const float pj = __expf(sc - mn);
            d = d * scale + pj;
#pragma unroll
            for (int c = 0; c < Cc; c++)
                acc[c] = fmaf(acc[c], scale, pj * V[(long)c * Pp + j * Lm + l]);
            m = mn;
        }
        const float inv = 1.f / d;
#pragma unroll
        for (int c = 0; c < Cc; c++)
            out[(long)(h * Cc + c) * Pp + i * Lm + l] = acc[c] * inv;
    }
}

// ---------------------------------------------------------------------------
// Host side
// ---------------------------------------------------------------------------
extern "C" void kernel_launch(void* const* d_in, const int* in_sizes, int n_in,
                              void* d_out, int out_size)
{
    const float* x     = (const float*)d_in[0];
    const float* w_row = (const float*)d_in[1];
    const float* b_row = (const float*)d_in[2];
    const float* w_col = (const float*)d_in[3];
    const float* b_col = (const float*)d_in[4];
    const float* w_an1 = (const float*)d_in[5];
    const float* b_an1 = (const float*)d_in[6];
    const float* w_an2 = (const float*)d_in[7];
    const float* b_an2 = (const float*)d_in[8];
    const float* w_ff1 = (const float*)d_in[9];
    const float* b_ff1 = (const float*)d_in[10];
    const float* w_ff2 = (const float*)d_in[11];
    const float* b_ff2 = (const float*)d_in[12];
    const float* w_ln1 = (const float*)d_in[13];
    const float* b_ln1 = (const float*)d_in[14];
    const float* w_ln2 = (const float*)d_in[15];
    const float* b_ln2 = (const float*)d_in[16];
    float* outp = (float*)d_out;

    float *qkv, *scores, *tmp, *out1, *attn;
    __nv_bfloat16 *bth, *btl, *ffh, *ffl, *wrh, *wrl, *wch, *wcl, *f1h, *f1l, *f2h, *f2l;
    cudaGetSymbolAddress((void**)&qkv,    g_qkv);
    cudaGetSymbolAddress((void**)&scores, g_scores);
    cudaGetSymbolAddress((void**)&tmp,    g_tmp);
    cudaGetSymbolAddress((void**)&out1,   g_out1);
    cudaGetSymbolAddress((void**)&attn,   g_attn);
    cudaGetSymbolAddress((void**)&bth,    g_bth);
    cudaGetSymbolAddress((void**)&btl,    g_btl);
    cudaGetSymbolAddress((void**)&ffh,    g_ffh);
    cudaGetSymbolAddress((void**)&ffl,    g_ffl);
    cudaGetSymbolAddress((void**)&wrh,    g_wrh);
    cudaGetSymbolAddress((void**)&wrl,    g_wrl);
    cudaGetSymbolAddress((void**)&wch,    g_wch);
    cudaGetSymbolAddress((void**)&wcl,    g_wcl);
    cudaGetSymbolAddress((void**)&f1h,    g_f1h);
    cudaGetSymbolAddress((void**)&f1l,    g_f1l);
    cudaGetSymbolAddress((void**)&f2h,    g_f2h);
    cudaGetSymbolAddress((void**)&f2l,    g_f2l);

    cudaFuncSetAttribute(gemm_mma<0>, cudaFuncAttributeMaxDynamicSharedMemorySize, MM_SMEM);
    cudaFuncSetAttribute(gemm_mma<1>, cudaFuncAttributeMaxDynamicSharedMemorySize, MM_SMEM);

    const long headQK = (long)Cc * Pp;

    // weight conversions
    convw_kernel<<<(3 * Dm * Dm + 255) / 256, 256>>>(w_row, wrh, wrl, 3 * Dm * Dm);
    convw_kernel<<<(3 * Dm * Dm + 255) / 256, 256>>>(w_col, wch, wcl, 3 * Dm * Dm);
    convw_kernel<<<(Fm * Dm + 255) / 256, 256>>>(w_ff1, f1h, f1l, Fm * Dm);
    convw_kernel<<<(Dm * Fm + 255) / 256, 256>>>(w_ff2, f2h, f2l, Dm * Fm);

    // x -> transposed bf16 hi/lo
    convt_kernel<<<dim3(Pp / 32, Dm / 32), dim3(32, 8)>>>(x, bth, btl, Dm, Pp);

    // 1) row qkv = w_row @ x + b_row   [1536 x 16384]
    gemm_mma<0><<<dim3((3 * Dm) / 128, Pp / 128), 256, MM_SMEM>>>(
        wrh, wrl, bth, btl, b_row, qkv, nullptr, nullptr, 3 * Dm, Pp, Dm);

    // 2) row scores = Q_h^T K_h per head
    sgemm_kernel<true, false><<<dim3(Lm / 128, Lm / 128, Hh), 256>>>(
        qkv, qkv + (long)Dm * Pp, scores, Lm, Lm, Cc * Sm, headQK, headQK, (long)Lm * Lm);

    // 3) softmax
    softmax_kernel<<<Hh * Lm, 256>>>(scores);

    // 4) row_out = V * P^T per head
    sgemm_kernel<false, true><<<dim3(Lm / 128, (Cc * Sm) / 128, Hh), 256>>>(
        qkv + 2L * Dm * Pp, scores, tmp, Cc * Sm, Lm, Lm, headQK, (long)Lm * Lm, headQK);

    // 5) out1 = LN(x + row_out; an1); transpose-convert for col qkv
    ln_kernel<<<Pp / 128, 128>>>(x, tmp, w_an1, b_an1, out1);
    convt_kernel<<<dim3(Pp / 32, Dm / 32), dim3(32, 8)>>>(out1, bth, btl, Dm, Pp);

    // 6) col qkv = w_col @ out1 + b_col
    gemm_mma<0><<<dim3((3 * Dm) / 128, Pp / 128), 256, MM_SMEM>>>(
        wch, wcl, bth, btl, b_col, qkv, nullptr, nullptr, 3 * Dm, Pp, Dm);

    // 7) column attention
    colattn_kernel<<<dim3(Lm / 32, 1, Hh), dim3(32, 32)>>>(qkv, tmp);

    // 8) attn_out = LN(out1 + col_out; an2)
    ln_kernel<<<Pp / 128, 128>>>(out1, tmp, w_an2, b_an2, attn);

    // 9) h = LN(attn_out; ln1); transpose-convert for ff1
    ln_kernel<<<Pp / 128, 128>>>(attn, nullptr, w_ln1, b_ln1, out1);
    convt_kernel<<<dim3(Pp / 32, Dm / 32), dim3(32, 8)>>>(out1, bth, btl, Dm, Pp);

    // 10) ff1: relu(w_ff1 @ h + b_ff1) -> bf16 hi/lo transposed [Pp, Fm]
    gemm_mma<1><<<dim3(Fm / 128, Pp / 128), 256, MM_SMEM>>>(
        f1h, f1l, bth, btl, b_ff1, nullptr, ffh, ffl, Fm, Pp, Dm);

    // 11) ff2 = w_ff2 @ ff1 + b_ff2
    gemm_mma<0><<<dim3(Dm / 128, Pp / 128), 256, MM_SMEM>>>(
        f2h, f2l, ffh, ffl, b_ff2, tmp, nullptr, nullptr, Dm, Pp, Fm);

    // 12) out = LN(h + ff2; ln2)
    ln_kernel<<<Pp / 128, 128>>>(out1, tmp, w_ln2, b_ln2, outp);
}

// round 4
// speedup vs baseline: 1.8678x; 1.1596x over previous
#include <cuda_runtime.h>
#include <cuda_bf16.h>
#include <cuda_fp16.h>
#include <math_constants.h>
#include <cstdint>
#include <cstddef>

// ---------------------------------------------------------------------------
// Problem constants
// ---------------------------------------------------------------------------
#define Dm   512
#define Sm   64
#define Lm   256
#define Fm   2048
#define Hh   64
#define Cc   8
#define Pp   (Sm * Lm)          // 16384 spatial positions
#define EPS  1e-5f

// ---------------------------------------------------------------------------
// Scratch buffers (static device globals -- allocation-free)
// ---------------------------------------------------------------------------
__device__ __align__(256) float g_qkv   [3L * Dm * Pp];       // 1536 x 16384
__device__ __align__(256) float g_scores[(long)Hh * Lm * Lm]; // 64 x 256 x 256
__device__ __align__(256) float g_tmp   [(long)Dm * Pp];
__device__ __align__(256) float g_out1  [(long)Dm * Pp];
__device__ __align__(256) float g_attn  [(long)Dm * Pp];

// fp16 operands: weights split hi/lo, activations single (transposed [N,K])
__device__ __align__(256) __half g_bt [(long)Pp * Dm];   // act^T [Pp,512]
__device__ __align__(256) __half g_ff [(long)Pp * Fm];   // ff1^T [Pp,2048]
__device__ __align__(256) __half g_wrh[3 * Dm * Dm], g_wrl[3 * Dm * Dm];
__device__ __align__(256) __half g_wch[3 * Dm * Dm], g_wcl[3 * Dm * Dm];
__device__ __align__(256) __half g_f1h[Fm * Dm],     g_f1l[Fm * Dm];
__device__ __align__(256) __half g_f2h[Dm * Fm],     g_f2l[Dm * Fm];

// ---------------------------------------------------------------------------
// PTX helpers (baseline ISA only: cp.async / ldmatrix / mma.sync)
// ---------------------------------------------------------------------------
__device__ __forceinline__ uint32_t smem_u32(const void* p) {
    uint32_t a;
    asm("{ .reg .u64 t; cvta.to.shared.u64 t, %1; cvt.u32.u64 %0, t; }" : "=r"(a) : "l"(p));
    return a;
}
__device__ __forceinline__ void cpasync16(uint32_t dst, const void* src) {
    asm volatile("cp.async.cg.shared.global [%0], [%1], 16;" :: "r"(dst), "l"(src));
}
__device__ __forceinline__ void cp_commit() {
    asm volatile("cp.async.commit_group;" ::: "memory");
}
template<int N>
__device__ __forceinline__ void cp_wait() {
    asm volatile("cp.async.wait_group %0;" :: "n"(N) : "memory");
}
__device__ __forceinline__ void ldsm4(uint32_t* r, uint32_t addr) {
    asm volatile("ldmatrix.sync.aligned.m8n8.x4.shared.b16 {%0,%1,%2,%3}, [%4];"
                 : "=r"(r[0]), "=r"(r[1]), "=r"(r[2]), "=r"(r[3]) : "r"(addr));
}
__device__ __forceinline__ void mma16816h(float* d, const uint32_t* a, uint32_t b0, uint32_t b1) {
    asm volatile("mma.sync.aligned.m16n8k16.row.col.f32.f16.f16.f32 "
                 "{%0,%1,%2,%3}, {%4,%5,%6,%7}, {%8,%9}, {%0,%1,%2,%3};"
                 : "+f"(d[0]), "+f"(d[1]), "+f"(d[2]), "+f"(d[3])
                 : "r"(a[0]), "r"(a[1]), "r"(a[2]), "r"(a[3]), "r"(b0), "r"(b1));
}

// ---------------------------------------------------------------------------
// fp16 split GEMM: C[M,N] = (Ah+Al)[M,K] * B[N,K]^T (+bias)
//   A = weights (fp16 hi/lo), B = activations (single fp16)
//   MODE 0: C fp32 [M,N], += bias[m]
//   MODE 1: relu(+bias) -> fp16, TRANSPOSED [N,M] (smem-staged)
// CTA tile 128x128, BK=64, 3-stage cp.async ring, 8 warps (4m x 2n), warp 32x64.
// Stage: Ah(16KB) Al(16KB) B(16KB), SW128 swizzled.
// ---------------------------------------------------------------------------
#define MM_STAGES 3
#define MM_STAGE_BYTES 49152
#define MM_SMEM (MM_STAGES * MM_STAGE_BYTES)

template<int MODE>
__global__ void __launch_bounds__(256, 1)
gemm_mma(const __half* __restrict__ Ah, const __half* __restrict__ Al,
         const __half* __restrict__ B,
         const float* __restrict__ bias,
         float* __restrict__ C, __half* __restrict__ oH,
         int M, int N, int K)
{
    extern __shared__ char smem[];
    const uint32_t sb = smem_u32(smem);

    const int tid  = threadIdx.x;
    const int wid  = tid >> 5;
    const int lane = tid & 31;
    const int warpM = wid & 3;          // 4 row-warps, 32 rows each
    const int warpN = wid >> 2;         // 2 col-warps, 64 cols each
    const int bm = blockIdx.x * 128;
    const int bn = blockIdx.y * 128;

    // ---- stage loader: 12 x cp.async(16B) per thread ----
    auto load_stage = [&](int st, int it) {
        const uint32_t sbase = sb + st * MM_STAGE_BYTES;
        const int k0 = it << 6;
#pragma unroll
        for (int j = 0; j < 4; j++) {
            const int idx = tid + j * 256;          // 0..1023
            const int row = idx >> 3;               // 0..127
            const int c   = idx & 7;                // 16B chunk in 128B row
            const uint32_t soff = row * 128 + ((c * 16) ^ ((row & 7) << 4));
            const size_t ga = (size_t)(bm + row) * K + k0 + c * 8;
            const size_t gb = (size_t)(bn + row) * K + k0 + c * 8;
            cpasync16(sbase +         soff, Ah + ga);
            cpasync16(sbase + 16384 + soff, Al + ga);
            cpasync16(sbase + 32768 + soff, B  + gb);
        }
    };

    float acc[2][8][4];
#pragma unroll
    for (int i = 0; i < 2; i++)
#pragma unroll
        for (int j = 0; j < 8; j++)
#pragma unroll
            for (int v = 0; v < 4; v++) acc[i][j][v] = 0.f;

    const int nIter = K >> 6;

    load_stage(0, 0); cp_commit();
    load_stage(1, 1); cp_commit();

    // per-thread ldmatrix addressing
    const int rsub  = lane & 15;                  // row within 16-row tile
    const int khalf = ((lane >> 4) & 1) * 16;     // 16B half of the k16 slab
    const int rA = warpM * 32 + rsub;             // A row in [0,128)
    const int rB = warpN * 64 + rsub;             // B row in [0,128)
    const uint32_t xA = (rA & 7) << 4;            // swizzle XOR
    const uint32_t xB = (rB & 7) << 4;

    for (int it = 0; it < nIter; it++) {
        cp_wait<1>();
        __syncthreads();
        // prefetch next-next stage BEFORE compute so DMA overlaps MMAs
        if (it + 2 < nIter) load_stage((it + 2) % MM_STAGES, it + 2);
        cp_commit();

        const uint32_t sbase = sb + (it % MM_STAGES) * MM_STAGE_BYTES;
        const uint32_t pAh = sbase +         rA * 128;
        const uint32_t pAl = sbase + 16384 + rA * 128;
        const uint32_t pB  = sbase + 32768 + rB * 128;

#pragma unroll
        for (int q = 0; q < 4; q++) {
            const uint32_t kb = q * 32 + khalf;
            uint32_t ah[2][4], al[2][4], bb[4][4];
#pragma unroll
            for (int mt = 0; mt < 2; mt++) {
                ldsm4(ah[mt], pAh + mt * 2048 + (kb ^ xA));
                ldsm4(al[mt], pAl + mt * 2048 + (kb ^ xA));
            }
#pragma unroll
            for (int g = 0; g < 4; g++)
                ldsm4(bb[g], pB + g * 2048 + (kb ^ xB));
#pragma unroll
            for (int mt = 0; mt < 2; mt++)
#pragma unroll
                for (int nt = 0; nt < 8; nt++) {
                    const int g = nt >> 1, o = nt & 1;
                    mma16816h(acc[mt][nt], ah[mt], bb[g][o], bb[g][o + 2]); // Wh*act
                    mma16816h(acc[mt][nt], al[mt], bb[g][o], bb[g][o + 2]); // Wl*act
                }
        }
    }
    cp_wait<0>();
    __syncthreads();

    if (MODE == 0) {
#pragma unroll
        for (int mt = 0; mt < 2; mt++) {
            const int r0 = bm + warpM * 32 + mt * 16 + (lane >> 2);
            const float bv0 = bias[r0], bv1 = bias[r0 + 8];
#pragma unroll
            for (int nt = 0; nt < 8; nt++) {
                const int c0 = bn + warpN * 64 + nt * 8 + (lane & 3) * 2;
                float* d = acc[mt][nt];
                float2 v0 = make_float2(d[0] + bv0, d[1] + bv0);
                float2 v1 = make_float2(d[2] + bv1, d[3] + bv1);
                *reinterpret_cast<float2*>(&C[(size_t)r0 * N + c0]) = v0;
                *reinterpret_cast<float2*>(&C[(size_t)(r0 + 8) * N + c0]) = v1;
            }
        }
    } else {
        // bias + relu, stage through smem, emit transposed fp16 [N,M]
        float* T = reinterpret_cast<float*>(smem);   // [128][130]
#pragma unroll
        for (int mt = 0; mt < 2; mt++) {
            const int lr0 = warpM * 32 + mt * 16 + (lane >> 2);
            const float bv0 = bias[bm + lr0], bv1 = bias[bm + lr0 + 8];
#pragma unroll
            for (int nt = 0; nt < 8; nt++) {
                const int lc0 = warpN * 64 + nt * 8 + (lane & 3) * 2;
                float* d = acc[mt][nt];
                T[lr0 * 130 + lc0]           = fmaxf(d[0] + bv0, 0.f);
                T[lr0 * 130 + lc0 + 1]       = fmaxf(d[1] + bv0, 0.f);
                T[(lr0 + 8) * 130 + lc0]     = fmaxf(d[2] + bv1, 0.f);
                T[(lr0 + 8) * 130 + lc0 + 1] = fmaxf(d[3] + bv1, 0.f);
            }
        }
        __syncthreads();
        const int mloc = tid & 127;
#pragma unroll 4
        for (int rep = 0; rep < 64; rep++) {
            const int nl = rep * 2 + (tid >> 7);
            const float v = T[mloc * 130 + nl];
            oH[(size_t)(bn + nl) * M + bm + mloc] = __float2half(v);
        }
    }
}

// ---------------------------------------------------------------------------
// fp32 -> fp16 hi/lo weight conversion
// ---------------------------------------------------------------------------
__global__ void convw_kernel(const float* __restrict__ w,
                             __half* __restrict__ oh, __half* __restrict__ ol, int n)
{
    int i = blockIdx.x * 256 + threadIdx.x;
    if (i < n) {
        float v = w[i];
        __half h = __float2half(v);
        oh[i] = h;
        ol[i] = __float2half(v - __half2float(h));
    }
}

// transpose-convert: in fp32 [K, N] -> out fp16 [N, K]
__global__ void __launch_bounds__(256)
convt_kernel(const float* __restrict__ in, __half* __restrict__ oh, int K, int N)
{
    __shared__ float t[32][33];
    const int n0 = blockIdx.x * 32, k0 = blockIdx.y * 32;
    const int tx = threadIdx.x, ty = threadIdx.y;  // 32 x 8
#pragma unroll
    for (int i = 0; i < 4; i++)
        t[ty + 8 * i][tx] = in[(size_t)(k0 + ty + 8 * i) * N + n0 + tx];
    __syncthreads();
#pragma unroll
    for (int i = 0; i < 4; i++) {
        const int r = ty + 8 * i;           // local n
        oh[(size_t)(n0 + r) * K + k0 + tx] = __float2half(t[tx][r]);
    }
}

// ---------------------------------------------------------------------------
// SGEMM for the attention GEMMs
// ---------------------------------------------------------------------------
template<bool TA, bool TB>
__global__ __launch_bounds__(256)
void sgemm_kernel(const float* __restrict__ Ag, const float* __restrict__ Bg,
                  float* __restrict__ Cg, int M, int N, int K,
                  long sA, long sB, long sC)
{
    __shared__ float As[16][132];
    __shared__ float Bs[16][132];

    const int bm = blockIdx.y * 128;
    const int bn = blockIdx.x * 128;
    const float* A = Ag + (long)blockIdx.z * sA;
    const float* B = Bg + (long)blockIdx.z * sB;
    float*       C = Cg + (long)blockIdx.z * sC;

    const int tid = threadIdx.x;
    const int tx  = tid & 15;
    const int ty  = tid >> 4;

    const int lda = TA ? M : K;
    const int ldb = TB ? K : N;

    float acc[8][8];
#pragma unroll
    for (int i = 0; i < 8; i++)
#pragma unroll
        for (int j = 0; j < 8; j++) acc[i][j] = 0.f;

    for (int k0 = 0; k0 < K; k0 += 16) {
        if (TA) {
#pragma unroll
            for (int r = 0; r < 2; r++) {
                int id = tid + r * 256;
                int k  = id >> 5;
                int m4 = (id & 31) << 2;
                float4 v = *reinterpret_cast<const float4*>(&A[(long)(k0 + k) * lda + bm + m4]);
                *reinterpret_cast<float4*>(&As[k][m4]) = v;
            }
        } else {
#pragma unroll
            for (int r = 0; r < 2; r++) {
                int id = tid + r * 256;
                int m  = id >> 2;
                int k4 = (id & 3) << 2;
                float4 v = *reinterpret_cast<const float4*>(&A[(long)(bm + m) * lda + k0 + k4]);
                As[k4 + 0][m] = v.x; As[k4 + 1][m] = v.y;
                As[k4 + 2][m] = v.z; As[k4 + 3][m] = v.w;
            }
        }
        if (TB) {
#pragma unroll
            for (int r = 0; r < 2; r++) {
                int id = tid + r * 256;
                int n  = id >> 2;
                int k4 = (id & 3) << 2;
                float4 v = *reinterpret_cast<const float4*>(&B[(long)(bn + n) * ldb + k0 + k4]);
                Bs[k4 + 0][n] = v.x; Bs[k4 + 1][n] = v.y;
                Bs[k4 + 2][n] = v.z; Bs[k4 + 3][n] = v.w;
            }
        } else {
#pragma unroll
            for (int r = 0; r < 2; r++) {
                int id = tid + r * 256;
                int k  = id >> 5;
                int n4 = (id & 31) << 2;
                float4 v = *reinterpret_cast<const float4*>(&B[(long)(k0 + k) * ldb + bn + n4]);
                *reinterpret_cast<float4*>(&Bs[k][n4]) = v;
            }
        }
        __syncthreads();

#pragma unroll
        for (int kk = 0; kk < 16; kk++) {
            float ra[8], rb[8];
#pragma unroll
            for (int w = 0; w < 4; w++) {
                ra[w]     = As[kk][ty * 4 + w];
                ra[4 + w] = As[kk][64 + ty * 4 + w];
                rb[w]     = Bs[kk][tx * 4 + w];
                rb[4 + w] = Bs[kk][64 + tx * 4 + w];
            }
#pragma unroll
            for (int i = 0; i < 8; i++)
#pragma unroll
                for (int j = 0; j < 8; j++)
                    acc[i][j] = fmaf(ra[i], rb[j], acc[i][j]);
        }
        __syncthreads();
    }

#pragma unroll
    for (int i = 0; i < 8; i++) {
        int m = bm + ((i < 4) ? (ty * 4 + i) : (64 + ty * 4 + (i - 4)));
#pragma unroll
        for (int jh = 0; jh < 2; jh++) {
            float4 v;
            v.x = acc[i][jh * 4 + 0];
            v.y = acc[i][jh * 4 + 1];
            v.z = acc[i][jh * 4 + 2];
            v.w = acc[i][jh * 4 + 3];
            *reinterpret_cast<float4*>(&C[(long)m * N + bn + jh * 64 + tx * 4]) = v;
        }
    }
}

// ---------------------------------------------------------------------------
// Row softmax over last axis (16384 rows of 256)
// ---------------------------------------------------------------------------
__global__ __launch_bounds__(256)
void softmax_kernel(float* __restrict__ S)
{
    __shared__ float red[8];
    const long row = blockIdx.x;
    float* p = S + row * 256;
    const int t = threadIdx.x;
    const int lane = t & 31, warp = t >> 5;

    float v = p[t];
    float m = v;
#pragma unroll
    for (int o = 16; o; o >>= 1) m = fmaxf(m, __shfl_xor_sync(0xffffffffu, m, o));
    if (lane == 0) red[warp] = m;
    __syncthreads();
    float mm = red[0];
#pragma unroll
    for (int i = 1; i < 8; i++) mm = fmaxf(mm, red[i]);
    __syncthreads();

    float e = __expf(v - mm);
    float s = e;
#pragma unroll
    for (int o = 16; o; o >>= 1) s += __shfl_xor_sync(0xffffffffu, s, o);
    if (lane == 0) red[warp] = s;
    __syncthreads();
    float tot = 0.f;
#pragma unroll
    for (int i = 0; i < 8; i++) tot += red[i];

    p[t] = e / tot;
}

// ---------------------------------------------------------------------------
// Channel LayerNorm over D=512 (optional residual)
// ---------------------------------------------------------------------------
__global__ __launch_bounds__(128)
void ln_kernel(const float* __restrict__ in, const float* __restrict__ res,
               const float* __restrict__ w, const float* __restrict__ b,
               float* __restrict__ out)
{
    const int pos = blockIdx.x * 128 + threadIdx.x;
    float s = 0.f, s2 = 0.f;
    if (res) {
        for (int c = 0; c < Dm; c++) {
            float v = in[(long)c * Pp + pos] + res[(long)c * Pp + pos];
            s += v; s2 += v * v;
        }
    } else {
        for (int c = 0; c < Dm; c++) {
            float v = in[(long)c * Pp + pos];
            s += v; s2 += v * v;
        }
    }
    const float mean = s * (1.f / Dm);
    const float var  = s2 * (1.f / Dm) - mean * mean;
    const float rstd = rsqrtf(var + EPS);
    if (res) {
        for (int c = 0; c < Dm; c++) {
            float v = in[(long)c * Pp + pos] + res[(long)c * Pp + pos];
            out[(long)c * Pp + pos] = (v - mean) * rstd * w[c] + b[c];
        }
    } else {
        for (int c = 0; c < Dm; c++) {
            float v = in[(long)c * Pp + pos];
            out[(long)c * Pp + pos] = (v - mean) * rstd * w[c] + b[c];
        }
    }
}

// ---------------------------------------------------------------------------
// Column attention (online softmax; 1 thread per (i,l), 2 i's per thread)
// ---------------------------------------------------------------------------
__global__ __launch_bounds__(1024)
void colattn_kernel(const float* __restrict__ qkv, float* __restrict__ out)
{
    const int h = blockIdx.z;
    const int l = blockIdx.x * 32 + threadIdx.x;
    const float* Q  = qkv + (long)h * Cc * Pp;
    const float* Kp = Q + (long)Dm * Pp;
    const float* V  = Q + 2L * Dm * Pp;

#pragma unroll
    for (int ii = 0; ii < 2; ii++) {
        const int i = threadIdx.y + 32 * ii;
        float q[Cc];
#pragma unroll
        for (int c = 0; c < Cc; c++) q[c] = Q[(long)c * Pp + i * Lm + l];

        float m = -CUDART_INF_F, d = 0.f;
        float acc[Cc];
#pragma unroll
        for (int c = 0; c < Cc; c++) acc[c] = 0.f;

        for (int j = 0; j < Sm; j++) {
            float sc = 0.f;
#pragma unroll
            for (int c = 0; c < Cc; c++)
                sc = fmaf(q[c], Kp[(long)c * Pp + j * Lm + l], sc);
            const float mn = fmaxf(m, sc);
            const float scale = __expf(m - mn);
            const float pj = __expf(sc - mn);
            d = d * scale + pj;
#pragma unroll
            for (int c = 0; c < Cc; c++)
                acc[c] = fmaf(acc[c], scale, pj * V[(long)c * Pp + j * Lm + l]);
            m = mn;
        }
        const float inv = 1.f / d;
#pragma unroll
        for (int c = 0; c < Cc; c++)
            out[(long)(h * Cc + c) * Pp + i * Lm + l] = acc[c] * inv;
    }
}

// ---------------------------------------------------------------------------
// Host side
// ---------------------------------------------------------------------------
extern "C" void kernel_launch(void* const* d_in, const int* in_sizes, int n_in,
                              void* d_out, int out_size)
{
    const float* x     = (const float*)d_in[0];
    const float* w_row = (const float*)d_in[1];
    const float* b_row = (const float*)d_in[2];
    const float* w_col = (const float*)d_in[3];
    const float* b_col = (const float*)d_in[4];
    const float* w_an1 = (const float*)d_in[5];
    const float* b_an1 = (const float*)d_in[6];
    const float* w_an2 = (const float*)d_in[7];
    const float* b_an2 = (const float*)d_in[8];
    const float* w_ff1 = (const float*)d_in[9];
    const float* b_ff1 = (const float*)d_in[10];
    const float* w_ff2 = (const float*)d_in[11];
    const float* b_ff2 = (const float*)d_in[12];
    const float* w_ln1 = (const float*)d_in[13];
    const float* b_ln1 = (const float*)d_in[14];
    const float* w_ln2 = (const float*)d_in[15];
    const float* b_ln2 = (const float*)d_in[16];
    float* outp = (float*)d_out;

    float *qkv, *scores, *tmp, *out1, *attn;
    __half *bt, *ff, *wrh, *wrl, *wch, *wcl, *f1h, *f1l, *f2h, *f2l;
    cudaGetSymbolAddress((void**)&qkv,    g_qkv);
    cudaGetSymbolAddress((void**)&scores, g_scores);
    cudaGetSymbolAddress((void**)&tmp,    g_tmp);
    cudaGetSymbolAddress((void**)&out1,   g_out1);
    cudaGetSymbolAddress((void**)&attn,   g_attn);
    cudaGetSymbolAddress((void**)&bt,     g_bt);
    cudaGetSymbolAddress((void**)&ff,     g_ff);
    cudaGetSymbolAddress((void**)&wrh,    g_wrh);
    cudaGetSymbolAddress((void**)&wrl,    g_wrl);
    cudaGetSymbolAddress((void**)&wch,    g_wch);
    cudaGetSymbolAddress((void**)&wcl,    g_wcl);
    cudaGetSymbolAddress((void**)&f1h,    g_f1h);
    cudaGetSymbolAddress((void**)&f1l,    g_f1l);
    cudaGetSymbolAddress((void**)&f2h,    g_f2h);
    cudaGetSymbolAddress((void**)&f2l,    g_f2l);

    cudaFuncSetAttribute(gemm_mma<0>, cudaFuncAttributeMaxDynamicSharedMemorySize, MM_SMEM);
    cudaFuncSetAttribute(gemm_mma<1>, cudaFuncAttributeMaxDynamicSharedMemorySize, MM_SMEM);

    const long headQK = (long)Cc * Pp;

    // weight conversions (fp16 hi/lo)
    convw_kernel<<<(3 * Dm * Dm + 255) / 256, 256>>>(w_row, wrh, wrl, 3 * Dm * Dm);
    convw_kernel<<<(3 * Dm * Dm + 255) / 256, 256>>>(w_col, wch, wcl, 3 * Dm * Dm);
    convw_kernel<<<(Fm * Dm + 255) / 256, 256>>>(w_ff1, f1h, f1l, Fm * Dm);
    convw_kernel<<<(Dm * Fm + 255) / 256, 256>>>(w_ff2, f2h, f2l, Dm * Fm);

    // x -> transposed fp16
    convt_kernel<<<dim3(Pp / 32, Dm / 32), dim3(32, 8)>>>(x, bt, Dm, Pp);

    // 1) row qkv = w_row @ x + b_row   [1536 x 16384]
    gemm_mma<0><<<dim3((3 * Dm) / 128, Pp / 128), 256, MM_SMEM>>>(
        wrh, wrl, bt, b_row, qkv, nullptr, 3 * Dm, Pp, Dm);

    // 2) row scores = Q_h^T K_h per head
    sgemm_kernel<true, false><<<dim3(Lm / 128, Lm / 128, Hh), 256>>>(
        qkv, qkv + (long)Dm * Pp, scores, Lm, Lm, Cc * Sm, headQK, headQK, (long)Lm * Lm);

    // 3) softmax
    softmax_kernel<<<Hh * Lm, 256>>>(scores);

    // 4) row_out = V * P^T per head
    sgemm_kernel<false, true><<<dim3(Lm / 128, (Cc * Sm) / 128, Hh), 256>>>(
        qkv + 2L * Dm * Pp, scores, tmp, Cc * Sm, Lm, Lm, headQK, (long)Lm * Lm, headQK);

    // 5) out1 = LN(x + row_out; an1); transpose-convert for col qkv
    ln_kernel<<<Pp / 128, 128>>>(x, tmp, w_an1, b_an1, out1);
    convt_kernel<<<dim3(Pp / 32, Dm / 32), dim3(32, 8)>>>(out1, bt, Dm, Pp);

    // 6) col qkv = w_col @ out1 + b_col
    gemm_mma<0><<<dim3((3 * Dm) / 128, Pp / 128), 256, MM_SMEM>>>(
        wch, wcl, bt, b_col, qkv, nullptr, 3 * Dm, Pp, Dm);

    // 7) column attention
    colattn_kernel<<<dim3(Lm / 32, 1, Hh), dim3(32, 32)>>>(qkv, tmp);

    // 8) attn_out = LN(out1 + col_out; an2)
    ln_kernel<<<Pp / 128, 128>>>(out1, tmp, w_an2, b_an2, attn);

    // 9) h = LN(attn_out; ln1); transpose-convert for ff1
    ln_kernel<<<Pp / 128, 128>>>(attn, nullptr, w_ln1, b_ln1, out1);
    convt_kernel<<<dim3(Pp / 32, Dm / 32), dim3(32, 8)>>>(out1, bt, Dm, Pp);

    // 10) ff1: relu(w_ff1 @ h + b_ff1) -> fp16 transposed [Pp, Fm]
    gemm_mma<1><<<dim3(Fm / 128, Pp / 128), 256, MM_SMEM>>>(
        f1h, f1l, bt, b_ff1, nullptr, ff, Fm, Pp, Dm);

    // 11) ff2 = w_ff2 @ ff1 + b_ff2
    gemm_mma<0><<<dim3(Dm / 128, Pp / 128), 256, MM_SMEM>>>(
        f2h, f2l, ff, b_ff2, tmp, nullptr, Dm, Pp, Fm);

    // 12) out = LN(h + ff2; ln2)
    ln_kernel<<<Pp / 128, 128>>>(out1, tmp, w_ln2, b_ln2, outp);
}

// round 5
// speedup vs baseline: 2.6821x; 1.4360x over previous
#include <cuda_runtime.h>
#include <cuda_fp16.h>
#include <math_constants.h>
#include <cstdint>
#include <cstddef>

// ---------------------------------------------------------------------------
// Problem constants
// ---------------------------------------------------------------------------
#define Dm   512
#define Sm   64
#define Lm   256
#define Fm   2048
#define Hh   64
#define Cc   8
#define Pp   (Sm * Lm)          // 16384 spatial positions
#define EPS  1e-5f

// ---------------------------------------------------------------------------
// Scratch buffers (static device globals -- allocation-free)
// ---------------------------------------------------------------------------
__device__ __align__(256) float g_qkv   [3L * Dm * Pp];       // 1536 x 16384
__device__ __align__(256) float g_scores[(long)Hh * Lm * Lm]; // 64 x 256 x 256
__device__ __align__(256) float g_tmp   [(long)Dm * Pp];
__device__ __align__(256) float g_out1  [(long)Dm * Pp];
__device__ __align__(256) float g_attn  [(long)Dm * Pp];

// fp16 operands
__device__ __align__(256) __half g_bt [(long)Pp * Dm];   // act^T [Pp,512]
__device__ __align__(256) __half g_ff [(long)Pp * Fm];   // ff1^T [Pp,2048]
__device__ __align__(256) __half g_wrh[3 * Dm * Dm], g_wrl[3 * Dm * Dm];
__device__ __align__(256) __half g_wch[3 * Dm * Dm], g_wcl[3 * Dm * Dm];
__device__ __align__(256) __half g_f1 [Fm * Dm];
__device__ __align__(256) __half g_f2 [Dm * Fm];
// attention fp16 operands
__device__ __align__(256) __half g_qth[(long)Hh * Lm * Dm], g_qtl[(long)Hh * Lm * Dm]; // Q^T per head [h][i][k]
__device__ __align__(256) __half g_kth[(long)Hh * Lm * Dm], g_ktl[(long)Hh * Lm * Dm]; // K^T per head [h][j][k]
__device__ __align__(256) __half g_v16[(long)Dm * Pp];                                  // V fp16 (qkv layout)
__device__ __align__(256) __half g_ph [(long)Hh * Lm * Lm], g_pl[(long)Hh * Lm * Lm];   // P hi/lo [h][i][j]

// ---------------------------------------------------------------------------
// PTX helpers (baseline ISA only: cp.async / ldmatrix / mma.sync)
// ---------------------------------------------------------------------------
__device__ __forceinline__ uint32_t smem_u32(const void* p) {
    uint32_t a;
    asm("{ .reg .u64 t; cvta.to.shared.u64 t, %1; cvt.u32.u64 %0, t; }" : "=r"(a) : "l"(p));
    return a;
}
__device__ __forceinline__ void cpasync16(uint32_t dst, const void* src) {
    asm volatile("cp.async.cg.shared.global [%0], [%1], 16;" :: "r"(dst), "l"(src));
}
__device__ __forceinline__ void cp_commit() {
    asm volatile("cp.async.commit_group;" ::: "memory");
}
template<int N>
__device__ __forceinline__ void cp_wait() {
    asm volatile("cp.async.wait_group %0;" :: "n"(N) : "memory");
}
__device__ __forceinline__ void ldsm4(uint32_t* r, uint32_t addr) {
    asm volatile("ldmatrix.sync.aligned.m8n8.x4.shared.b16 {%0,%1,%2,%3}, [%4];"
                 : "=r"(r[0]), "=r"(r[1]), "=r"(r[2]), "=r"(r[3]) : "r"(addr));
}
__device__ __forceinline__ void mma16816h(float* d, const uint32_t* a, uint32_t b0, uint32_t b1) {
    asm volatile("mma.sync.aligned.m16n8k16.row.col.f32.f16.f16.f32 "
                 "{%0,%1,%2,%3}, {%4,%5,%6,%7}, {%8,%9}, {%0,%1,%2,%3};"
                 : "+f"(d[0]), "+f"(d[1]), "+f"(d[2]), "+f"(d[3])
                 : "r"(a[0]), "r"(a[1]), "r"(a[2]), "r"(a[3]), "r"(b0), "r"(b1));
}

// ---------------------------------------------------------------------------
// Big GEMM: C[M,N] = W[M,K] * B[N,K]^T (+bias)
//   APASS=2: W split hi/lo (2 MMA passes); APASS=1: single fp16 W.
//   MODE 0: C fp32 [M,N] + bias.   MODE 1: relu(+bias) -> fp16 transposed [N,M].
// CTA tile 128x128, BK=64, 3-stage cp.async ring, 8 warps (4m x 2n).
// ---------------------------------------------------------------------------
template<int MODE, int APASS>
__global__ void __launch_bounds__(256, 1)
gemm_mma(const __half* __restrict__ Ah, const __half* __restrict__ Al,
         const __half* __restrict__ B,
         const float* __restrict__ bias,
         float* __restrict__ C, __half* __restrict__ oH,
         int M, int N, int K)
{
    constexpr uint32_t SBYTES = (APASS + 1) * 16384;
    constexpr uint32_t BOFF   = APASS * 16384;
    extern __shared__ char smem[];
    const uint32_t sb = smem_u32(smem);

    const int tid  = threadIdx.x;
    const int wid  = tid >> 5;
    const int lane = tid & 31;
    const int warpM = wid & 3;
    const int warpN = wid >> 2;
    const int bm = blockIdx.x * 128;
    const int bn = blockIdx.y * 128;

    auto load_stage = [&](int st, int it) {
        const uint32_t sbase = sb + st * SBYTES;
        const int k0 = it << 6;
#pragma unroll
        for (int j = 0; j < 4; j++) {
            const int idx = tid + j * 256;
            const int row = idx >> 3;
            const int c   = idx & 7;
            const uint32_t soff = row * 128 + ((c * 16) ^ ((row & 7) << 4));
            const size_t ga = (size_t)(bm + row) * K + k0 + c * 8;
            const size_t gb = (size_t)(bn + row) * K + k0 + c * 8;
            cpasync16(sbase + soff, Ah + ga);
            if (APASS == 2) cpasync16(sbase + 16384 + soff, Al + ga);
            cpasync16(sbase + BOFF + soff, B + gb);
        }
    };

    float acc[2][8][4];
#pragma unroll
    for (int i = 0; i < 2; i++)
#pragma unroll
        for (int j = 0; j < 8; j++)
#pragma unroll
            for (int v = 0; v < 4; v++) acc[i][j][v] = 0.f;

    const int nIter = K >> 6;
    load_stage(0, 0); cp_commit();
    load_stage(1, 1); cp_commit();

    const int rsub  = lane & 15;
    const int khalf = ((lane >> 4) & 1) * 16;
    const int rA = warpM * 32 + rsub;
    const int rB = warpN * 64 + rsub;
    const uint32_t xA = (rA & 7) << 4;
    const uint32_t xB = (rB & 7) << 4;

    for (int it = 0; it < nIter; it++) {
        cp_wait<1>();
        __syncthreads();
        if (it + 2 < nIter) load_stage((it + 2) % 3, it + 2);
        cp_commit();

        const uint32_t sbase = sb + (it % 3) * SBYTES;
        const uint32_t pAh = sbase + rA * 128;
        const uint32_t pAl = sbase + 16384 + rA * 128;
        const uint32_t pB  = sbase + BOFF + rB * 128;

#pragma unroll
        for (int q = 0; q < 4; q++) {
            const uint32_t kb = q * 32 + khalf;
            uint32_t ah[2][4], al[2][4], bb[4][4];
#pragma unroll
            for (int mt = 0; mt < 2; mt++) {
                ldsm4(ah[mt], pAh + mt * 2048 + (kb ^ xA));
                if (APASS == 2) ldsm4(al[mt], pAl + mt * 2048 + (kb ^ xA));
            }
#pragma unroll
            for (int g = 0; g < 4; g++)
                ldsm4(bb[g], pB + g * 2048 + (kb ^ xB));
#pragma unroll
            for (int mt = 0; mt < 2; mt++)
#pragma unroll
                for (int nt = 0; nt < 8; nt++) {
                    const int g = nt >> 1, o = nt & 1;
                    mma16816h(acc[mt][nt], ah[mt], bb[g][o], bb[g][o + 2]);
                    if (APASS == 2) mma16816h(acc[mt][nt], al[mt], bb[g][o], bb[g][o + 2]);
                }
        }
    }
    cp_wait<0>();
    __syncthreads();

    if (MODE == 0) {
#pragma unroll
        for (int mt = 0; mt < 2; mt++) {
            const int r0 = bm + warpM * 32 + mt * 16 + (lane >> 2);
            const float bv0 = bias[r0], bv1 = bias[r0 + 8];
#pragma unroll
            for (int nt = 0; nt < 8; nt++) {
                const int c0 = bn + warpN * 64 + nt * 8 + (lane & 3) * 2;
                float* d = acc[mt][nt];
                *reinterpret_cast<float2*>(&C[(size_t)r0 * N + c0])       = make_float2(d[0] + bv0, d[1] + bv0);
                *reinterpret_cast<float2*>(&C[(size_t)(r0 + 8) * N + c0]) = make_float2(d[2] + bv1, d[3] + bv1);
            }
        }
    } else {
        float* T = reinterpret_cast<float*>(smem);   // [128][130]
#pragma unroll
        for (int mt = 0; mt < 2; mt++) {
            const int lr0 = warpM * 32 + mt * 16 + (lane >> 2);
            const float bv0 = bias[bm + lr0], bv1 = bias[bm + lr0 + 8];
#pragma unroll
            for (int nt = 0; nt < 8; nt++) {
                const int lc0 = warpN * 64 + nt * 8 + (lane & 3) * 2;
                float* d = acc[mt][nt];
                T[lr0 * 130 + lc0]           = fmaxf(d[0] + bv0, 0.f);
                T[lr0 * 130 + lc0 + 1]       = fmaxf(d[1] + bv0, 0.f);
                T[(lr0 + 8) * 130 + lc0]     = fmaxf(d[2] + bv1, 0.f);
                T[(lr0 + 8) * 130 + lc0 + 1] = fmaxf(d[3] + bv1, 0.f);
            }
        }
        __syncthreads();
        const int mloc = tid & 127;
#pragma unroll 4
        for (int rep = 0; rep < 64; rep++) {
            const int nl = rep * 2 + (tid >> 7);
            oH[(size_t)(bn + nl) * M + bm + mloc] = __float2half(T[mloc * 130 + nl]);
        }
    }
}

// ---------------------------------------------------------------------------
// Row-attention scores: per head, S[i,j] = sum_k Q^T[i,k]*K^T[j,k]
// Both operands fp16 hi/lo, 3-pass. M=N=256, K=512, batch=64 (blockIdx.z).
// ---------------------------------------------------------------------------
__global__ void __launch_bounds__(256, 1)
gemm_scores(const __half* __restrict__ Qh, const __half* __restrict__ Ql,
            const __half* __restrict__ Kh, const __half* __restrict__ Kl,
            float* __restrict__ S)
{
    constexpr int K = 512, N = 256;
    constexpr uint32_t SBYTES = 65536;
    extern __shared__ char smem[];
    const uint32_t sb = smem_u32(smem);

    const int tid = threadIdx.x, wid = tid >> 5, lane = tid & 31;
    const int warpM = wid & 3, warpN = wid >> 2;
    const int bm = blockIdx.x * 128, bn = blockIdx.y * 128;
    const int h = blockIdx.z;
    const __half* Ah = Qh + (size_t)h * Lm * Dm;
    const __half* Al = Ql + (size_t)h * Lm * Dm;
    const __half* Bh = Kh + (size_t)h * Lm * Dm;
    const __half* Bl = Kl + (size_t)h * Lm * Dm;
    float* C = S + (size_t)h * Lm * Lm;

    auto load_stage = [&](int st, int it) {
        const uint32_t sbase = sb + st * SBYTES;
        const int k0 = it << 6;
#pragma unroll
        for (int j = 0; j < 4; j++) {
            const int idx = tid + j * 256;
            const int row = idx >> 3;
            const int c   = idx & 7;
            const uint32_t soff = row * 128 + ((c * 16) ^ ((row & 7) << 4));
            const size_t ga = (size_t)(bm + row) * K + k0 + c * 8;
            const size_t gb = (size_t)(bn + row) * K + k0 + c * 8;
            cpasync16(sbase +         soff, Ah + ga);
            cpasync16(sbase + 16384 + soff, Al + ga);
            cpasync16(sbase + 32768 + soff, Bh + gb);
            cpasync16(sbase + 49152 + soff, Bl + gb);
        }
    };

    float acc[2][8][4];
#pragma unroll
    for (int i = 0; i < 2; i++)
#pragma unroll
        for (int j = 0; j < 8; j++)
#pragma unroll
            for (int v = 0; v < 4; v++) acc[i][j][v] = 0.f;

    load_stage(0, 0); cp_commit();
    load_stage(1, 1); cp_commit();

    const int rsub  = lane & 15;
    const int khalf = ((lane >> 4) & 1) * 16;
    const int rA = warpM * 32 + rsub;
    const int rB = warpN * 64 + rsub;
    const uint32_t xA = (rA & 7) << 4;
    const uint32_t xB = (rB & 7) << 4;

    for (int it = 0; it < 8; it++) {
        cp_wait<1>();
        __syncthreads();
        if (it + 2 < 8) load_stage((it + 2) % 3, it + 2);
        cp_commit();

        const uint32_t sbase = sb + (it % 3) * SBYTES;
        const uint32_t pAh = sbase +         rA * 128;
        const uint32_t pAl = sbase + 16384 + rA * 128;
        const uint32_t pBh = sbase + 32768 + rB * 128;
        const uint32_t pBl = sbase + 49152 + rB * 128;

#pragma unroll
        for (int q = 0; q < 4; q++) {
            const uint32_t kb = q * 32 + khalf;
            uint32_t ah[2][4], al[2][4], bh[4][4], bl[4][4];
#pragma unroll
            for (int mt = 0; mt < 2; mt++) {
                ldsm4(ah[mt], pAh + mt * 2048 + (kb ^ xA));
                ldsm4(al[mt], pAl + mt * 2048 + (kb ^ xA));
            }
#pragma unroll
            for (int g = 0; g < 4; g++) {
                ldsm4(bh[g], pBh + g * 2048 + (kb ^ xB));
                ldsm4(bl[g], pBl + g * 2048 + (kb ^ xB));
            }
#pragma unroll
            for (int mt = 0; mt < 2; mt++)
#pragma unroll
                for (int nt = 0; nt < 8; nt++) {
                    const int g = nt >> 1, o = nt & 1;
                    mma16816h(acc[mt][nt], ah[mt], bh[g][o], bh[g][o + 2]);
                    mma16816h(acc[mt][nt], ah[mt], bl[g][o], bl[g][o + 2]);
                    mma16816h(acc[mt][nt], al[mt], bh[g][o], bh[g][o + 2]);
                }
        }
    }
    cp_wait<0>();
    __syncthreads();

#pragma unroll
    for (int mt = 0; mt < 2; mt++) {
        const int r0 = bm + warpM * 32 + mt * 16 + (lane >> 2);
#pragma unroll
        for (int nt = 0; nt < 8; nt++) {
            const int c0 = bn + warpN * 64 + nt * 8 + (lane & 3) * 2;
            float* d = acc[mt][nt];
            *reinterpret_cast<float2*>(&C[(size_t)r0 * N + c0])       = make_float2(d[0], d[1]);
            *reinterpret_cast<float2*>(&C[(size_t)(r0 + 8) * N + c0]) = make_float2(d[2], d[3]);
        }
    }
}

// ---------------------------------------------------------------------------
// Row-attention output: per head, C[m=(c,s), i] = sum_j V[m,j] * P[i,j]
// V single fp16 (A), P hi/lo (B), 2-pass. M=512, N=256, K=256, batch=64.
// A rows and C rows use the (c,s) address mapping into the [D][S][L] layout.
// ---------------------------------------------------------------------------
__global__ void __launch_bounds__(256, 1)
gemm_vp(const __half* __restrict__ V, const __half* __restrict__ Ph,
        const __half* __restrict__ Pl, float* __restrict__ O)
{
    constexpr int K = 256;
    constexpr uint32_t SBYTES = 49152;
    extern __shared__ char smem[];
    const uint32_t sb = smem_u32(smem);

    const int tid = threadIdx.x, wid = tid >> 5, lane = tid & 31;
    const int warpM = wid & 3, warpN = wid >> 2;
    const int bm = blockIdx.x * 128, bn = blockIdx.y * 128;
    const int h = blockIdx.z;
    const __half* Av = V + (size_t)h * 8 * Pp;
    const __half* Bh = Ph + (size_t)h * Lm * Lm;
    const __half* Bl = Pl + (size_t)h * Lm * Lm;
    float* C = O + (size_t)h * 8 * Pp;

    auto load_stage = [&](int st, int it) {
        const uint32_t sbase = sb + st * SBYTES;
        const int k0 = it << 6;
#pragma unroll
        for (int j = 0; j < 4; j++) {
            const int idx = tid + j * 256;
            const int row = idx >> 3;
            const int c   = idx & 7;
            const uint32_t soff = row * 128 + ((c * 16) ^ ((row & 7) << 4));
            const int mrow = bm + row;
            const size_t ga = (size_t)(mrow >> 6) * Pp + (mrow & 63) * 256 + k0 + c * 8;
            const size_t gb = (size_t)(bn + row) * K + k0 + c * 8;
            cpasync16(sbase +         soff, Av + ga);
            cpasync16(sbase + 16384 + soff, Bh + gb);
            cpasync16(sbase + 32768 + soff, Bl + gb);
        }
    };

    float acc[2][8][4];
#pragma unroll
    for (int i = 0; i < 2; i++)
#pragma unroll
        for (int j = 0; j < 8; j++)
#pragma unroll
            for (int v = 0; v < 4; v++) acc[i][j][v] = 0.f;

    load_stage(0, 0); cp_commit();
    load_stage(1, 1); cp_commit();

    const int rsub  = lane & 15;
    const int khalf = ((lane >> 4) & 1) * 16;
    const int rA = warpM * 32 + rsub;
    const int rB = warpN * 64 + rsub;
    const uint32_t xA = (rA & 7) << 4;
    const uint32_t xB = (rB & 7) << 4;

    for (int it = 0; it < 4; it++) {
        cp_wait<1>();
        __syncthreads();
        if (it + 2 < 4) load_stage((it + 2) % 3, it + 2);
        cp_commit();

        const uint32_t sbase = sb + (it % 3) * SBYTES;
        const uint32_t pA  = sbase +         rA * 128;
        const uint32_t pBh = sbase + 16384 + rB * 128;
        const uint32_t pBl = sbase + 32768 + rB * 128;

#pragma unroll
        for (int q = 0; q < 4; q++) {
            const uint32_t kb = q * 32 + khalf;
            uint32_t av[2][4], bh[4][4], bl[4][4];
#pragma unroll
            for (int mt = 0; mt < 2; mt++)
                ldsm4(av[mt], pA + mt * 2048 + (kb ^ xA));
#pragma unroll
            for (int g = 0; g < 4; g++) {
                ldsm4(bh[g], pBh + g * 2048 + (kb ^ xB));
                ldsm4(bl[g], pBl + g * 2048 + (kb ^ xB));
            }
#pragma unroll
            for (int mt = 0; mt < 2; mt++)
#pragma unroll
                for (int nt = 0; nt < 8; nt++) {
                    const int g = nt >> 1, o = nt & 1;
                    mma16816h(acc[mt][nt], av[mt], bh[g][o], bh[g][o + 2]);
                    mma16816h(acc[mt][nt], av[mt], bl[g][o], bl[g][o + 2]);
                }
        }
    }
    cp_wait<0>();
    __syncthreads();

#pragma unroll
    for (int mt = 0; mt < 2; mt++) {
        const int r0 = bm + warpM * 32 + mt * 16 + (lane >> 2);
        const int r1 = r0 + 8;
        const size_t a0 = (size_t)(r0 >> 6) * Pp + (r0 & 63) * 256;
        const size_t a1 = (size_t)(r1 >> 6) * Pp + (r1 & 63) * 256;
#pragma unroll
        for (int nt = 0; nt < 8; nt++) {
            const int c0 = bn + warpN * 64 + nt * 8 + (lane & 3) * 2;
            float* d = acc[mt][nt];
            *reinterpret_cast<float2*>(&C[a0 + c0]) = make_float2(d[0], d[1]);
            *reinterpret_cast<float2*>(&C[a1 + c0]) = make_float2(d[2], d[3]);
        }
    }
}

// ---------------------------------------------------------------------------
// Conversions
// ---------------------------------------------------------------------------
__global__ void convw2_kernel(const float* __restrict__ w,
                              __half* __restrict__ oh, __half* __restrict__ ol, int n)
{
    int i = blockIdx.x * 256 + threadIdx.x;
    if (i < n) {
        float v = w[i];
        __half h = __float2half(v);
        oh[i] = h;
        ol[i] = __float2half(v - __half2float(h));
    }
}
__global__ void convw1_kernel(const float* __restrict__ w, __half* __restrict__ oh, int n)
{
    int i = blockIdx.x * 256 + threadIdx.x;
    if (i < n) oh[i] = __float2half(w[i]);
}
// act fp32 [K, N] -> fp16 [N, K] (transposed)
__global__ void __launch_bounds__(256)
convt_kernel(const float* __restrict__ in, __half* __restrict__ oh, int K, int N)
{
    __shared__ float t[32][33];
    const int n0 = blockIdx.x * 32, k0 = blockIdx.y * 32;
    const int tx = threadIdx.x, ty = threadIdx.y;
#pragma unroll
    for (int i = 0; i < 4; i++)
        t[ty + 8 * i][tx] = in[(size_t)(k0 + ty + 8 * i) * N + n0 + tx];
    __syncthreads();
#pragma unroll
    for (int i = 0; i < 4; i++) {
        const int r = ty + 8 * i;
        oh[(size_t)(n0 + r) * K + k0 + tx] = __float2half(t[tx][r]);
    }
}
// Q/K per-head transpose-convert hi/lo: in (c,s)-rows of [D][S][L]; out [h][l][k=(c*64+s)]
__global__ void __launch_bounds__(256)
convtqk_kernel(const float* __restrict__ qkv,
               __half* __restrict__ qh, __half* __restrict__ ql,
               __half* __restrict__ kh, __half* __restrict__ kl)
{
    __shared__ float t[32][33];
    const int h = blockIdx.z >> 1;
    const int isK = blockIdx.z & 1;
    const float* in = qkv + (isK ? (size_t)Dm * Pp : 0) + (size_t)h * 8 * Pp;
    __half* oh = (isK ? kh : qh) + (size_t)h * Lm * Dm;
    __half* ol = (isK ? kl : ql) + (size_t)h * Lm * Dm;
    const int l0 = blockIdx.x * 32, k0 = blockIdx.y * 32;
    const int tx = threadIdx.x, ty = threadIdx.y;
#pragma unroll
    for (int i = 0; i < 4; i++) {
        const int k = k0 + ty + 8 * i;
        t[ty + 8 * i][tx] = in[(size_t)(k >> 6) * Pp + (k & 63) * 256 + l0 + tx];
    }
    __syncthreads();
#pragma unroll
    for (int i = 0; i < 4; i++) {
        const int r = ty + 8 * i;            // local l
        const float v = t[tx][r];
        const __half hv = __float2half(v);
        const size_t o = (size_t)(l0 + r) * Dm + k0 + tx;
        oh[o] = hv;
        ol[o] = __float2half(v - __half2float(hv));
    }
}
// V fp32 -> fp16 elementwise
__global__ void convv_kernel(const float* __restrict__ v, __half* __restrict__ o, long n)
{
    long i = (long)blockIdx.x * 256 + threadIdx.x;
    if (i < n) o[i] = __float2half(v[i]);
}

// ---------------------------------------------------------------------------
// Row softmax over last axis -> P fp16 hi/lo
// ---------------------------------------------------------------------------
__global__ __launch_bounds__(256)
void softmax16_kernel(const float* __restrict__ S, __half* __restrict__ ph, __half* __restrict__ pl)
{
    __shared__ float red[8];
    const size_t row = blockIdx.x;
    const float* p = S + row * 256;
    const int t = threadIdx.x;
    const int lane = t & 31, warp = t >> 5;

    float v = p[t];
    float m = v;
#pragma unroll
    for (int o = 16; o; o >>= 1) m = fmaxf(m, __shfl_xor_sync(0xffffffffu, m, o));
    if (lane == 0) red[warp] = m;
    __syncthreads();
    float mm = red[0];
#pragma unroll
    for (int i = 1; i < 8; i++) mm = fmaxf(mm, red[i]);
    __syncthreads();

    float e = __expf(v - mm);
    float s = e;
#pragma unroll
    for (int o = 16; o; o >>= 1) s += __shfl_xor_sync(0xffffffffu, s, o);
    if (lane == 0) red[warp] = s;
    __syncthreads();
    float tot = 0.f;
#pragma unroll
    for (int i = 0; i < 8; i++) tot += red[i];

    const float pr = e / tot;
    const __half hv = __float2half(pr);
    ph[row * 256 + t] = hv;
    pl[row * 256 + t] = __float2half(pr - __half2float(hv));
}

// ---------------------------------------------------------------------------
// Channel LayerNorm over D=512 (optional residual)
// ---------------------------------------------------------------------------
__global__ __launch_bounds__(128)
void ln_kernel(const float* __restrict__ in, const float* __restrict__ res,
               const float* __restrict__ w, const float* __restrict__ b,
               float* __restrict__ out)
{
    const int pos = blockIdx.x * 128 + threadIdx.x;
    float s = 0.f, s2 = 0.f;
    if (res) {
        for (int c = 0; c < Dm; c++) {
            float v = in[(long)c * Pp + pos] + res[(long)c * Pp + pos];
            s += v; s2 += v * v;
        }
    } else {
        for (int c = 0; c < Dm; c++) {
            float v = in[(long)c * Pp + pos];
            s += v; s2 += v * v;
        }
    }
    const float mean = s * (1.f / Dm);
    const float var  = s2 * (1.f / Dm) - mean * mean;
    const float rstd = rsqrtf(var + EPS);
    if (res) {
        for (int c = 0; c < Dm; c++) {
            float v = in[(long)c * Pp + pos] + res[(long)c * Pp + pos];
            out[(long)c * Pp + pos] = (v - mean) * rstd * w[c] + b[c];
        }
    } else {
        for (int c = 0; c < Dm; c++) {
            float v = in[(long)c * Pp + pos];
            out[(long)c * Pp + pos] = (v - mean) * rstd * w[c] + b[c];
        }
    }
}

// ---------------------------------------------------------------------------
// Column attention — direct softmax (scores are small; no max needed)
// ---------------------------------------------------------------------------
__global__ __launch_bounds__(1024)
void colattn_kernel(const float* __restrict__ qkv, float* __restrict__ out)
{
    const int h = blockIdx.z;
    const int l = blockIdx.x * 32 + threadIdx.x;
    const float* Q  = qkv + (long)h * Cc * Pp;
    const float* Kp = Q + (long)Dm * Pp;
    const float* V  = Q + 2L * Dm * Pp;

#pragma unroll
    for (int ii = 0; ii < 2; ii++) {
        const int i = threadIdx.y + 32 * ii;
        float q[Cc];
#pragma unroll
        for (int c = 0; c < Cc; c++) q[c] = Q[(long)c * Pp + i * Lm + l];

        float d = 0.f;
        float acc[Cc];
#pragma unroll
        for (int c = 0; c < Cc; c++) acc[c] = 0.f;

        for (int j = 0; j < Sm; j++) {
            float sc = 0.f;
#pragma unroll
            for (int c = 0; c < Cc; c++)
                sc = fmaf(q[c], Kp[(long)c * Pp + j * Lm + l], sc);
            const float e = __expf(sc);
            d += e;
#pragma unroll
            for (int c = 0; c < Cc; c++)
                acc[c] = fmaf(e, V[(long)c * Pp + j * Lm + l], acc[c]);
        }
        const float inv = 1.f / d;
#pragma unroll
        for (int c = 0; c < Cc; c++)
            out[(long)(h * Cc + c) * Pp + i * Lm + l] = acc[c] * inv;
    }
}

// ---------------------------------------------------------------------------
// Host side
// ---------------------------------------------------------------------------
extern "C" void kernel_launch(void* const* d_in, const int* in_sizes, int n_in,
                              void* d_out, int out_size)
{
    const float* x     = (const float*)d_in[0];
    const float* w_row = (const float*)d_in[1];
    const float* b_row = (const float*)d_in[2];
    const float* w_col = (const float*)d_in[3];
    const float* b_col = (const float*)d_in[4];
    const float* w_an1 = (const float*)d_in[5];
    const float* b_an1 = (const float*)d_in[6];
    const float* w_an2 = (const float*)d_in[7];
    const float* b_an2 = (const float*)d_in[8];
    const float* w_ff1 = (const float*)d_in[9];
    const float* b_ff1 = (const float*)d_in[10];
    const float* w_ff2 = (const float*)d_in[11];
    const float* b_ff2 = (const float*)d_in[12];
    const float* w_ln1 = (const float*)d_in[13];
    const float* b_ln1 = (const float*)d_in[14];
    const float* w_ln2 = (const float*)d_in[15];
    const float* b_ln2 = (const float*)d_in[16];
    float* outp = (float*)d_out;

    float *qkv, *scores, *tmp, *out1, *attn;
    __half *bt, *ff, *wrh, *wrl, *wch, *wcl, *f1, *f2;
    __half *qth, *qtl, *kth, *ktl, *v16, *ph, *pl;
    cudaGetSymbolAddress((void**)&qkv,    g_qkv);
    cudaGetSymbolAddress((void**)&scores, g_scores);
    cudaGetSymbolAddress((void**)&tmp,    g_tmp);
    cudaGetSymbolAddress((void**)&out1,   g_out1);
    cudaGetSymbolAddress((void**)&attn,   g_attn);
    cudaGetSymbolAddress((void**)&bt,     g_bt);
    cudaGetSymbolAddress((void**)&ff,     g_ff);
    cudaGetSymbolAddress((void**)&wrh,    g_wrh);
    cudaGetSymbolAddress((void**)&wrl,    g_wrl);
    cudaGetSymbolAddress((void**)&wch,    g_wch);
    cudaGetSymbolAddress((void**)&wcl,    g_wcl);
    cudaGetSymbolAddress((void**)&f1,     g_f1);
    cudaGetSymbolAddress((void**)&f2,     g_f2);
    cudaGetSymbolAddress((void**)&qth,    g_qth);
    cudaGetSymbolAddress((void**)&qtl,    g_qtl);
    cudaGetSymbolAddress((void**)&kth,    g_kth);
    cudaGetSymbolAddress((void**)&ktl,    g_ktl);
    cudaGetSymbolAddress((void**)&v16,    g_v16);
    cudaGetSymbolAddress((void**)&ph,     g_ph);
    cudaGetSymbolAddress((void**)&pl,     g_pl);

    cudaFuncSetAttribute(gemm_mma<0,2>, cudaFuncAttributeMaxDynamicSharedMemorySize, 3 * 49152);
    cudaFuncSetAttribute(gemm_mma<0,1>, cudaFuncAttributeMaxDynamicSharedMemorySize, 3 * 32768);
    cudaFuncSetAttribute(gemm_mma<1,1>, cudaFuncAttributeMaxDynamicSharedMemorySize, 3 * 32768);
    cudaFuncSetAttribute(gemm_scores,   cudaFuncAttributeMaxDynamicSharedMemorySize, 3 * 65536);
    cudaFuncSetAttribute(gemm_vp,       cudaFuncAttributeMaxDynamicSharedMemorySize, 3 * 49152);

    // weight conversions
    convw2_kernel<<<(3 * Dm * Dm + 255) / 256, 256>>>(w_row, wrh, wrl, 3 * Dm * Dm);
    convw2_kernel<<<(3 * Dm * Dm + 255) / 256, 256>>>(w_col, wch, wcl, 3 * Dm * Dm);
    convw1_kernel<<<(Fm * Dm + 255) / 256, 256>>>(w_ff1, f1, Fm * Dm);
    convw1_kernel<<<(Dm * Fm + 255) / 256, 256>>>(w_ff2, f2, Dm * Fm);

    // x -> transposed fp16
    convt_kernel<<<dim3(Pp / 32, Dm / 32), dim3(32, 8)>>>(x, bt, Dm, Pp);

    // 1) row qkv = w_row @ x + b_row
    gemm_mma<0,2><<<dim3((3 * Dm) / 128, Pp / 128), 256, 3 * 49152>>>(
        wrh, wrl, bt, b_row, qkv, nullptr, 3 * Dm, Pp, Dm);

    // 2) Q/K transpose-convert (hi/lo), V elementwise convert
    convtqk_kernel<<<dim3(Lm / 32, Dm / 32, 2 * Hh), dim3(32, 8)>>>(qkv, qth, qtl, kth, ktl);
    convv_kernel<<<(int)(((long)Dm * Pp + 255) / 256), 256>>>(qkv + 2L * Dm * Pp, v16, (long)Dm * Pp);

    // 3) scores (tensor-core, 3-pass) + softmax -> P hi/lo
    gemm_scores<<<dim3(2, 2, Hh), 256, 3 * 65536>>>(qth, qtl, kth, ktl, scores);
    softmax16_kernel<<<Hh * Lm, 256>>>(scores, ph, pl);

    // 4) row_out = V * P^T (tensor-core, 2-pass)
    gemm_vp<<<dim3(4, 2, Hh), 256, 3 * 49152>>>(v16, ph, pl, tmp);

    // 5) out1 = LN(x + row_out; an1); transpose-convert
    ln_kernel<<<Pp / 128, 128>>>(x, tmp, w_an1, b_an1, out1);
    convt_kernel<<<dim3(Pp / 32, Dm / 32), dim3(32, 8)>>>(out1, bt, Dm, Pp);

    // 6) col qkv = w_col @ out1 + b_col
    gemm_mma<0,2><<<dim3((3 * Dm) / 128, Pp / 128), 256, 3 * 49152>>>(
        wch, wcl, bt, b_col, qkv, nullptr, 3 * Dm, Pp, Dm);

    // 7) column attention
    colattn_kernel<<<dim3(Lm / 32, 1, Hh), dim3(32, 32)>>>(qkv, tmp);

    // 8) attn_out = LN(out1 + col_out; an2)
    ln_kernel<<<Pp / 128, 128>>>(out1, tmp, w_an2, b_an2, attn);

    // 9) h = LN(attn_out; ln1); transpose-convert
    ln_kernel<<<Pp / 128, 128>>>(attn, nullptr, w_ln1, b_ln1, out1);
    convt_kernel<<<dim3(Pp / 32, Dm / 32), dim3(32, 8)>>>(out1, bt, Dm, Pp);

    // 10) ff1: relu(w_ff1 @ h + b_ff1) -> fp16 transposed (single-pass weights)
    gemm_mma<1,1><<<dim3(Fm / 128, Pp / 128), 256, 3 * 32768>>>(
        f1, nullptr, bt, b_ff1, nullptr, ff, Fm, Pp, Dm);

    // 11) ff2 = w_ff2 @ ff1 + b_ff2 (single-pass weights)
    gemm_mma<0,1><<<dim3(Dm / 128, Pp / 128), 256, 3 * 32768>>>(
        f2, nullptr, ff, b_ff2, tmp, nullptr, Dm, Pp, Fm);

    // 12) out = LN(h + ff2; ln2)
    ln_kernel<<<Pp / 128, 128>>>(out1, tmp, w_ln2, b_ln2, outp);
}

// round 6
// speedup vs baseline: 3.5137x; 1.3100x over previous
#include <cuda_runtime.h>
#include <cuda_fp16.h>
#include <math_constants.h>
#include <cstdint>
#include <cstddef>

// ---------------------------------------------------------------------------
// Problem constants
// ---------------------------------------------------------------------------
#define Dm   512
#define Sm   64
#define Lm   256
#define Fm   2048
#define Hh   64
#define Cc   8
#define Pp   (Sm * Lm)          // 16384 spatial positions
#define EPS  1e-5f

// ---------------------------------------------------------------------------
// Scratch buffers (static device globals -- allocation-free)
// ---------------------------------------------------------------------------
__device__ __align__(256) float g_qkv   [3L * Dm * Pp];       // 1536 x 16384
__device__ __align__(256) float g_scores[(long)Hh * Lm * Lm]; // 64 x 256 x 256
__device__ __align__(256) float g_tmp   [(long)Dm * Pp];
__device__ __align__(256) float g_out1  [(long)Dm * Pp];
__device__ __align__(256) float g_attn  [(long)Dm * Pp];

// fp16 operands (all single-plane)
__device__ __align__(256) __half g_bt [(long)Pp * Dm];   // act^T [Pp,512]
__device__ __align__(256) __half g_ff [(long)Pp * Fm];   // ff1^T [Pp,2048]
__device__ __align__(256) __half g_wr [3 * Dm * Dm];
__device__ __align__(256) __half g_wc [3 * Dm * Dm];
__device__ __align__(256) __half g_f1 [Fm * Dm];
__device__ __align__(256) __half g_f2 [Dm * Fm];
__device__ __align__(256) __half g_qt [(long)Hh * Lm * Dm];  // Q^T per head [h][i][k]
__device__ __align__(256) __half g_kt [(long)Hh * Lm * Dm];  // K^T per head [h][j][k]
__device__ __align__(256) __half g_v16[(long)Dm * Pp];       // V fp16 (qkv layout)
__device__ __align__(256) __half g_p16[(long)Hh * Lm * Lm];  // P [h][i][j]

// ---------------------------------------------------------------------------
// PTX helpers
// ---------------------------------------------------------------------------
__device__ __forceinline__ uint32_t smem_u32(const void* p) {
    uint32_t a;
    asm("{ .reg .u64 t; cvta.to.shared.u64 t, %1; cvt.u32.u64 %0, t; }" : "=r"(a) : "l"(p));
    return a;
}
__device__ __forceinline__ void cpasync16(uint32_t dst, const void* src) {
    asm volatile("cp.async.cg.shared.global [%0], [%1], 16;" :: "r"(dst), "l"(src));
}
__device__ __forceinline__ void cp_commit() {
    asm volatile("cp.async.commit_group;" ::: "memory");
}
template<int N>
__device__ __forceinline__ void cp_wait() {
    asm volatile("cp.async.wait_group %0;" :: "n"(N) : "memory");
}
__device__ __forceinline__ void ldsm4(uint32_t* r, uint32_t addr) {
    asm volatile("ldmatrix.sync.aligned.m8n8.x4.shared.b16 {%0,%1,%2,%3}, [%4];"
                 : "=r"(r[0]), "=r"(r[1]), "=r"(r[2]), "=r"(r[3]) : "r"(addr));
}
__device__ __forceinline__ void mma16816h(float* d, const uint32_t* a, uint32_t b0, uint32_t b1) {
    asm volatile("mma.sync.aligned.m16n8k16.row.col.f32.f16.f16.f32 "
                 "{%0,%1,%2,%3}, {%4,%5,%6,%7}, {%8,%9}, {%0,%1,%2,%3};"
                 : "+f"(d[0]), "+f"(d[1]), "+f"(d[2]), "+f"(d[3])
                 : "r"(a[0]), "r"(a[1]), "r"(a[2]), "r"(a[3]), "r"(b0), "r"(b1));
}

// ---------------------------------------------------------------------------
// Big GEMM: C[M,N] = W[M,K] * B[N,K]^T (+bias), single fp16 pass.
//   MODE 0: C fp32 [M,N] + bias.   MODE 1: relu(+bias) -> fp16 transposed [N,M].
// CTA tile 128x128, BK=64, 3-stage cp.async ring, 8 warps (4m x 2n).
// ---------------------------------------------------------------------------
#define MM_SBYTES 32768u
#define MM_SMEM   (3 * MM_SBYTES)

template<int MODE>
__global__ void __launch_bounds__(256, 1)
gemm_mma(const __half* __restrict__ A, const __half* __restrict__ B,
         const float* __restrict__ bias,
         float* __restrict__ C, __half* __restrict__ oH,
         int M, int N, int K)
{
    extern __shared__ char smem[];
    const uint32_t sb = smem_u32(smem);

    const int tid  = threadIdx.x;
    const int wid  = tid >> 5;
    const int lane = tid & 31;
    const int warpM = wid & 3;
    const int warpN = wid >> 2;
    const int bm = blockIdx.x * 128;
    const int bn = blockIdx.y * 128;

    auto load_stage = [&](int st, int it) {
        const uint32_t sbase = sb + st * MM_SBYTES;
        const int k0 = it << 6;
#pragma unroll
        for (int j = 0; j < 4; j++) {
            const int idx = tid + j * 256;
            const int row = idx >> 3;
            const int c   = idx & 7;
            const uint32_t soff = row * 128 + ((c * 16) ^ ((row & 7) << 4));
            cpasync16(sbase +         soff, A + (size_t)(bm + row) * K + k0 + c * 8);
            cpasync16(sbase + 16384 + soff, B + (size_t)(bn + row) * K + k0 + c * 8);
        }
    };

    float acc[2][8][4];
#pragma unroll
    for (int i = 0; i < 2; i++)
#pragma unroll
        for (int j = 0; j < 8; j++)
#pragma unroll
            for (int v = 0; v < 4; v++) acc[i][j][v] = 0.f;

    const int nIter = K >> 6;
    load_stage(0, 0); cp_commit();
    load_stage(1, 1); cp_commit();

    const int rsub  = lane & 15;
    const int khalf = ((lane >> 4) & 1) * 16;
    const int rA = warpM * 32 + rsub;
    const int rB = warpN * 64 + rsub;
    const uint32_t xA = (rA & 7) << 4;
    const uint32_t xB = (rB & 7) << 4;

    for (int it = 0; it < nIter; it++) {
        cp_wait<1>();
        __syncthreads();
        if (it + 2 < nIter) load_stage((it + 2) % 3, it + 2);
        cp_commit();

        const uint32_t sbase = sb + (it % 3) * MM_SBYTES;
        const uint32_t pA = sbase +         rA * 128;
        const uint32_t pB = sbase + 16384 + rB * 128;

#pragma unroll
        for (int q = 0; q < 4; q++) {
            const uint32_t kb = q * 32 + khalf;
            uint32_t ah[2][4], bb[4][4];
#pragma unroll
            for (int mt = 0; mt < 2; mt++)
                ldsm4(ah[mt], pA + mt * 2048 + (kb ^ xA));
#pragma unroll
            for (int g = 0; g < 4; g++)
                ldsm4(bb[g], pB + g * 2048 + (kb ^ xB));
#pragma unroll
            for (int mt = 0; mt < 2; mt++)
#pragma unroll
                for (int nt = 0; nt < 8; nt++) {
                    const int g = nt >> 1, o = nt & 1;
                    mma16816h(acc[mt][nt], ah[mt], bb[g][o], bb[g][o + 2]);
                }
        }
    }
    cp_wait<0>();
    __syncthreads();

    if (MODE == 0) {
#pragma unroll
        for (int mt = 0; mt < 2; mt++) {
            const int r0 = bm + warpM * 32 + mt * 16 + (lane >> 2);
            const float bv0 = bias[r0], bv1 = bias[r0 + 8];
#pragma unroll
            for (int nt = 0; nt < 8; nt++) {
                const int c0 = bn + warpN * 64 + nt * 8 + (lane & 3) * 2;
                float* d = acc[mt][nt];
                *reinterpret_cast<float2*>(&C[(size_t)r0 * N + c0])       = make_float2(d[0] + bv0, d[1] + bv0);
                *reinterpret_cast<float2*>(&C[(size_t)(r0 + 8) * N + c0]) = make_float2(d[2] + bv1, d[3] + bv1);
            }
        }
    } else {
        float* T = reinterpret_cast<float*>(smem);   // [128][130]
#pragma unroll
        for (int mt = 0; mt < 2; mt++) {
            const int lr0 = warpM * 32 + mt * 16 + (lane >> 2);
            const float bv0 = bias[bm + lr0], bv1 = bias[bm + lr0 + 8];
#pragma unroll
            for (int nt = 0; nt < 8; nt++) {
                const int lc0 = warpN * 64 + nt * 8 + (lane & 3) * 2;
                float* d = acc[mt][nt];
                T[lr0 * 130 + lc0]           = fmaxf(d[0] + bv0, 0.f);
                T[lr0 * 130 + lc0 + 1]       = fmaxf(d[1] + bv0, 0.f);
                T[(lr0 + 8) * 130 + lc0]     = fmaxf(d[2] + bv1, 0.f);
                T[(lr0 + 8) * 130 + lc0 + 1] = fmaxf(d[3] + bv1, 0.f);
            }
        }
        __syncthreads();
        const int mloc = tid & 127;
#pragma unroll 4
        for (int rep = 0; rep < 64; rep++) {
            const int nl = rep * 2 + (tid >> 7);
            oH[(size_t)(bn + nl) * M + bm + mloc] = __float2half(T[mloc * 130 + nl]);
        }
    }
}

// ---------------------------------------------------------------------------
// Row-attention scores: per head, S[i,j] = sum_k Q^T[i,k]*K^T[j,k], single pass.
// ---------------------------------------------------------------------------
__global__ void __launch_bounds__(256, 1)
gemm_scores(const __half* __restrict__ Q, const __half* __restrict__ Kt,
            float* __restrict__ S)
{
    constexpr int K = 512, N = 256;
    extern __shared__ char smem[];
    const uint32_t sb = smem_u32(smem);

    const int tid = threadIdx.x, wid = tid >> 5, lane = tid & 31;
    const int warpM = wid & 3, warpN = wid >> 2;
    const int bm = blockIdx.x * 128, bn = blockIdx.y * 128;
    const int h = blockIdx.z;
    const __half* A = Q  + (size_t)h * Lm * Dm;
    const __half* B = Kt + (size_t)h * Lm * Dm;
    float* C = S + (size_t)h * Lm * Lm;

    auto load_stage = [&](int st, int it) {
        const uint32_t sbase = sb + st * MM_SBYTES;
        const int k0 = it << 6;
#pragma unroll
        for (int j = 0; j < 4; j++) {
            const int idx = tid + j * 256;
            const int row = idx >> 3;
            const int c   = idx & 7;
            const uint32_t soff = row * 128 + ((c * 16) ^ ((row & 7) << 4));
            cpasync16(sbase +         soff, A + (size_t)(bm + row) * K + k0 + c * 8);
            cpasync16(sbase + 16384 + soff, B + (size_t)(bn + row) * K + k0 + c * 8);
        }
    };

    float acc[2][8][4];
#pragma unroll
    for (int i = 0; i < 2; i++)
#pragma unroll
        for (int j = 0; j < 8; j++)
#pragma unroll
            for (int v = 0; v < 4; v++) acc[i][j][v] = 0.f;

    load_stage(0, 0); cp_commit();
    load_stage(1, 1); cp_commit();

    const int rsub  = lane & 15;
    const int khalf = ((lane >> 4) & 1) * 16;
    const int rA = warpM * 32 + rsub;
    const int rB = warpN * 64 + rsub;
    const uint32_t xA = (rA & 7) << 4;
    const uint32_t xB = (rB & 7) << 4;

    for (int it = 0; it < 8; it++) {
        cp_wait<1>();
        __syncthreads();
        if (it + 2 < 8) load_stage((it + 2) % 3, it + 2);
        cp_commit();

        const uint32_t sbase = sb + (it % 3) * MM_SBYTES;
        const uint32_t pA = sbase +         rA * 128;
        const uint32_t pB = sbase + 16384 + rB * 128;

#pragma unroll
        for (int q = 0; q < 4; q++) {
            const uint32_t kb = q * 32 + khalf;
            uint32_t ah[2][4], bb[4][4];
#pragma unroll
            for (int mt = 0; mt < 2; mt++)
                ldsm4(ah[mt], pA + mt * 2048 + (kb ^ xA));
#pragma unroll
            for (int g = 0; g < 4; g++)
                ldsm4(bb[g], pB + g * 2048 + (kb ^ xB));
#pragma unroll
            for (int mt = 0; mt < 2; mt++)
#pragma unroll
                for (int nt = 0; nt < 8; nt++) {
                    const int g = nt >> 1, o = nt & 1;
                    mma16816h(acc[mt][nt], ah[mt], bb[g][o], bb[g][o + 2]);
                }
        }
    }
    cp_wait<0>();
    __syncthreads();

#pragma unroll
    for (int mt = 0; mt < 2; mt++) {
        const int r0 = bm + warpM * 32 + mt * 16 + (lane >> 2);
#pragma unroll
        for (int nt = 0; nt < 8; nt++) {
            const int c0 = bn + warpN * 64 + nt * 8 + (lane & 3) * 2;
            float* d = acc[mt][nt];
            *reinterpret_cast<float2*>(&C[(size_t)r0 * N + c0])       = make_float2(d[0], d[1]);
            *reinterpret_cast<float2*>(&C[(size_t)(r0 + 8) * N + c0]) = make_float2(d[2], d[3]);
        }
    }
}

// ---------------------------------------------------------------------------
// Row-attention output: per head, C[m=(c,s), i] = sum_j V[m,j] * P[i,j], single pass.
// ---------------------------------------------------------------------------
__global__ void __launch_bounds__(256, 1)
gemm_vp(const __half* __restrict__ V, const __half* __restrict__ P,
        float* __restrict__ O)
{
    constexpr int K = 256;
    extern __shared__ char smem[];
    const uint32_t sb = smem_u32(smem);

    const int tid = threadIdx.x, wid = tid >> 5, lane = tid & 31;
    const int warpM = wid & 3, warpN = wid >> 2;
    const int bm = blockIdx.x * 128, bn = blockIdx.y * 128;
    const int h = blockIdx.z;
    const __half* Av = V + (size_t)h * 8 * Pp;
    const __half* Bp = P + (size_t)h * Lm * Lm;
    float* C = O + (size_t)h * 8 * Pp;

    auto load_stage = [&](int st, int it) {
        const uint32_t sbase = sb + st * MM_SBYTES;
        const int k0 = it << 6;
#pragma unroll
        for (int j = 0; j < 4; j++) {
            const int idx = tid + j * 256;
            const int row = idx >> 3;
            const int c   = idx & 7;
            const uint32_t soff = row * 128 + ((c * 16) ^ ((row & 7) << 4));
            const int mrow = bm + row;
            const size_t ga = (size_t)(mrow >> 6) * Pp + (mrow & 63) * 256 + k0 + c * 8;
            cpasync16(sbase +         soff, Av + ga);
            cpasync16(sbase + 16384 + soff, Bp + (size_t)(bn + row) * K + k0 + c * 8);
        }
    };

    float acc[2][8][4];
#pragma unroll
    for (int i = 0; i < 2; i++)
#pragma unroll
        for (int j = 0; j < 8; j++)
#pragma unroll
            for (int v = 0; v < 4; v++) acc[i][j][v] = 0.f;

    load_stage(0, 0); cp_commit();
    load_stage(1, 1); cp_commit();

    const int rsub  = lane & 15;
    const int khalf = ((lane >> 4) & 1) * 16;
    const int rA = warpM * 32 + rsub;
    const int rB = warpN * 64 + rsub;
    const uint32_t xA = (rA & 7) << 4;
    const uint32_t xB = (rB & 7) << 4;

    for (int it = 0; it < 4; it++) {
        cp_wait<1>();
        __syncthreads();
        if (it + 2 < 4) load_stage((it + 2) % 3, it + 2);
        cp_commit();

        const uint32_t sbase = sb + (it % 3) * MM_SBYTES;
        const uint32_t pA = sbase +         rA * 128;
        const uint32_t pB = sbase + 16384 + rB * 128;

#pragma unroll
        for (int q = 0; q < 4; q++) {
            const uint32_t kb = q * 32 + khalf;
            uint32_t av[2][4], bb[4][4];
#pragma unroll
            for (int mt = 0; mt < 2; mt++)
                ldsm4(av[mt], pA + mt * 2048 + (kb ^ xA));
#pragma unroll
            for (int g = 0; g < 4; g++)
                ldsm4(bb[g], pB + g * 2048 + (kb ^ xB));
#pragma unroll
            for (int mt = 0; mt < 2; mt++)
#pragma unroll
                for (int nt = 0; nt < 8; nt++) {
                    const int g = nt >> 1, o = nt & 1;
                    mma16816h(acc[mt][nt], av[mt], bb[g][o], bb[g][o + 2]);
                }
        }
    }
    cp_wait<0>();
    __syncthreads();

#pragma unroll
    for (int mt = 0; mt < 2; mt++) {
        const int r0 = bm + warpM * 32 + mt * 16 + (lane >> 2);
        const int r1 = r0 + 8;
        const size_t a0 = (size_t)(r0 >> 6) * Pp + (r0 & 63) * 256;
        const size_t a1 = (size_t)(r1 >> 6) * Pp + (r1 & 63) * 256;
#pragma unroll
        for (int nt = 0; nt < 8; nt++) {
            const int c0 = bn + warpN * 64 + nt * 8 + (lane & 3) * 2;
            float* d = acc[mt][nt];
            *reinterpret_cast<float2*>(&C[a0 + c0]) = make_float2(d[0], d[1]);
            *reinterpret_cast<float2*>(&C[a1 + c0]) = make_float2(d[2], d[3]);
        }
    }
}

// ---------------------------------------------------------------------------
// Conversions
// ---------------------------------------------------------------------------
__global__ void convw1_kernel(const float* __restrict__ w, __half* __restrict__ oh, int n)
{
    int i = blockIdx.x * 256 + threadIdx.x;
    if (i < n) oh[i] = __float2half(w[i]);
}
// act fp32 [K, N] -> fp16 [N, K] (transposed)
__global__ void __launch_bounds__(256)
convt_kernel(const float* __restrict__ in, __half* __restrict__ oh, int K, int N)
{
    __shared__ float t[32][33];
    const int n0 = blockIdx.x * 32, k0 = blockIdx.y * 32;
    const int tx = threadIdx.x, ty = threadIdx.y;
#pragma unroll
    for (int i = 0; i < 4; i++)
        t[ty + 8 * i][tx] = in[(size_t)(k0 + ty + 8 * i) * N + n0 + tx];
    __syncthreads();
#pragma unroll
    for (int i = 0; i < 4; i++) {
        const int r = ty + 8 * i;
        oh[(size_t)(n0 + r) * K + k0 + tx] = __float2half(t[tx][r]);
    }
}
// Q/K per-head transpose-convert: in (c,s)-rows of [D][S][L]; out [h][l][k=(c*64+s)]
__global__ void __launch_bounds__(256)
convtqk_kernel(const float* __restrict__ qkv,
               __half* __restrict__ qo, __half* __restrict__ ko)
{
    __shared__ float t[32][33];
    const int h = blockIdx.z >> 1;
    const int isK = blockIdx.z & 1;
    const float* in = qkv + (isK ? (size_t)Dm * Pp : 0) + (size_t)h * 8 * Pp;
    __half* o = (isK ? ko : qo) + (size_t)h * Lm * Dm;
    const int l0 = blockIdx.x * 32, k0 = blockIdx.y * 32;
    const int tx = threadIdx.x, ty = threadIdx.y;
#pragma unroll
    for (int i = 0; i < 4; i++) {
        const int k = k0 + ty + 8 * i;
        t[ty + 8 * i][tx] = in[(size_t)(k >> 6) * Pp + (k & 63) * 256 + l0 + tx];
    }
    __syncthreads();
#pragma unroll
    for (int i = 0; i < 4; i++) {
        const int r = ty + 8 * i;
        o[(size_t)(l0 + r) * Dm + k0 + tx] = __float2half(t[tx][r]);
    }
}
// V fp32 -> fp16 elementwise
__global__ void convv_kernel(const float* __restrict__ v, __half* __restrict__ o, long n)
{
    long i = (long)blockIdx.x * 256 + threadIdx.x;
    if (i < n) o[i] = __float2half(v[i]);
}

// ---------------------------------------------------------------------------
// Row softmax over last axis -> P fp16
// ---------------------------------------------------------------------------
__global__ __launch_bounds__(256)
void softmax16_kernel(const float* __restrict__ S, __half* __restrict__ ph)
{
    __shared__ float red[8];
    const size_t row = blockIdx.x;
    const float* p = S + row * 256;
    const int t = threadIdx.x;
    const int lane = t & 31, warp = t >> 5;

    float v = p[t];
    float m = v;
#pragma unroll
    for (int o = 16; o; o >>= 1) m = fmaxf(m, __shfl_xor_sync(0xffffffffu, m, o));
    if (lane == 0) red[warp] = m;
    __syncthreads();
    float mm = red[0];
#pragma unroll
    for (int i = 1; i < 8; i++) mm = fmaxf(mm, red[i]);
    __syncthreads();

    float e = __expf(v - mm);
    float s = e;
#pragma unroll
    for (int o = 16; o; o >>= 1) s += __shfl_xor_sync(0xffffffffu, s, o);
    if (lane == 0) red[warp] = s;
    __syncthreads();
    float tot = 0.f;
#pragma unroll
    for (int i = 0; i < 8; i++) tot += red[i];

    ph[row * 256 + t] = __float2half(e / tot);
}

// ---------------------------------------------------------------------------
// Channel LayerNorm over D=512 (optional residual).
// Block (32 pos, 8 channel-slices); 512 blocks -> good SM coverage.
// ---------------------------------------------------------------------------
__global__ __launch_bounds__(256)
void ln_kernel(const float* __restrict__ in, const float* __restrict__ res,
               const float* __restrict__ w, const float* __restrict__ b,
               float* __restrict__ out)
{
    __shared__ float ss[8][32], ss2[8][32];
    const int tx = threadIdx.x, ty = threadIdx.y;
    const int pos = blockIdx.x * 32 + tx;

    float s = 0.f, s2 = 0.f;
    if (res) {
        for (int c = ty; c < Dm; c += 8) {
            float v = in[(size_t)c * Pp + pos] + res[(size_t)c * Pp + pos];
            s += v; s2 += v * v;
        }
    } else {
        for (int c = ty; c < Dm; c += 8) {
            float v = in[(size_t)c * Pp + pos];
            s += v; s2 += v * v;
        }
    }
    ss[ty][tx] = s; ss2[ty][tx] = s2;
    __syncthreads();
    float st = 0.f, st2 = 0.f;
#pragma unroll
    for (int y = 0; y < 8; y++) { st += ss[y][tx]; st2 += ss2[y][tx]; }
    const float mean = st * (1.f / Dm);
    const float var  = st2 * (1.f / Dm) - mean * mean;
    const float rstd = rsqrtf(var + EPS);

    if (res) {
        for (int c = ty; c < Dm; c += 8) {
            float v = in[(size_t)c * Pp + pos] + res[(size_t)c * Pp + pos];
            out[(size_t)c * Pp + pos] = (v - mean) * rstd * w[c] + b[c];
        }
    } else {
        for (int c = ty; c < Dm; c += 8) {
            float v = in[(size_t)c * Pp + pos];
            out[(size_t)c * Pp + pos] = (v - mean) * rstd * w[c] + b[c];
        }
    }
}

// ---------------------------------------------------------------------------
// Column attention — K/V loads amortized over 4 i-rows per thread.
// Block (32 l, 16 y); each thread: i = ty + 16*ii, ii=0..3. Direct exp.
// ---------------------------------------------------------------------------
__global__ __launch_bounds__(512)
void colattn_kernel(const float* __restrict__ qkv, float* __restrict__ out)
{
    const int h = blockIdx.z;
    const int l = blockIdx.x * 32 + threadIdx.x;
    const int ty = threadIdx.y;
    const float* Q  = qkv + (size_t)h * Cc * Pp;
    const float* Kp = Q + (size_t)Dm * Pp;
    const float* V  = Q + 2L * (size_t)Dm * Pp;

    float q[4][Cc];
#pragma unroll
    for (int ii = 0; ii < 4; ii++) {
        const int i = ty + 16 * ii;
#pragma unroll
        for (int c = 0; c < Cc; c++) q[ii][c] = Q[(size_t)c * Pp + i * Lm + l];
    }

    float d[4] = {0.f, 0.f, 0.f, 0.f};
    float acc[4][Cc];
#pragma unroll
    for (int ii = 0; ii < 4; ii++)
#pragma unroll
        for (int c = 0; c < Cc; c++) acc[ii][c] = 0.f;

    for (int j = 0; j < Sm; j++) {
        float kv[Cc], vv[Cc];
#pragma unroll
        for (int c = 0; c < Cc; c++) {
            kv[c] = Kp[(size_t)c * Pp + j * Lm + l];
            vv[c] = V [(size_t)c * Pp + j * Lm + l];
        }
#pragma unroll
        for (int ii = 0; ii < 4; ii++) {
            float sc = 0.f;
#pragma unroll
            for (int c = 0; c < Cc; c++) sc = fmaf(q[ii][c], kv[c], sc);
            const float e = __expf(sc);
            d[ii] += e;
#pragma unroll
            for (int c = 0; c < Cc; c++) acc[ii][c] = fmaf(e, vv[c], acc[ii][c]);
        }
    }
#pragma unroll
    for (int ii = 0; ii < 4; ii++) {
        const int i = ty + 16 * ii;
        const float inv = 1.f / d[ii];
#pragma unroll
        for (int c = 0; c < Cc; c++)
            out[(size_t)(h * Cc + c) * Pp + i * Lm + l] = acc[ii][c] * inv;
    }
}

// ---------------------------------------------------------------------------
// Host side
// ---------------------------------------------------------------------------
extern "C" void kernel_launch(void* const* d_in, const int* in_sizes, int n_in,
                              void* d_out, int out_size)
{
    const float* x     = (const float*)d_in[0];
    const float* w_row = (const float*)d_in[1];
    const float* b_row = (const float*)d_in[2];
    const float* w_col = (const float*)d_in[3];
    const float* b_col = (const float*)d_in[4];
    const float* w_an1 = (const float*)d_in[5];
    const float* b_an1 = (const float*)d_in[6];
    const float* w_an2 = (const float*)d_in[7];
    const float* b_an2 = (const float*)d_in[8];
    const float* w_ff1 = (const float*)d_in[9];
    const float* b_ff1 = (const float*)d_in[10];
    const float* w_ff2 = (const float*)d_in[11];
    const float* b_ff2 = (const float*)d_in[12];
    const float* w_ln1 = (const float*)d_in[13];
    const float* b_ln1 = (const float*)d_in[14];
    const float* w_ln2 = (const float*)d_in[15];
    const float* b_ln2 = (const float*)d_in[16];
    float* outp = (float*)d_out;

    float *qkv, *scores, *tmp, *out1, *attn;
    __half *bt, *ff, *wr, *wc, *f1, *f2, *qt, *kt, *v16, *p16;
    cudaGetSymbolAddress((void**)&qkv,    g_qkv);
    cudaGetSymbolAddress((void**)&scores, g_scores);
    cudaGetSymbolAddress((void**)&tmp,    g_tmp);
    cudaGetSymbolAddress((void**)&out1,   g_out1);
    cudaGetSymbolAddress((void**)&attn,   g_attn);
    cudaGetSymbolAddress((void**)&bt,     g_bt);
    cudaGetSymbolAddress((void**)&ff,     g_ff);
    cudaGetSymbolAddress((void**)&wr,     g_wr);
    cudaGetSymbolAddress((void**)&wc,     g_wc);
    cudaGetSymbolAddress((void**)&f1,     g_f1);
    cudaGetSymbolAddress((void**)&f2,     g_f2);
    cudaGetSymbolAddress((void**)&qt,     g_qt);
    cudaGetSymbolAddress((void**)&kt,     g_kt);
    cudaGetSymbolAddress((void**)&v16,    g_v16);
    cudaGetSymbolAddress((void**)&p16,    g_p16);

    cudaFuncSetAttribute(gemm_mma<0>, cudaFuncAttributeMaxDynamicSharedMemorySize, MM_SMEM);
    cudaFuncSetAttribute(gemm_mma<1>, cudaFuncAttributeMaxDynamicSharedMemorySize, MM_SMEM);
    cudaFuncSetAttribute(gemm_scores, cudaFuncAttributeMaxDynamicSharedMemorySize, MM_SMEM);
    cudaFuncSetAttribute(gemm_vp,     cudaFuncAttributeMaxDynamicSharedMemorySize, MM_SMEM);

    // weight conversions (single fp16)
    convw1_kernel<<<(3 * Dm * Dm + 255) / 256, 256>>>(w_row, wr, 3 * Dm * Dm);
    convw1_kernel<<<(3 * Dm * Dm + 255) / 256, 256>>>(w_col, wc, 3 * Dm * Dm);
    convw1_kernel<<<(Fm * Dm + 255) / 256, 256>>>(w_ff1, f1, Fm * Dm);
    convw1_kernel<<<(Dm * Fm + 255) / 256, 256>>>(w_ff2, f2, Dm * Fm);

    // x -> transposed fp16
    convt_kernel<<<dim3(Pp / 32, Dm / 32), dim3(32, 8)>>>(x, bt, Dm, Pp);

    // 1) row qkv = w_row @ x + b_row
    gemm_mma<0><<<dim3((3 * Dm) / 128, Pp / 128), 256, MM_SMEM>>>(
        wr, bt, b_row, qkv, nullptr, 3 * Dm, Pp, Dm);

    // 2) Q/K transpose-convert, V elementwise convert
    convtqk_kernel<<<dim3(Lm / 32, Dm / 32, 2 * Hh), dim3(32, 8)>>>(qkv, qt, kt);
    convv_kernel<<<(int)(((long)Dm * Pp + 255) / 256), 256>>>(qkv + 2L * Dm * Pp, v16, (long)Dm * Pp);

    // 3) scores + softmax -> P fp16
    gemm_scores<<<dim3(2, 2, Hh), 256, MM_SMEM>>>(qt, kt, scores);
    softmax16_kernel<<<Hh * Lm, 256>>>(scores, p16);

    // 4) row_out = V * P^T
    gemm_vp<<<dim3(4, 2, Hh), 256, MM_SMEM>>>(v16, p16, tmp);

    // 5) out1 = LN(x + row_out; an1); transpose-convert
    ln_kernel<<<Pp / 32, dim3(32, 8)>>>(x, tmp, w_an1, b_an1, out1);
    convt_kernel<<<dim3(Pp / 32, Dm / 32), dim3(32, 8)>>>(out1, bt, Dm, Pp);

    // 6) col qkv = w_col @ out1 + b_col
    gemm_mma<0><<<dim3((3 * Dm) / 128, Pp / 128), 256, MM_SMEM>>>(
        wc, bt, b_col, qkv, nullptr, 3 * Dm, Pp, Dm);

    // 7) column attention
    colattn_kernel<<<dim3(Lm / 32, 1, Hh), dim3(32, 16)>>>(qkv, tmp);

    // 8) attn_out = LN(out1 + col_out; an2)
    ln_kernel<<<Pp / 32, dim3(32, 8)>>>(out1, tmp, w_an2, b_an2, attn);

    // 9) h = LN(attn_out; ln1); transpose-convert
    ln_kernel<<<Pp / 32, dim3(32, 8)>>>(attn, nullptr, w_ln1, b_ln1, out1);
    convt_kernel<<<dim3(Pp / 32, Dm / 32), dim3(32, 8)>>>(out1, bt, Dm, Pp);

    // 10) ff1: relu(w_ff1 @ h + b_ff1) -> fp16 transposed
    gemm_mma<1><<<dim3(Fm / 128, Pp / 128), 256, MM_SMEM>>>(
        f1, bt, b_ff1, nullptr, ff, Fm, Pp, Dm);

    // 11) ff2 = w_ff2 @ ff1 + b_ff2
    gemm_mma<0><<<dim3(Dm / 128, Pp / 128), 256, MM_SMEM>>>(
        f2, ff, b_ff2, tmp, nullptr, Dm, Pp, Fm);

    // 12) out = LN(h + ff2; ln2)
    ln_kernel<<<Pp / 32, dim3(32, 8)>>>(out1, tmp, w_ln2, b_ln2, outp);
}

// round 7
// speedup vs baseline: 3.6493x; 1.0386x over previous
#include <cuda_runtime.h>
#include <cuda_fp16.h>
#include <math_constants.h>
#include <cstdint>
#include <cstddef>

// ---------------------------------------------------------------------------
// Problem constants
// ---------------------------------------------------------------------------
#define Dm   512
#define Sm   64
#define Lm   256
#define Fm   2048
#define Hh   64
#define Cc   8
#define Pp   (Sm * Lm)          // 16384 spatial positions
#define EPS  1e-5f

// ---------------------------------------------------------------------------
// Scratch buffers (static device globals -- allocation-free)
// ---------------------------------------------------------------------------
__device__ __align__(256) float g_qkv [3L * Dm * Pp];
__device__ __align__(256) float g_tmp [(long)Dm * Pp];
__device__ __align__(256) float g_out1[(long)Dm * Pp];
__device__ __align__(256) float g_attn[(long)Dm * Pp];

// fp16 operands (all single-plane)
__device__ __align__(256) __half g_bt [(long)Pp * Dm];   // act^T [Pp,512]
__device__ __align__(256) __half g_ff [(long)Pp * Fm];   // ff1^T [Pp,2048]
__device__ __align__(256) __half g_wr [3 * Dm * Dm];
__device__ __align__(256) __half g_wc [3 * Dm * Dm];
__device__ __align__(256) __half g_f1 [Fm * Dm];
__device__ __align__(256) __half g_f2 [Dm * Fm];
__device__ __align__(256) __half g_qt [(long)Hh * Lm * Dm];  // Q^T per head [h][i][k]
__device__ __align__(256) __half g_kt [(long)Hh * Lm * Dm];  // K^T per head [h][j][k]
__device__ __align__(256) __half g_v16[(long)Dm * Pp];       // V fp16 (qkv layout)
__device__ __align__(256) __half g_p16[(long)Hh * Lm * Lm];  // P [h][i][j]

// ---------------------------------------------------------------------------
// PTX helpers
// ---------------------------------------------------------------------------
__device__ __forceinline__ uint32_t smem_u32(const void* p) {
    uint32_t a;
    asm("{ .reg .u64 t; cvta.to.shared.u64 t, %1; cvt.u32.u64 %0, t; }" : "=r"(a) : "l"(p));
    return a;
}
__device__ __forceinline__ void cpasync16(uint32_t dst, const void* src) {
    asm volatile("cp.async.cg.shared.global [%0], [%1], 16;" :: "r"(dst), "l"(src));
}
__device__ __forceinline__ void cp_commit() {
    asm volatile("cp.async.commit_group;" ::: "memory");
}
template<int N>
__device__ __forceinline__ void cp_wait() {
    asm volatile("cp.async.wait_group %0;" :: "n"(N) : "memory");
}
__device__ __forceinline__ void ldsm4(uint32_t* r, uint32_t addr) {
    asm volatile("ldmatrix.sync.aligned.m8n8.x4.shared.b16 {%0,%1,%2,%3}, [%4];"
                 : "=r"(r[0]), "=r"(r[1]), "=r"(r[2]), "=r"(r[3]) : "r"(addr));
}
__device__ __forceinline__ void mma16816h(float* d, const uint32_t* a, uint32_t b0, uint32_t b1) {
    asm volatile("mma.sync.aligned.m16n8k16.row.col.f32.f16.f16.f32 "
                 "{%0,%1,%2,%3}, {%4,%5,%6,%7}, {%8,%9}, {%0,%1,%2,%3};"
                 : "+f"(d[0]), "+f"(d[1]), "+f"(d[2]), "+f"(d[3])
                 : "r"(a[0]), "r"(a[1]), "r"(a[2]), "r"(a[3]), "r"(b0), "r"(b1));
}

// ---------------------------------------------------------------------------
// Big GEMM: C[M,N] = W[M,K] * B[N,K]^T (+bias), single fp16 pass.
//   MODE 0: C fp32 [M,N] + bias; if oV != null, ALSO write fp16 copy for
//           rows >= 1024 (the V section of the row-qkv output).
//   MODE 1: relu(+bias) -> fp16 transposed [N,M].
// ---------------------------------------------------------------------------
#define MM_SBYTES 32768u
#define MM_SMEM   (3 * MM_SBYTES)

template<int MODE>
__global__ void __launch_bounds__(256, 1)
gemm_mma(const __half* __restrict__ A, const __half* __restrict__ B,
         const float* __restrict__ bias,
         float* __restrict__ C, __half* __restrict__ oH, __half* __restrict__ oV,
         int M, int N, int K)
{
    extern __shared__ char smem[];
    const uint32_t sb = smem_u32(smem);

    const int tid  = threadIdx.x;
    const int wid  = tid >> 5;
    const int lane = tid & 31;
    const int warpM = wid & 3;
    const int warpN = wid >> 2;
    const int bm = blockIdx.x * 128;
    const int bn = blockIdx.y * 128;

    auto load_stage = [&](int st, int it) {
        const uint32_t sbase = sb + st * MM_SBYTES;
        const int k0 = it << 6;
#pragma unroll
        for (int j = 0; j < 4; j++) {
            const int idx = tid + j * 256;
            const int row = idx >> 3;
            const int c   = idx & 7;
            const uint32_t soff = row * 128 + ((c * 16) ^ ((row & 7) << 4));
            cpasync16(sbase +         soff, A + (size_t)(bm + row) * K + k0 + c * 8);
            cpasync16(sbase + 16384 + soff, B + (size_t)(bn + row) * K + k0 + c * 8);
        }
    };

    float acc[2][8][4];
#pragma unroll
    for (int i = 0; i < 2; i++)
#pragma unroll
        for (int j = 0; j < 8; j++)
#pragma unroll
            for (int v = 0; v < 4; v++) acc[i][j][v] = 0.f;

    const int nIter = K >> 6;
    load_stage(0, 0); cp_commit();
    load_stage(1, 1); cp_commit();

    const int rsub  = lane & 15;
    const int khalf = ((lane >> 4) & 1) * 16;
    const int rA = warpM * 32 + rsub;
    const int rB = warpN * 64 + rsub;
    const uint32_t xA = (rA & 7) << 4;
    const uint32_t xB = (rB & 7) << 4;

    for (int it = 0; it < nIter; it++) {
        cp_wait<1>();
        __syncthreads();
        if (it + 2 < nIter) load_stage((it + 2) % 3, it + 2);
        cp_commit();

        const uint32_t sbase = sb + (it % 3) * MM_SBYTES;
        const uint32_t pA = sbase +         rA * 128;
        const uint32_t pB = sbase + 16384 + rB * 128;

#pragma unroll
        for (int q = 0; q < 4; q++) {
            const uint32_t kb = q * 32 + khalf;
            uint32_t ah[2][4], bb[4][4];
#pragma unroll
            for (int mt = 0; mt < 2; mt++)
                ldsm4(ah[mt], pA + mt * 2048 + (kb ^ xA));
#pragma unroll
            for (int g = 0; g < 4; g++)
                ldsm4(bb[g], pB + g * 2048 + (kb ^ xB));
#pragma unroll
            for (int mt = 0; mt < 2; mt++)
#pragma unroll
                for (int nt = 0; nt < 8; nt++) {
                    const int g = nt >> 1, o = nt & 1;
                    mma16816h(acc[mt][nt], ah[mt], bb[g][o], bb[g][o + 2]);
                }
        }
    }
    cp_wait<0>();
    __syncthreads();

    if (MODE == 0) {
        const bool wv = (oV != nullptr) && (bm >= 1024);
#pragma unroll
        for (int mt = 0; mt < 2; mt++) {
            const int r0 = bm + warpM * 32 + mt * 16 + (lane >> 2);
            const float bv0 = bias[r0], bv1 = bias[r0 + 8];
#pragma unroll
            for (int nt = 0; nt < 8; nt++) {
                const int c0 = bn + warpN * 64 + nt * 8 + (lane & 3) * 2;
                float* d = acc[mt][nt];
                const float v00 = d[0] + bv0, v01 = d[1] + bv0;
                const float v10 = d[2] + bv1, v11 = d[3] + bv1;
                *reinterpret_cast<float2*>(&C[(size_t)r0 * N + c0])       = make_float2(v00, v01);
                *reinterpret_cast<float2*>(&C[(size_t)(r0 + 8) * N + c0]) = make_float2(v10, v11);
                if (wv) {
                    *reinterpret_cast<__half2*>(&oV[(size_t)(r0 - 1024) * N + c0]) = __floats2half2_rn(v00, v01);
                    *reinterpret_cast<__half2*>(&oV[(size_t)(r0 - 1016) * N + c0]) = __floats2half2_rn(v10, v11);
                }
            }
        }
    } else {
        float* T = reinterpret_cast<float*>(smem);   // [128][130]
#pragma unroll
        for (int mt = 0; mt < 2; mt++) {
            const int lr0 = warpM * 32 + mt * 16 + (lane >> 2);
            const float bv0 = bias[bm + lr0], bv1 = bias[bm + lr0 + 8];
#pragma unroll
            for (int nt = 0; nt < 8; nt++) {
                const int lc0 = warpN * 64 + nt * 8 + (lane & 3) * 2;
                float* d = acc[mt][nt];
                T[lr0 * 130 + lc0]           = fmaxf(d[0] + bv0, 0.f);
                T[lr0 * 130 + lc0 + 1]       = fmaxf(d[1] + bv0, 0.f);
                T[(lr0 + 8) * 130 + lc0]     = fmaxf(d[2] + bv1, 0.f);
                T[(lr0 + 8) * 130 + lc0 + 1] = fmaxf(d[3] + bv1, 0.f);
            }
        }
        __syncthreads();
        const int mloc = tid & 127;
#pragma unroll 4
        for (int rep = 0; rep < 64; rep++) {
            const int nl = rep * 2 + (tid >> 7);
            oH[(size_t)(bn + nl) * M + bm + mloc] = __float2half(T[mloc * 130 + nl]);
        }
    }
}

// ---------------------------------------------------------------------------
// Row-attention scores + FUSED softmax: per head tile 64(i) x 256(j), K=512.
// Epilogue: stage S in smem, row-softmax, emit P fp16 directly.
// ---------------------------------------------------------------------------
#define SC_SBYTES 40960u          // A 8KB + B 32KB per stage
#define SC_SMEM   (3 * SC_SBYTES) // 120KB > 64*260*4 for the softmax tile

__global__ void __launch_bounds__(256, 1)
gemm_scores(const __half* __restrict__ Q, const __half* __restrict__ Kt,
            __half* __restrict__ P)
{
    constexpr int K = 512;
    extern __shared__ char smem[];
    const uint32_t sb = smem_u32(smem);

    const int tid = threadIdx.x, wid = tid >> 5, lane = tid & 31;
    const int warpM = wid & 3;      // 4 x 16 rows
    const int warpN = wid >> 2;     // 2 x 128 cols
    const int bm = blockIdx.x * 64;
    const int h = blockIdx.z;
    const __half* A = Q  + (size_t)h * Lm * Dm;
    const __half* B = Kt + (size_t)h * Lm * Dm;

    auto load_stage = [&](int st, int it) {
        const uint32_t sbase = sb + st * SC_SBYTES;
        const int k0 = it << 6;
#pragma unroll
        for (int j = 0; j < 10; j++) {
            const int idx = tid + j * 256;          // 0..2559
            if (idx < 512) {
                const int row = idx >> 3, c = idx & 7;
                const uint32_t soff = row * 128 + ((c * 16) ^ ((row & 7) << 4));
                cpasync16(sbase + soff, A + (size_t)(bm + row) * K + k0 + c * 8);
            } else {
                const int i2 = idx - 512;
                const int row = i2 >> 3, c = i2 & 7;
                const uint32_t soff = row * 128 + ((c * 16) ^ ((row & 7) << 4));
                cpasync16(sbase + 8192 + soff, B + (size_t)row * K + k0 + c * 8);
            }
        }
    };

    float acc[16][4];
#pragma unroll
    for (int j = 0; j < 16; j++)
#pragma unroll
        for (int v = 0; v < 4; v++) acc[j][v] = 0.f;

    load_stage(0, 0); cp_commit();
    load_stage(1, 1); cp_commit();

    const int rsub  = lane & 15;
    const int khalf = ((lane >> 4) & 1) * 16;
    const int rA = warpM * 16 + rsub;
    const int rBb = warpN * 128 + rsub;
    const uint32_t xs = (rsub & 7) << 4;

    for (int it = 0; it < 8; it++) {
        cp_wait<1>();
        __syncthreads();
        if (it + 2 < 8) load_stage((it + 2) % 3, it + 2);
        cp_commit();

        const uint32_t sbase = sb + (it % 3) * SC_SBYTES;
        const uint32_t pA = sbase +        rA  * 128;
        const uint32_t pB = sbase + 8192 + rBb * 128;

#pragma unroll
        for (int q = 0; q < 4; q++) {
            const uint32_t kb = q * 32 + khalf;
            uint32_t ah[4], bb[8][4];
            ldsm4(ah, pA + (kb ^ xs));
#pragma unroll
            for (int g = 0; g < 8; g++)
                ldsm4(bb[g], pB + g * 2048 + (kb ^ xs));
#pragma unroll
            for (int nt = 0; nt < 16; nt++) {
                const int g = nt >> 1, o = nt & 1;
                mma16816h(acc[nt], ah, bb[g][o], bb[g][o + 2]);
            }
        }
    }
    cp_wait<0>();
    __syncthreads();

    // stage S tile [64][260] fp32 in smem
    float* S = reinterpret_cast<float*>(smem);
    {
        const int r0 = warpM * 16 + (lane >> 2);
#pragma unroll
        for (int nt = 0; nt < 16; nt++) {
            const int c0 = warpN * 128 + nt * 8 + (lane & 3) * 2;
            float* d = acc[nt];
            S[r0 * 260 + c0]           = d[0];
            S[r0 * 260 + c0 + 1]       = d[1];
            S[(r0 + 8) * 260 + c0]     = d[2];
            S[(r0 + 8) * 260 + c0 + 1] = d[3];
        }
    }
    __syncthreads();

    // row softmax: each warp handles 8 rows; lane holds j = lane + 32k
#pragma unroll
    for (int rr = 0; rr < 8; rr++) {
        const int r = wid * 8 + rr;
        float v[8];
#pragma unroll
        for (int k = 0; k < 8; k++) v[k] = S[r * 260 + lane + 32 * k];
        float m = v[0];
#pragma unroll
        for (int k = 1; k < 8; k++) m = fmaxf(m, v[k]);
#pragma unroll
        for (int o = 16; o; o >>= 1) m = fmaxf(m, __shfl_xor_sync(0xffffffffu, m, o));
        float s = 0.f;
#pragma unroll
        for (int k = 0; k < 8; k++) { v[k] = __expf(v[k] - m); s += v[k]; }
#pragma unroll
        for (int o = 16; o; o >>= 1) s += __shfl_xor_sync(0xffffffffu, s, o);
        const float inv = 1.f / s;
        __half* dst = P + ((size_t)h * Lm + bm + r) * Lm;
#pragma unroll
        for (int k = 0; k < 8; k++) dst[lane + 32 * k] = __float2half(v[k] * inv);
    }
}

// ---------------------------------------------------------------------------
// Row-attention output: per head, C[m=(c,s), i] = sum_j V[m,j] * P[i,j].
// ---------------------------------------------------------------------------
__global__ void __launch_bounds__(256, 1)
gemm_vp(const __half* __restrict__ V, const __half* __restrict__ P,
        float* __restrict__ O)
{
    constexpr int K = 256;
    extern __shared__ char smem[];
    const uint32_t sb = smem_u32(smem);

    const int tid = threadIdx.x, wid = tid >> 5, lane = tid & 31;
    const int warpM = wid & 3, warpN = wid >> 2;
    const int bm = blockIdx.x * 128, bn = blockIdx.y * 128;
    const int h = blockIdx.z;
    const __half* Av = V + (size_t)h * 8 * Pp;
    const __half* Bp = P + (size_t)h * Lm * Lm;
    float* C = O + (size_t)h * 8 * Pp;

    auto load_stage = [&](int st, int it) {
        const uint32_t sbase = sb + st * MM_SBYTES;
        const int k0 = it << 6;
#pragma unroll
        for (int j = 0; j < 4; j++) {
            const int idx = tid + j * 256;
            const int row = idx >> 3;
            const int c   = idx & 7;
            const uint32_t soff = row * 128 + ((c * 16) ^ ((row & 7) << 4));
            const int mrow = bm + row;
            const size_t ga = (size_t)(mrow >> 6) * Pp + (mrow & 63) * 256 + k0 + c * 8;
            cpasync16(sbase +         soff, Av + ga);
            cpasync16(sbase + 16384 + soff, Bp + (size_t)(bn + row) * K + k0 + c * 8);
        }
    };

    float acc[2][8][4];
#pragma unroll
    for (int i = 0; i < 2; i++)
#pragma unroll
        for (int j = 0; j < 8; j++)
#pragma unroll
            for (int v = 0; v < 4; v++) acc[i][j][v] = 0.f;

    load_stage(0, 0); cp_commit();
    load_stage(1, 1); cp_commit();

    const int rsub  = lane & 15;
    const int khalf = ((lane >> 4) & 1) * 16;
    const int rA = warpM * 32 + rsub;
    const int rB = warpN * 64 + rsub;
    const uint32_t xA = (rA & 7) << 4;
    const uint32_t xB = (rB & 7) << 4;

    for (int it = 0; it < 4; it++) {
        cp_wait<1>();
        __syncthreads();
        if (it + 2 < 4) load_stage((it + 2) % 3, it + 2);
        cp_commit();

        const uint32_t sbase = sb + (it % 3) * MM_SBYTES;
        const uint32_t pA = sbase +         rA * 128;
        const uint32_t pB = sbase + 16384 + rB * 128;

#pragma unroll
        for (int q = 0; q < 4; q++) {
            const uint32_t kb = q * 32 + khalf;
            uint32_t av[2][4], bb[4][4];
#pragma unroll
            for (int mt = 0; mt < 2; mt++)
                ldsm4(av[mt], pA + mt * 2048 + (kb ^ xA));
#pragma unroll
            for (int g = 0; g < 4; g++)
                ldsm4(bb[g], pB + g * 2048 + (kb ^ xB));
#pragma unroll
            for (int mt = 0; mt < 2; mt++)
#pragma unroll
                for (int nt = 0; nt < 8; nt++) {
                    const int g = nt >> 1, o = nt & 1;
                    mma16816h(acc[mt][nt], av[mt], bb[g][o], bb[g][o + 2]);
                }
        }
    }
    cp_wait<0>();
    __syncthreads();

#pragma unroll
    for (int mt = 0; mt < 2; mt++) {
        const int r0 = bm + warpM * 32 + mt * 16 + (lane >> 2);
        const int r1 = r0 + 8;
        const size_t a0 = (size_t)(r0 >> 6) * Pp + (r0 & 63) * 256;
        const size_t a1 = (size_t)(r1 >> 6) * Pp + (r1 & 63) * 256;
#pragma unroll
        for (int nt = 0; nt < 8; nt++) {
            const int c0 = bn + warpN * 64 + nt * 8 + (lane & 3) * 2;
            float* d = acc[mt][nt];
            *reinterpret_cast<float2*>(&C[a0 + c0]) = make_float2(d[0], d[1]);
            *reinterpret_cast<float2*>(&C[a1 + c0]) = make_float2(d[2], d[3]);
        }
    }
}

// ---------------------------------------------------------------------------
// Conversions
// ---------------------------------------------------------------------------
__global__ void convw1_kernel(const float* __restrict__ w, __half* __restrict__ oh, int n)
{
    int i = blockIdx.x * 256 + threadIdx.x;
    if (i < n) oh[i] = __float2half(w[i]);
}
// act fp32 [K, N] -> fp16 [N, K] (transposed) — only for the initial x
__global__ void __launch_bounds__(256)
convt_kernel(const float* __restrict__ in, __half* __restrict__ oh, int K, int N)
{
    __shared__ float t[32][33];
    const int n0 = blockIdx.x * 32, k0 = blockIdx.y * 32;
    const int tx = threadIdx.x, ty = threadIdx.y;
#pragma unroll
    for (int i = 0; i < 4; i++)
        t[ty + 8 * i][tx] = in[(size_t)(k0 + ty + 8 * i) * N + n0 + tx];
    __syncthreads();
#pragma unroll
    for (int i = 0; i < 4; i++) {
        const int r = ty + 8 * i;
        oh[(size_t)(n0 + r) * K + k0 + tx] = __float2half(t[tx][r]);
    }
}
// Q/K per-head transpose-convert
__global__ void __launch_bounds__(256)
convtqk_kernel(const float* __restrict__ qkv,
               __half* __restrict__ qo, __half* __restrict__ ko)
{
    __shared__ float t[32][33];
    const int h = blockIdx.z >> 1;
    const int isK = blockIdx.z & 1;
    const float* in = qkv + (isK ? (size_t)Dm * Pp : 0) + (size_t)h * 8 * Pp;
    __half* o = (isK ? ko : qo) + (size_t)h * Lm * Dm;
    const int l0 = blockIdx.x * 32, k0 = blockIdx.y * 32;
    const int tx = threadIdx.x, ty = threadIdx.y;
#pragma unroll
    for (int i = 0; i < 4; i++) {
        const int k = k0 + ty + 8 * i;
        t[ty + 8 * i][tx] = in[(size_t)(k >> 6) * Pp + (k & 63) * 256 + l0 + tx];
    }
    __syncthreads();
#pragma unroll
    for (int i = 0; i < 4; i++) {
        const int r = ty + 8 * i;
        o[(size_t)(l0 + r) * Dm + k0 + tx] = __float2half(t[tx][r]);
    }
}

// ---------------------------------------------------------------------------
// Channel LayerNorm over D=512 (optional residual), optionally emitting a
// transposed fp16 copy (obt) via conflict-free smem staging.
// Block (32 pos, 8 ch-slices).
// ---------------------------------------------------------------------------
__global__ __launch_bounds__(256)
void ln_kernel(const float* __restrict__ in, const float* __restrict__ res,
               const float* __restrict__ w, const float* __restrict__ b,
               float* __restrict__ out, __half* __restrict__ obt)
{
    __shared__ float ss[8][32], ss2[8][32];
    __shared__ __half tbuf[32][514];
    const int tx = threadIdx.x, ty = threadIdx.y;
    const int tid = ty * 32 + tx;
    const int pos0 = blockIdx.x * 32;
    const int pos = pos0 + tx;

    float s = 0.f, s2 = 0.f;
    if (res) {
        for (int c = ty; c < Dm; c += 8) {
            float v = in[(size_t)c * Pp + pos] + res[(size_t)c * Pp + pos];
            s += v; s2 += v * v;
        }
    } else {
        for (int c = ty; c < Dm; c += 8) {
            float v = in[(size_t)c * Pp + pos];
            s += v; s2 += v * v;
        }
    }
    ss[ty][tx] = s; ss2[ty][tx] = s2;
    __syncthreads();
    float st = 0.f, st2 = 0.f;
#pragma unroll
    for (int y = 0; y < 8; y++) { st += ss[y][tx]; st2 += ss2[y][tx]; }
    const float mean = st * (1.f / Dm);
    const float var  = st2 * (1.f / Dm) - mean * mean;
    const float rstd = rsqrtf(var + EPS);

    if (res) {
        for (int c = ty; c < Dm; c += 8) {
            float v = in[(size_t)c * Pp + pos] + res[(size_t)c * Pp + pos];
            const float o = (v - mean) * rstd * w[c] + b[c];
            out[(size_t)c * Pp + pos] = o;
            if (obt) tbuf[tx][c] = __float2half(o);
        }
    } else {
        for (int c = ty; c < Dm; c += 8) {
            float v = in[(size_t)c * Pp + pos];
            const float o = (v - mean) * rstd * w[c] + b[c];
            out[(size_t)c * Pp + pos] = o;
            if (obt) tbuf[tx][c] = __float2half(o);
        }
    }
    if (obt) {
        __syncthreads();
        // write 32 rows of 512 halves; one row per iteration, coalesced uint32
#pragma unroll 4
        for (int r = 0; r < 32; r++) {
            const uint32_t val = *reinterpret_cast<const uint32_t*>(&tbuf[r][tid * 2]);
            *reinterpret_cast<uint32_t*>(&obt[(size_t)(pos0 + r) * Dm + tid * 2]) = val;
        }
    }
}

// ---------------------------------------------------------------------------
// Column attention — K/V loads amortized over 4 i-rows per thread.
// ---------------------------------------------------------------------------
__global__ __launch_bounds__(512)
void colattn_kernel(const float* __restrict__ qkv, float* __restrict__ out)
{
    const int h = blockIdx.z;
    const int l = blockIdx.x * 32 + threadIdx.x;
    const int ty = threadIdx.y;
    const float* Q  = qkv + (size_t)h * Cc * Pp;
    const float* Kp = Q + (size_t)Dm * Pp;
    const float* V  = Q + 2L * (size_t)Dm * Pp;

    float q[4][Cc];
#pragma unroll
    for (int ii = 0; ii < 4; ii++) {
        const int i = ty + 16 * ii;
#pragma unroll
        for (int c = 0; c < Cc; c++) q[ii][c] = Q[(size_t)c * Pp + i * Lm + l];
    }

    float d[4] = {0.f, 0.f, 0.f, 0.f};
    float acc[4][Cc];
#pragma unroll
    for (int ii = 0; ii < 4; ii++)
#pragma unroll
        for (int c = 0; c < Cc; c++) acc[ii][c] = 0.f;

    for (int j = 0; j < Sm; j++) {
        float kv[Cc], vv[Cc];
#pragma unroll
        for (int c = 0; c < Cc; c++) {
            kv[c] = Kp[(size_t)c * Pp + j * Lm + l];
            vv[c] = V [(size_t)c * Pp + j * Lm + l];
        }
#pragma unroll
        for (int ii = 0; ii < 4; ii++) {
            float sc = 0.f;
#pragma unroll
            for (int c = 0; c < Cc; c++) sc = fmaf(q[ii][c], kv[c], sc);
            const float e = __expf(sc);
            d[ii] += e;
#pragma unroll
            for (int c = 0; c < Cc; c++) acc[ii][c] = fmaf(e, vv[c], acc[ii][c]);
        }
    }
#pragma unroll
    for (int ii = 0; ii < 4; ii++) {
        const int i = ty + 16 * ii;
        const float inv = 1.f / d[ii];
#pragma unroll
        for (int c = 0; c < Cc; c++)
            out[(size_t)(h * Cc + c) * Pp + i * Lm + l] = acc[ii][c] * inv;
    }
}

// ---------------------------------------------------------------------------
// Host side
// ---------------------------------------------------------------------------
extern "C" void kernel_launch(void* const* d_in, const int* in_sizes, int n_in,
                              void* d_out, int out_size)
{
    const float* x     = (const float*)d_in[0];
    const float* w_row = (const float*)d_in[1];
    const float* b_row = (const float*)d_in[2];
    const float* w_col = (const float*)d_in[3];
    const float* b_col = (const float*)d_in[4];
    const float* w_an1 = (const float*)d_in[5];
    const float* b_an1 = (const float*)d_in[6];
    const float* w_an2 = (const float*)d_in[7];
    const float* b_an2 = (const float*)d_in[8];
    const float* w_ff1 = (const float*)d_in[9];
    const float* b_ff1 = (const float*)d_in[10];
    const float* w_ff2 = (const float*)d_in[11];
    const float* b_ff2 = (const float*)d_in[12];
    const float* w_ln1 = (const float*)d_in[13];
    const float* b_ln1 = (const float*)d_in[14];
    const float* w_ln2 = (const float*)d_in[15];
    const float* b_ln2 = (const float*)d_in[16];
    float* outp = (float*)d_out;

    float *qkv, *tmp, *out1, *attn;
    __half *bt, *ff, *wr, *wc, *f1, *f2, *qt, *kt, *v16, *p16;
    cudaGetSymbolAddress((void**)&qkv,  g_qkv);
    cudaGetSymbolAddress((void**)&tmp,  g_tmp);
    cudaGetSymbolAddress((void**)&out1, g_out1);
    cudaGetSymbolAddress((void**)&attn, g_attn);
    cudaGetSymbolAddress((void**)&bt,   g_bt);
    cudaGetSymbolAddress((void**)&ff,   g_ff);
    cudaGetSymbolAddress((void**)&wr,   g_wr);
    cudaGetSymbolAddress((void**)&wc,   g_wc);
    cudaGetSymbolAddress((void**)&f1,   g_f1);
    cudaGetSymbolAddress((void**)&f2,   g_f2);
    cudaGetSymbolAddress((void**)&qt,   g_qt);
    cudaGetSymbolAddress((void**)&kt,   g_kt);
    cudaGetSymbolAddress((void**)&v16,  g_v16);
    cudaGetSymbolAddress((void**)&p16,  g_p16);

    cudaFuncSetAttribute(gemm_mma<0>, cudaFuncAttributeMaxDynamicSharedMemorySize, MM_SMEM);
    cudaFuncSetAttribute(gemm_mma<1>, cudaFuncAttributeMaxDynamicSharedMemorySize, MM_SMEM);
    cudaFuncSetAttribute(gemm_scores, cudaFuncAttributeMaxDynamicSharedMemorySize, SC_SMEM);
    cudaFuncSetAttribute(gemm_vp,     cudaFuncAttributeMaxDynamicSharedMemorySize, MM_SMEM);

    // weight conversions
    convw1_kernel<<<(3 * Dm * Dm + 255) / 256, 256>>>(w_row, wr, 3 * Dm * Dm);
    convw1_kernel<<<(3 * Dm * Dm + 255) / 256, 256>>>(w_col, wc, 3 * Dm * Dm);
    convw1_kernel<<<(Fm * Dm + 255) / 256, 256>>>(w_ff1, f1, Fm * Dm);
    convw1_kernel<<<(Dm * Fm + 255) / 256, 256>>>(w_ff2, f2, Dm * Fm);

    // x -> transposed fp16
    convt_kernel<<<dim3(Pp / 32, Dm / 32), dim3(32, 8)>>>(x, bt, Dm, Pp);

    // 1) row qkv = w_row @ x + b_row ; V section also emitted as fp16
    gemm_mma<0><<<dim3((3 * Dm) / 128, Pp / 128), 256, MM_SMEM>>>(
        wr, bt, b_row, qkv, nullptr, v16, 3 * Dm, Pp, Dm);

    // 2) Q/K transpose-convert
    convtqk_kernel<<<dim3(Lm / 32, Dm / 32, 2 * Hh), dim3(32, 8)>>>(qkv, qt, kt);

    // 3) scores + fused softmax -> P fp16
    gemm_scores<<<dim3(Lm / 64, 1, Hh), 256, SC_SMEM>>>(qt, kt, p16);

    // 4) row_out = V * P^T
    gemm_vp<<<dim3(4, 2, Hh), 256, MM_SMEM>>>(v16, p16, tmp);

    // 5) out1 = LN(x + row_out; an1), fused transposed fp16 -> bt
    ln_kernel<<<Pp / 32, dim3(32, 8)>>>(x, tmp, w_an1, b_an1, out1, bt);

    // 6) col qkv = w_col @ out1 + b_col
    gemm_mma<0><<<dim3((3 * Dm) / 128, Pp / 128), 256, MM_SMEM>>>(
        wc, bt, b_col, qkv, nullptr, nullptr, 3 * Dm, Pp, Dm);

    // 7) column attention
    colattn_kernel<<<dim3(Lm / 32, 1, Hh), dim3(32, 16)>>>(qkv, tmp);

    // 8) attn_out = LN(out1 + col_out; an2)
    ln_kernel<<<Pp / 32, dim3(32, 8)>>>(out1, tmp, w_an2, b_an2, attn, nullptr);

    // 9) h = LN(attn_out; ln1), fused transposed fp16 -> bt
    ln_kernel<<<Pp / 32, dim3(32, 8)>>>(attn, nullptr, w_ln1, b_ln1, out1, bt);

    // 10) ff1: relu(w_ff1 @ h + b_ff1) -> fp16 transposed
    gemm_mma<1><<<dim3(Fm / 128, Pp / 128), 256, MM_SMEM>>>(
        f1, bt, b_ff1, nullptr, ff, nullptr, Fm, Pp, Dm);

    // 11) ff2 = w_ff2 @ ff1 + b_ff2
    gemm_mma<0><<<dim3(Dm / 128, Pp / 128), 256, MM_SMEM>>>(
        f2, ff, b_ff2, tmp, nullptr, nullptr, Dm, Pp, Fm);

    // 12) out = LN(h + ff2; ln2)
    ln_kernel<<<Pp / 32, dim3(32, 8)>>>(out1, tmp, w_ln2, b_ln2, outp, nullptr);
}

// round 8
// speedup vs baseline: 3.7367x; 1.0240x over previous
#include <cuda_runtime.h>
#include <cuda_fp16.h>
#include <math_constants.h>
#include <cstdint>
#include <cstddef>

// ---------------------------------------------------------------------------
// Problem constants
// ---------------------------------------------------------------------------
#define Dm   512
#define Sm   64
#define Lm   256
#define Fm   2048
#define Hh   64
#define Cc   8
#define Pp   (Sm * Lm)          // 16384 spatial positions
#define EPS  1e-5f

// ---------------------------------------------------------------------------
// Scratch buffers (static device globals -- allocation-free)
// ---------------------------------------------------------------------------
__device__ __align__(256) float g_qkv [3L * Dm * Pp];
__device__ __align__(256) float g_tmp [(long)Dm * Pp];
__device__ __align__(256) float g_out1[(long)Dm * Pp];
__device__ __align__(256) float g_attn[(long)Dm * Pp];

// fp16 operands (all single-plane)
__device__ __align__(256) __half g_bt [(long)Pp * Dm];   // act^T [Pp,512]
__device__ __align__(256) __half g_ff [(long)Pp * Fm];   // ff1^T [Pp,2048]
__device__ __align__(256) __half g_wr [3 * Dm * Dm];
__device__ __align__(256) __half g_wc [3 * Dm * Dm];
__device__ __align__(256) __half g_f1 [Fm * Dm];
__device__ __align__(256) __half g_f2 [Dm * Fm];
__device__ __align__(256) __half g_qt [(long)Hh * Lm * Dm];  // Q^T per head
__device__ __align__(256) __half g_kt [(long)Hh * Lm * Dm];  // K^T per head
__device__ __align__(256) __half g_v16[(long)Dm * Pp];       // V fp16 (qkv layout)
__device__ __align__(256) __half g_p16[(long)Hh * Lm * Lm];  // P [h][i][j]

// ---------------------------------------------------------------------------
// PTX helpers
// ---------------------------------------------------------------------------
__device__ __forceinline__ uint32_t smem_u32(const void* p) {
    uint32_t a;
    asm("{ .reg .u64 t; cvta.to.shared.u64 t, %1; cvt.u32.u64 %0, t; }" : "=r"(a) : "l"(p));
    return a;
}
__device__ __forceinline__ void cpasync16(uint32_t dst, const void* src) {
    asm volatile("cp.async.cg.shared.global [%0], [%1], 16;" :: "r"(dst), "l"(src));
}
__device__ __forceinline__ void cp_commit() {
    asm volatile("cp.async.commit_group;" ::: "memory");
}
template<int N>
__device__ __forceinline__ void cp_wait() {
    asm volatile("cp.async.wait_group %0;" :: "n"(N) : "memory");
}
__device__ __forceinline__ void ldsm4(uint32_t* r, uint32_t addr) {
    asm volatile("ldmatrix.sync.aligned.m8n8.x4.shared.b16 {%0,%1,%2,%3}, [%4];"
                 : "=r"(r[0]), "=r"(r[1]), "=r"(r[2]), "=r"(r[3]) : "r"(addr));
}
__device__ __forceinline__ void mma16816h(float* d, const uint32_t* a, uint32_t b0, uint32_t b1) {
    asm volatile("mma.sync.aligned.m16n8k16.row.col.f32.f16.f16.f32 "
                 "{%0,%1,%2,%3}, {%4,%5,%6,%7}, {%8,%9}, {%0,%1,%2,%3};"
                 : "+f"(d[0]), "+f"(d[1]), "+f"(d[2]), "+f"(d[3])
                 : "r"(a[0]), "r"(a[1]), "r"(a[2]), "r"(a[3]), "r"(b0), "r"(b1));
}

// ---------------------------------------------------------------------------
// Big GEMM: C[M,N] = W[M,K] * B[N,K]^T (+bias), single fp16 pass.
// CTA tile 128(M) x 256(N), BK=64, 3-stage ring, 8 warps as 2m x 4n (warp 64x64).
//   MODE 0: C fp32 [M,N] + bias; oV: fp16 copy for rows >= 1024 (V section).
//   MODE 1: relu(+bias) -> fp16 transposed [N,M].
// ---------------------------------------------------------------------------
#define MM_SBYTES 49152u            // A 16KB + B 32KB
#define MM_SMEM   (3 * MM_SBYTES)   // 144KB

template<int MODE>
__global__ void __launch_bounds__(256, 1)
gemm_mma(const __half* __restrict__ A, const __half* __restrict__ B,
         const float* __restrict__ bias,
         float* __restrict__ C, __half* __restrict__ oH, __half* __restrict__ oV,
         int M, int N, int K)
{
    extern __shared__ char smem[];
    const uint32_t sb = smem_u32(smem);

    const int tid  = threadIdx.x;
    const int wid  = tid >> 5;
    const int lane = tid & 31;
    const int warpM = wid & 1;          // 2 x 64 rows
    const int warpN = wid >> 1;         // 4 x 64 cols
    const int bm = blockIdx.x * 128;
    const int bn = blockIdx.y * 256;

    auto load_stage = [&](int st, int it) {
        const uint32_t sbase = sb + st * MM_SBYTES;
        const int k0 = it << 6;
#pragma unroll
        for (int j = 0; j < 12; j++) {
            const int idx = tid + j * 256;          // 0..3071
            if (idx < 1024) {
                const int row = idx >> 3, c = idx & 7;
                const uint32_t soff = row * 128 + ((c * 16) ^ ((row & 7) << 4));
                cpasync16(sbase + soff, A + (size_t)(bm + row) * K + k0 + c * 8);
            } else {
                const int i2 = idx - 1024;
                const int row = i2 >> 3, c = i2 & 7;
                const uint32_t soff = row * 128 + ((c * 16) ^ ((row & 7) << 4));
                cpasync16(sbase + 16384 + soff, B + (size_t)(bn + row) * K + k0 + c * 8);
            }
        }
    };

    float acc[4][8][4];
#pragma unroll
    for (int i = 0; i < 4; i++)
#pragma unroll
        for (int j = 0; j < 8; j++)
#pragma unroll
            for (int v = 0; v < 4; v++) acc[i][j][v] = 0.f;

    const int nIter = K >> 6;
    load_stage(0, 0); cp_commit();
    load_stage(1, 1); cp_commit();

    const int rsub  = lane & 15;
    const int khalf = ((lane >> 4) & 1) * 16;
    const int rA = warpM * 64 + rsub;
    const int rB = warpN * 64 + rsub;
    const uint32_t xA = (rA & 7) << 4;
    const uint32_t xB = (rB & 7) << 4;

    for (int it = 0; it < nIter; it++) {
        cp_wait<1>();
        __syncthreads();
        if (it + 2 < nIter) load_stage((it + 2) % 3, it + 2);
        cp_commit();

        const uint32_t sbase = sb + (it % 3) * MM_SBYTES;
        const uint32_t pA = sbase +         rA * 128;
        const uint32_t pB = sbase + 16384 + rB * 128;

#pragma unroll
        for (int q = 0; q < 4; q++) {
            const uint32_t kb = q * 32 + khalf;
            uint32_t ah[4][4], bb[4][4];
#pragma unroll
            for (int mt = 0; mt < 4; mt++)
                ldsm4(ah[mt], pA + mt * 2048 + (kb ^ xA));
#pragma unroll
            for (int g = 0; g < 4; g++)
                ldsm4(bb[g], pB + g * 2048 + (kb ^ xB));
#pragma unroll
            for (int mt = 0; mt < 4; mt++)
#pragma unroll
                for (int nt = 0; nt < 8; nt++) {
                    const int g = nt >> 1, o = nt & 1;
                    mma16816h(acc[mt][nt], ah[mt], bb[g][o], bb[g][o + 2]);
                }
        }
    }
    cp_wait<0>();
    __syncthreads();

    if (MODE == 0) {
        const bool wv = (oV != nullptr) && (bm >= 1024);
#pragma unroll
        for (int mt = 0; mt < 4; mt++) {
            const int r0 = bm + warpM * 64 + mt * 16 + (lane >> 2);
            const float bv0 = bias[r0], bv1 = bias[r0 + 8];
#pragma unroll
            for (int nt = 0; nt < 8; nt++) {
                const int c0 = bn + warpN * 64 + nt * 8 + (lane & 3) * 2;
                float* d = acc[mt][nt];
                const float v00 = d[0] + bv0, v01 = d[1] + bv0;
                const float v10 = d[2] + bv1, v11 = d[3] + bv1;
                *reinterpret_cast<float2*>(&C[(size_t)r0 * N + c0])       = make_float2(v00, v01);
                *reinterpret_cast<float2*>(&C[(size_t)(r0 + 8) * N + c0]) = make_float2(v10, v11);
                if (wv) {
                    *reinterpret_cast<__half2*>(&oV[(size_t)(r0 - 1024) * N + c0]) = __floats2half2_rn(v00, v01);
                    *reinterpret_cast<__half2*>(&oV[(size_t)(r0 - 1016) * N + c0]) = __floats2half2_rn(v10, v11);
                }
            }
        }
    } else {
        // bias+relu, stage [128 m][258 n] fp32 in smem, emit fp16 transposed [N,M]
        float* T = reinterpret_cast<float*>(smem);
#pragma unroll
        for (int mt = 0; mt < 4; mt++) {
            const int lr0 = warpM * 64 + mt * 16 + (lane >> 2);
            const float bv0 = bias[bm + lr0], bv1 = bias[bm + lr0 + 8];
#pragma unroll
            for (int nt = 0; nt < 8; nt++) {
                const int lc0 = warpN * 64 + nt * 8 + (lane & 3) * 2;
                float* d = acc[mt][nt];
                T[lr0 * 258 + lc0]           = fmaxf(d[0] + bv0, 0.f);
                T[lr0 * 258 + lc0 + 1]       = fmaxf(d[1] + bv0, 0.f);
                T[(lr0 + 8) * 258 + lc0]     = fmaxf(d[2] + bv1, 0.f);
                T[(lr0 + 8) * 258 + lc0 + 1] = fmaxf(d[3] + bv1, 0.f);
            }
        }
        __syncthreads();
        const int mloc = tid & 127;
#pragma unroll 4
        for (int rep = 0; rep < 128; rep++) {
            const int nl = rep * 2 + (tid >> 7);
            oH[(size_t)(bn + nl) * M + bm + mloc] = __float2half(T[mloc * 258 + nl]);
        }
    }
}

// ---------------------------------------------------------------------------
// Row-attention scores + FUSED softmax: per head tile 64(i) x 256(j), K=512.
// ---------------------------------------------------------------------------
#define SC_SBYTES 40960u
#define SC_SMEM   (3 * SC_SBYTES)

__global__ void __launch_bounds__(256, 1)
gemm_scores(const __half* __restrict__ Q, const __half* __restrict__ Kt,
            __half* __restrict__ P)
{
    constexpr int K = 512;
    extern __shared__ char smem[];
    const uint32_t sb = smem_u32(smem);

    const int tid = threadIdx.x, wid = tid >> 5, lane = tid & 31;
    const int warpM = wid & 3;
    const int warpN = wid >> 2;
    const int bm = blockIdx.x * 64;
    const int h = blockIdx.z;
    const __half* A = Q  + (size_t)h * Lm * Dm;
    const __half* B = Kt + (size_t)h * Lm * Dm;

    auto load_stage = [&](int st, int it) {
        const uint32_t sbase = sb + st * SC_SBYTES;
        const int k0 = it << 6;
#pragma unroll
        for (int j = 0; j < 10; j++) {
            const int idx = tid + j * 256;
            if (idx < 512) {
                const int row = idx >> 3, c = idx & 7;
                const uint32_t soff = row * 128 + ((c * 16) ^ ((row & 7) << 4));
                cpasync16(sbase + soff, A + (size_t)(bm + row) * K + k0 + c * 8);
            } else {
                const int i2 = idx - 512;
                const int row = i2 >> 3, c = i2 & 7;
                const uint32_t soff = row * 128 + ((c * 16) ^ ((row & 7) << 4));
                cpasync16(sbase + 8192 + soff, B + (size_t)row * K + k0 + c * 8);
            }
        }
    };

    float acc[16][4];
#pragma unroll
    for (int j = 0; j < 16; j++)
#pragma unroll
        for (int v = 0; v < 4; v++) acc[j][v] = 0.f;

    load_stage(0, 0); cp_commit();
    load_stage(1, 1); cp_commit();

    const int rsub  = lane & 15;
    const int khalf = ((lane >> 4) & 1) * 16;
    const int rA = warpM * 16 + rsub;
    const int rBb = warpN * 128 + rsub;
    const uint32_t xs = (rsub & 7) << 4;

    for (int it = 0; it < 8; it++) {
        cp_wait<1>();
        __syncthreads();
        if (it + 2 < 8) load_stage((it + 2) % 3, it + 2);
        cp_commit();

        const uint32_t sbase = sb + (it % 3) * SC_SBYTES;
        const uint32_t pA = sbase +        rA  * 128;
        const uint32_t pB = sbase + 8192 + rBb * 128;

#pragma unroll
        for (int q = 0; q < 4; q++) {
            const uint32_t kb = q * 32 + khalf;
            uint32_t ah[4], bb[8][4];
            ldsm4(ah, pA + (kb ^ xs));
#pragma unroll
            for (int g = 0; g < 8; g++)
                ldsm4(bb[g], pB + g * 2048 + (kb ^ xs));
#pragma unroll
            for (int nt = 0; nt < 16; nt++) {
                const int g = nt >> 1, o = nt & 1;
                mma16816h(acc[nt], ah, bb[g][o], bb[g][o + 2]);
            }
        }
    }
    cp_wait<0>();
    __syncthreads();

    float* S = reinterpret_cast<float*>(smem);
    {
        const int r0 = warpM * 16 + (lane >> 2);
#pragma unroll
        for (int nt = 0; nt < 16; nt++) {
            const int c0 = warpN * 128 + nt * 8 + (lane & 3) * 2;
            float* d = acc[nt];
            S[r0 * 260 + c0]           = d[0];
            S[r0 * 260 + c0 + 1]       = d[1];
            S[(r0 + 8) * 260 + c0]     = d[2];
            S[(r0 + 8) * 260 + c0 + 1] = d[3];
        }
    }
    __syncthreads();

#pragma unroll
    for (int rr = 0; rr < 8; rr++) {
        const int r = wid * 8 + rr;
        float v[8];
#pragma unroll
        for (int k = 0; k < 8; k++) v[k] = S[r * 260 + lane + 32 * k];
        float m = v[0];
#pragma unroll
        for (int k = 1; k < 8; k++) m = fmaxf(m, v[k]);
#pragma unroll
        for (int o = 16; o; o >>= 1) m = fmaxf(m, __shfl_xor_sync(0xffffffffu, m, o));
        float s = 0.f;
#pragma unroll
        for (int k = 0; k < 8; k++) { v[k] = __expf(v[k] - m); s += v[k]; }
#pragma unroll
        for (int o = 16; o; o >>= 1) s += __shfl_xor_sync(0xffffffffu, s, o);
        const float inv = 1.f / s;
        __half* dst = P + ((size_t)h * Lm + bm + r) * Lm;
#pragma unroll
        for (int k = 0; k < 8; k++) dst[lane + 32 * k] = __float2half(v[k] * inv);
    }
}

// ---------------------------------------------------------------------------
// Row-attention output: per head, C[m=(c,s), i] = sum_j V[m,j] * P[i,j].
// CTA 128x128, warps 4m x 2n (unchanged engine).
// ---------------------------------------------------------------------------
#define VP_SBYTES 32768u
#define VP_SMEM   (3 * VP_SBYTES)

__global__ void __launch_bounds__(256, 1)
gemm_vp(const __half* __restrict__ V, const __half* __restrict__ P,
        float* __restrict__ O)
{
    constexpr int K = 256;
    extern __shared__ char smem[];
    const uint32_t sb = smem_u32(smem);

    const int tid = threadIdx.x, wid = tid >> 5, lane = tid & 31;
    const int warpM = wid & 3, warpN = wid >> 2;
    const int bm = blockIdx.x * 128, bn = blockIdx.y * 128;
    const int h = blockIdx.z;
    const __half* Av = V + (size_t)h * 8 * Pp;
    const __half* Bp = P + (size_t)h * Lm * Lm;
    float* C = O + (size_t)h * 8 * Pp;

    auto load_stage = [&](int st, int it) {
        const uint32_t sbase = sb + st * VP_SBYTES;
        const int k0 = it << 6;
#pragma unroll
        for (int j = 0; j < 4; j++) {
            const int idx = tid + j * 256;
            const int row = idx >> 3;
            const int c   = idx & 7;
            const uint32_t soff = row * 128 + ((c * 16) ^ ((row & 7) << 4));
            const int mrow = bm + row;
            const size_t ga = (size_t)(mrow >> 6) * Pp + (mrow & 63) * 256 + k0 + c * 8;
            cpasync16(sbase +         soff, Av + ga);
            cpasync16(sbase + 16384 + soff, Bp + (size_t)(bn + row) * K + k0 + c * 8);
        }
    };

    float acc[2][8][4];
#pragma unroll
    for (int i = 0; i < 2; i++)
#pragma unroll
        for (int j = 0; j < 8; j++)
#pragma unroll
            for (int v = 0; v < 4; v++) acc[i][j][v] = 0.f;

    load_stage(0, 0); cp_commit();
    load_stage(1, 1); cp_commit();

    const int rsub  = lane & 15;
    const int khalf = ((lane >> 4) & 1) * 16;
    const int rA = warpM * 32 + rsub;
    const int rB = warpN * 64 + rsub;
    const uint32_t xA = (rA & 7) << 4;
    const uint32_t xB = (rB & 7) << 4;

    for (int it = 0; it < 4; it++) {
        cp_wait<1>();
        __syncthreads();
        if (it + 2 < 4) load_stage((it + 2) % 3, it + 2);
        cp_commit();

        const uint32_t sbase = sb + (it % 3) * VP_SBYTES;
        const uint32_t pA = sbase +         rA * 128;
        const uint32_t pB = sbase + 16384 + rB * 128;

#pragma unroll
        for (int q = 0; q < 4; q++) {
            const uint32_t kb = q * 32 + khalf;
            uint32_t av[2][4], bb[4][4];
#pragma unroll
            for (int mt = 0; mt < 2; mt++)
                ldsm4(av[mt], pA + mt * 2048 + (kb ^ xA));
#pragma unroll
            for (int g = 0; g < 4; g++)
                ldsm4(bb[g], pB + g * 2048 + (kb ^ xB));
#pragma unroll
            for (int mt = 0; mt < 2; mt++)
#pragma unroll
                for (int nt = 0; nt < 8; nt++) {
                    const int g = nt >> 1, o = nt & 1;
                    mma16816h(acc[mt][nt], av[mt], bb[g][o], bb[g][o + 2]);
                }
        }
    }
    cp_wait<0>();
    __syncthreads();

#pragma unroll
    for (int mt = 0; mt < 2; mt++) {
        const int r0 = bm + warpM * 32 + mt * 16 + (lane >> 2);
        const int r1 = r0 + 8;
        const size_t a0 = (size_t)(r0 >> 6) * Pp + (r0 & 63) * 256;
        const size_t a1 = (size_t)(r1 >> 6) * Pp + (r1 & 63) * 256;
#pragma unroll
        for (int nt = 0; nt < 8; nt++) {
            const int c0 = bn + warpN * 64 + nt * 8 + (lane & 3) * 2;
            float* d = acc[mt][nt];
            *reinterpret_cast<float2*>(&C[a0 + c0]) = make_float2(d[0], d[1]);
            *reinterpret_cast<float2*>(&C[a1 + c0]) = make_float2(d[2], d[3]);
        }
    }
}

// ---------------------------------------------------------------------------
// Conversions
// ---------------------------------------------------------------------------
__global__ void convw1_kernel(const float* __restrict__ w, __half* __restrict__ oh, int n)
{
    int i = blockIdx.x * 256 + threadIdx.x;
    if (i < n) oh[i] = __float2half(w[i]);
}
__global__ void __launch_bounds__(256)
convt_kernel(const float* __restrict__ in, __half* __restrict__ oh, int K, int N)
{
    __shared__ float t[32][33];
    const int n0 = blockIdx.x * 32, k0 = blockIdx.y * 32;
    const int tx = threadIdx.x, ty = threadIdx.y;
#pragma unroll
    for (int i = 0; i < 4; i++)
        t[ty + 8 * i][tx] = in[(size_t)(k0 + ty + 8 * i) * N + n0 + tx];
    __syncthreads();
#pragma unroll
    for (int i = 0; i < 4; i++) {
        const int r = ty + 8 * i;
        oh[(size_t)(n0 + r) * K + k0 + tx] = __float2half(t[tx][r]);
    }
}
__global__ void __launch_bounds__(256)
convtqk_kernel(const float* __restrict__ qkv,
               __half* __restrict__ qo, __half* __restrict__ ko)
{
    __shared__ float t[32][33];
    const int h = blockIdx.z >> 1;
    const int isK = blockIdx.z & 1;
    const float* in = qkv + (isK ? (size_t)Dm * Pp : 0) + (size_t)h * 8 * Pp;
    __half* o = (isK ? ko : qo) + (size_t)h * Lm * Dm;
    const int l0 = blockIdx.x * 32, k0 = blockIdx.y * 32;
    const int tx = threadIdx.x, ty = threadIdx.y;
#pragma unroll
    for (int i = 0; i < 4; i++) {
        const int k = k0 + ty + 8 * i;
        t[ty + 8 * i][tx] = in[(size_t)(k >> 6) * Pp + (k & 63) * 256 + l0 + tx];
    }
    __syncthreads();
#pragma unroll
    for (int i = 0; i < 4; i++) {
        const int r = ty + 8 * i;
        o[(size_t)(l0 + r) * Dm + k0 + tx] = __float2half(t[tx][r]);
    }
}

// ---------------------------------------------------------------------------
// Channel LayerNorm over D=512 (optional residual, optional transposed fp16 out)
// ---------------------------------------------------------------------------
__global__ __launch_bounds__(256)
void ln_kernel(const float* __restrict__ in, const float* __restrict__ res,
               const float* __restrict__ w, const float* __restrict__ b,
               float* __restrict__ out, __half* __restrict__ obt)
{
    __shared__ float ss[8][32], ss2[8][32];
    __shared__ __half tbuf[32][514];
    const int tx = threadIdx.x, ty = threadIdx.y;
    const int tid = ty * 32 + tx;
    const int pos0 = blockIdx.x * 32;
    const int pos = pos0 + tx;

    float s = 0.f, s2 = 0.f;
    if (res) {
        for (int c = ty; c < Dm; c += 8) {
            float v = in[(size_t)c * Pp + pos] + res[(size_t)c * Pp + pos];
            s += v; s2 += v * v;
        }
    } else {
        for (int c = ty; c < Dm; c += 8) {
            float v = in[(size_t)c * Pp + pos];
            s += v; s2 += v * v;
        }
    }
    ss[ty][tx] = s; ss2[ty][tx] = s2;
    __syncthreads();
    float st = 0.f, st2 = 0.f;
#pragma unroll
    for (int y = 0; y < 8; y++) { st += ss[y][tx]; st2 += ss2[y][tx]; }
    const float mean = st * (1.f / Dm);
    const float var  = st2 * (1.f / Dm) - mean * mean;
    const float rstd = rsqrtf(var + EPS);

    if (res) {
        for (int c = ty; c < Dm; c += 8) {
            float v = in[(size_t)c * Pp + pos] + res[(size_t)c * Pp + pos];
            const float o = (v - mean) * rstd * w[c] + b[c];
            out[(size_t)c * Pp + pos] = o;
            if (obt) tbuf[tx][c] = __float2half(o);
        }
    } else {
        for (int c = ty; c < Dm; c += 8) {
            float v = in[(size_t)c * Pp + pos];
            const float o = (v - mean) * rstd * w[c] + b[c];
            out[(size_t)c * Pp + pos] = o;
            if (obt) tbuf[tx][c] = __float2half(o);
        }
    }
    if (obt) {
        __syncthreads();
#pragma unroll 4
        for (int r = 0; r < 32; r++) {
            const uint32_t val = *reinterpret_cast<const uint32_t*>(&tbuf[r][tid * 2]);
            *reinterpret_cast<uint32_t*>(&obt[(size_t)(pos0 + r) * Dm + tid * 2]) = val;
        }
    }
}

// ---------------------------------------------------------------------------
// Column attention — K/V loads amortized over 4 i-rows per thread.
// ---------------------------------------------------------------------------
__global__ __launch_bounds__(512)
void colattn_kernel(const float* __restrict__ qkv, float* __restrict__ out)
{
    const int h = blockIdx.z;
    const int l = blockIdx.x * 32 + threadIdx.x;
    const int ty = threadIdx.y;
    const float* Q  = qkv + (size_t)h * Cc * Pp;
    const float* Kp = Q + (size_t)Dm * Pp;
    const float* V  = Q + 2L * (size_t)Dm * Pp;

    float q[4][Cc];
#pragma unroll
    for (int ii = 0; ii < 4; ii++) {
        const int i = ty + 16 * ii;
#pragma unroll
        for (int c = 0; c < Cc; c++) q[ii][c] = Q[(size_t)c * Pp + i * Lm + l];
    }

    float d[4] = {0.f, 0.f, 0.f, 0.f};
    float acc[4][Cc];
#pragma unroll
    for (int ii = 0; ii < 4; ii++)
#pragma unroll
        for (int c = 0; c < Cc; c++) acc[ii][c] = 0.f;

    for (int j = 0; j < Sm; j++) {
        float kv[Cc], vv[Cc];
#pragma unroll
        for (int c = 0; c < Cc; c++) {
            kv[c] = Kp[(size_t)c * Pp + j * Lm + l];
            vv[c] = V [(size_t)c * Pp + j * Lm + l];
        }
#pragma unroll
        for (int ii = 0; ii < 4; ii++) {
            float sc = 0.f;
#pragma unroll
            for (int c = 0; c < Cc; c++) sc = fmaf(q[ii][c], kv[c], sc);
            const float e = __expf(sc);
            d[ii] += e;
#pragma unroll
            for (int c = 0; c < Cc; c++) acc[ii][c] = fmaf(e, vv[c], acc[ii][c]);
        }
    }
#pragma unroll
    for (int ii = 0; ii < 4; ii++) {
        const int i = ty + 16 * ii;
        const float inv = 1.f / d[ii];
#pragma unroll
        for (int c = 0; c < Cc; c++)
            out[(size_t)(h * Cc + c) * Pp + i * Lm + l] = acc[ii][c] * inv;
    }
}

// ---------------------------------------------------------------------------
// Host side
// ---------------------------------------------------------------------------
extern "C" void kernel_launch(void* const* d_in, const int* in_sizes, int n_in,
                              void* d_out, int out_size)
{
    const float* x     = (const float*)d_in[0];
    const float* w_row = (const float*)d_in[1];
    const float* b_row = (const float*)d_in[2];
    const float* w_col = (const float*)d_in[3];
    const float* b_col = (const float*)d_in[4];
    const float* w_an1 = (const float*)d_in[5];
    const float* b_an1 = (const float*)d_in[6];
    const float* w_an2 = (const float*)d_in[7];
    const float* b_an2 = (const float*)d_in[8];
    const float* w_ff1 = (const float*)d_in[9];
    const float* b_ff1 = (const float*)d_in[10];
    const float* w_ff2 = (const float*)d_in[11];
    const float* b_ff2 = (const float*)d_in[12];
    const float* w_ln1 = (const float*)d_in[13];
    const float* b_ln1 = (const float*)d_in[14];
    const float* w_ln2 = (const float*)d_in[15];
    const float* b_ln2 = (const float*)d_in[16];
    float* outp = (float*)d_out;

    float *qkv, *tmp, *out1, *attn;
    __half *bt, *ff, *wr, *wc, *f1, *f2, *qt, *kt, *v16, *p16;
    cudaGetSymbolAddress((void**)&qkv,  g_qkv);
    cudaGetSymbolAddress((void**)&tmp,  g_tmp);
    cudaGetSymbolAddress((void**)&out1, g_out1);
    cudaGetSymbolAddress((void**)&attn, g_attn);
    cudaGetSymbolAddress((void**)&bt,   g_bt);
    cudaGetSymbolAddress((void**)&ff,   g_ff);
    cudaGetSymbolAddress((void**)&wr,   g_wr);
    cudaGetSymbolAddress((void**)&wc,   g_wc);
    cudaGetSymbolAddress((void**)&f1,   g_f1);
    cudaGetSymbolAddress((void**)&f2,   g_f2);
    cudaGetSymbolAddress((void**)&qt,   g_qt);
    cudaGetSymbolAddress((void**)&kt,   g_kt);
    cudaGetSymbolAddress((void**)&v16,  g_v16);
    cudaGetSymbolAddress((void**)&p16,  g_p16);

    cudaFuncSetAttribute(gemm_mma<0>, cudaFuncAttributeMaxDynamicSharedMemorySize, MM_SMEM);
    cudaFuncSetAttribute(gemm_mma<1>, cudaFuncAttributeMaxDynamicSharedMemorySize, MM_SMEM);
    cudaFuncSetAttribute(gemm_scores, cudaFuncAttributeMaxDynamicSharedMemorySize, SC_SMEM);
    cudaFuncSetAttribute(gemm_vp,     cudaFuncAttributeMaxDynamicSharedMemorySize, VP_SMEM);

    // weight conversions
    convw1_kernel<<<(3 * Dm * Dm + 255) / 256, 256>>>(w_row, wr, 3 * Dm * Dm);
    convw1_kernel<<<(3 * Dm * Dm + 255) / 256, 256>>>(w_col, wc, 3 * Dm * Dm);
    convw1_kernel<<<(Fm * Dm + 255) / 256, 256>>>(w_ff1, f1, Fm * Dm);
    convw1_kernel<<<(Dm * Fm + 255) / 256, 256>>>(w_ff2, f2, Dm * Fm);

    // x -> transposed fp16
    convt_kernel<<<dim3(Pp / 32, Dm / 32), dim3(32, 8)>>>(x, bt, Dm, Pp);

    // 1) row qkv = w_row @ x + b_row ; V section also emitted as fp16
    gemm_mma<0><<<dim3((3 * Dm) / 128, Pp / 256), 256, MM_SMEM>>>(
        wr, bt, b_row, qkv, nullptr, v16, 3 * Dm, Pp, Dm);

    // 2) Q/K transpose-convert
    convtqk_kernel<<<dim3(Lm / 32, Dm / 32, 2 * Hh), dim3(32, 8)>>>(qkv, qt, kt);

    // 3) scores + fused softmax -> P fp16
    gemm_scores<<<dim3(Lm / 64, 1, Hh), 256, SC_SMEM>>>(qt, kt, p16);

    // 4) row_out = V * P^T
    gemm_vp<<<dim3(4, 2, Hh), 256, VP_SMEM>>>(v16, p16, tmp);

    // 5) out1 = LN(x + row_out; an1), fused transposed fp16 -> bt
    ln_kernel<<<Pp / 32, dim3(32, 8)>>>(x, tmp, w_an1, b_an1, out1, bt);

    // 6) col qkv = w_col @ out1 + b_col
    gemm_mma<0><<<dim3((3 * Dm) / 128, Pp / 256), 256, MM_SMEM>>>(
        wc, bt, b_col, qkv, nullptr, nullptr, 3 * Dm, Pp, Dm);

    // 7) column attention
    colattn_kernel<<<dim3(Lm / 32, 1, Hh), dim3(32, 16)>>>(qkv, tmp);

    // 8) attn_out = LN(out1 + col_out; an2)
    ln_kernel<<<Pp / 32, dim3(32, 8)>>>(out1, tmp, w_an2, b_an2, attn, nullptr);

    // 9) h = LN(attn_out; ln1), fused transposed fp16 -> bt
    ln_kernel<<<Pp / 32, dim3(32, 8)>>>(attn, nullptr, w_ln1, b_ln1, out1, bt);

    // 10) ff1: relu(w_ff1 @ h + b_ff1) -> fp16 transposed
    gemm_mma<1><<<dim3(Fm / 128, Pp / 256), 256, MM_SMEM>>>(
        f1, bt, b_ff1, nullptr, ff, nullptr, Fm, Pp, Dm);

    // 11) ff2 = w_ff2 @ ff1 + b_ff2
    gemm_mma<0><<<dim3(Dm / 128, Pp / 256), 256, MM_SMEM>>>(
        f2, ff, b_ff2, tmp, nullptr, nullptr, Dm, Pp, Fm);

    // 12) out = LN(h + ff2; ln2)
    ln_kernel<<<Pp / 32, dim3(32, 8)>>>(out1, tmp, w_ln2, b_ln2, outp, nullptr);
}

// round 9
// speedup vs baseline: 4.4008x; 1.1777x over previous
#include <cuda_runtime.h>
#include <cuda_fp16.h>
#include <math_constants.h>
#include <cstdint>
#include <cstddef>

// ---------------------------------------------------------------------------
// Problem constants
// ---------------------------------------------------------------------------
#define Dm   512
#define Sm   64
#define Lm   256
#define Fm   2048
#define Hh   64
#define Cc   8
#define Pp   (Sm * Lm)          // 16384 spatial positions
#define EPS  1e-5f

// ---------------------------------------------------------------------------
// Scratch buffers (static device globals -- allocation-free)
// ---------------------------------------------------------------------------
__device__ __align__(256) float g_tmp [(long)Dm * Pp];
__device__ __align__(256) float g_out1[(long)Dm * Pp];
__device__ __align__(256) float g_attn[(long)Dm * Pp];

// fp16 operands (all single-plane)
__device__ __align__(256) __half g_qkv16[3L * Dm * Pp];      // qkv fp16 [1536][16384]
__device__ __align__(256) __half g_bt [(long)Pp * Dm];       // act^T [Pp,512]
__device__ __align__(256) __half g_ff [(long)Pp * Fm];       // ff1^T [Pp,2048]
__device__ __align__(256) __half g_wr [3 * Dm * Dm];
__device__ __align__(256) __half g_wc [3 * Dm * Dm];
__device__ __align__(256) __half g_f1 [Fm * Dm];
__device__ __align__(256) __half g_f2 [Dm * Fm];
__device__ __align__(256) __half g_qt [(long)Hh * Lm * Dm];  // Q^T per head
__device__ __align__(256) __half g_kt [(long)Hh * Lm * Dm];  // K^T per head
__device__ __align__(256) __half g_p16[(long)Hh * Lm * Lm];  // P [h][i][j]

// ---------------------------------------------------------------------------
// PTX helpers
// ---------------------------------------------------------------------------
__device__ __forceinline__ uint32_t smem_u32(const void* p) {
    uint32_t a;
    asm("{ .reg .u64 t; cvta.to.shared.u64 t, %1; cvt.u32.u64 %0, t; }" : "=r"(a) : "l"(p));
    return a;
}
__device__ __forceinline__ void cpasync16(uint32_t dst, const void* src) {
    asm volatile("cp.async.cg.shared.global [%0], [%1], 16;" :: "r"(dst), "l"(src));
}
__device__ __forceinline__ void cp_commit() {
    asm volatile("cp.async.commit_group;" ::: "memory");
}
template<int N>
__device__ __forceinline__ void cp_wait() {
    asm volatile("cp.async.wait_group %0;" :: "n"(N) : "memory");
}
__device__ __forceinline__ void ldsm4(uint32_t* r, uint32_t addr) {
    asm volatile("ldmatrix.sync.aligned.m8n8.x4.shared.b16 {%0,%1,%2,%3}, [%4];"
                 : "=r"(r[0]), "=r"(r[1]), "=r"(r[2]), "=r"(r[3]) : "r"(addr));
}
__device__ __forceinline__ void mma16816h(float* d, const uint32_t* a, uint32_t b0, uint32_t b1) {
    asm volatile("mma.sync.aligned.m16n8k16.row.col.f32.f16.f16.f32 "
                 "{%0,%1,%2,%3}, {%4,%5,%6,%7}, {%8,%9}, {%0,%1,%2,%3};"
                 : "+f"(d[0]), "+f"(d[1]), "+f"(d[2]), "+f"(d[3])
                 : "r"(a[0]), "r"(a[1]), "r"(a[2]), "r"(a[3]), "r"(b0), "r"(b1));
}

// ---------------------------------------------------------------------------
// Big GEMM: C[M,N] = W[M,K] * B[N,K]^T (+bias), single fp16 pass.
// CTA tile 128x128, BK=64, 3-stage ring (96KB), 8 warps (4m x 2n), 2 CTAs/SM.
//   MODE 0: C fp32 [M,N] + bias.
//   MODE 1: relu(+bias) -> fp16 transposed [N,M].
//   MODE 2: fp16 [M,N] + bias (qkv chain).
// ---------------------------------------------------------------------------
#define MM_SBYTES 32768u
#define MM_SMEM   (3 * MM_SBYTES)

template<int MODE>
__global__ void __launch_bounds__(256, 2)
gemm_mma(const __half* __restrict__ A, const __half* __restrict__ B,
         const float* __restrict__ bias,
         float* __restrict__ C, __half* __restrict__ oH,
         int M, int N, int K)
{
    extern __shared__ char smem[];
    const uint32_t sb = smem_u32(smem);

    const int tid  = threadIdx.x;
    const int wid  = tid >> 5;
    const int lane = tid & 31;
    const int warpM = wid & 3;
    const int warpN = wid >> 2;
    const int bm = blockIdx.x * 128;
    const int bn = blockIdx.y * 128;

    auto load_stage = [&](int st, int it) {
        const uint32_t sbase = sb + st * MM_SBYTES;
        const int k0 = it << 6;
#pragma unroll
        for (int j = 0; j < 4; j++) {
            const int idx = tid + j * 256;
            const int row = idx >> 3;
            const int c   = idx & 7;
            const uint32_t soff = row * 128 + ((c * 16) ^ ((row & 7) << 4));
            cpasync16(sbase +         soff, A + (size_t)(bm + row) * K + k0 + c * 8);
            cpasync16(sbase + 16384 + soff, B + (size_t)(bn + row) * K + k0 + c * 8);
        }
    };

    float acc[2][8][4];
#pragma unroll
    for (int i = 0; i < 2; i++)
#pragma unroll
        for (int j = 0; j < 8; j++)
#pragma unroll
            for (int v = 0; v < 4; v++) acc[i][j][v] = 0.f;

    const int nIter = K >> 6;
    load_stage(0, 0); cp_commit();
    load_stage(1, 1); cp_commit();

    const int rsub  = lane & 15;
    const int khalf = ((lane >> 4) & 1) * 16;
    const int rA = warpM * 32 + rsub;
    const int rB = warpN * 64 + rsub;
    const uint32_t xA = (rA & 7) << 4;
    const uint32_t xB = (rB & 7) << 4;

    for (int it = 0; it < nIter; it++) {
        cp_wait<1>();
        __syncthreads();
        if (it + 2 < nIter) load_stage((it + 2) % 3, it + 2);
        cp_commit();

        const uint32_t sbase = sb + (it % 3) * MM_SBYTES;
        const uint32_t pA = sbase +         rA * 128;
        const uint32_t pB = sbase + 16384 + rB * 128;

#pragma unroll
        for (int q = 0; q < 4; q++) {
            const uint32_t kb = q * 32 + khalf;
            uint32_t ah[2][4], bb[4][4];
#pragma unroll
            for (int mt = 0; mt < 2; mt++)
                ldsm4(ah[mt], pA + mt * 2048 + (kb ^ xA));
#pragma unroll
            for (int g = 0; g < 4; g++)
                ldsm4(bb[g], pB + g * 2048 + (kb ^ xB));
#pragma unroll
            for (int mt = 0; mt < 2; mt++)
#pragma unroll
                for (int nt = 0; nt < 8; nt++) {
                    const int g = nt >> 1, o = nt & 1;
                    mma16816h(acc[mt][nt], ah[mt], bb[g][o], bb[g][o + 2]);
                }
        }
    }
    cp_wait<0>();
    __syncthreads();

    if (MODE == 0) {
#pragma unroll
        for (int mt = 0; mt < 2; mt++) {
            const int r0 = bm + warpM * 32 + mt * 16 + (lane >> 2);
            const float bv0 = bias[r0], bv1 = bias[r0 + 8];
#pragma unroll
            for (int nt = 0; nt < 8; nt++) {
                const int c0 = bn + warpN * 64 + nt * 8 + (lane & 3) * 2;
                float* d = acc[mt][nt];
                *reinterpret_cast<float2*>(&C[(size_t)r0 * N + c0])       = make_float2(d[0] + bv0, d[1] + bv0);
                *reinterpret_cast<float2*>(&C[(size_t)(r0 + 8) * N + c0]) = make_float2(d[2] + bv1, d[3] + bv1);
            }
        }
    } else if (MODE == 2) {
#pragma unroll
        for (int mt = 0; mt < 2; mt++) {
            const int r0 = bm + warpM * 32 + mt * 16 + (lane >> 2);
            const float bv0 = bias[r0], bv1 = bias[r0 + 8];
#pragma unroll
            for (int nt = 0; nt < 8; nt++) {
                const int c0 = bn + warpN * 64 + nt * 8 + (lane & 3) * 2;
                float* d = acc[mt][nt];
                *reinterpret_cast<__half2*>(&oH[(size_t)r0 * N + c0])       = __floats2half2_rn(d[0] + bv0, d[1] + bv0);
                *reinterpret_cast<__half2*>(&oH[(size_t)(r0 + 8) * N + c0]) = __floats2half2_rn(d[2] + bv1, d[3] + bv1);
            }
        }
    } else {
        float* T = reinterpret_cast<float*>(smem);   // [128][130]
#pragma unroll
        for (int mt = 0; mt < 2; mt++) {
            const int lr0 = warpM * 32 + mt * 16 + (lane >> 2);
            const float bv0 = bias[bm + lr0], bv1 = bias[bm + lr0 + 8];
#pragma unroll
            for (int nt = 0; nt < 8; nt++) {
                const int lc0 = warpN * 64 + nt * 8 + (lane & 3) * 2;
                float* d = acc[mt][nt];
                T[lr0 * 130 + lc0]           = fmaxf(d[0] + bv0, 0.f);
                T[lr0 * 130 + lc0 + 1]       = fmaxf(d[1] + bv0, 0.f);
                T[(lr0 + 8) * 130 + lc0]     = fmaxf(d[2] + bv1, 0.f);
                T[(lr0 + 8) * 130 + lc0 + 1] = fmaxf(d[3] + bv1, 0.f);
            }
        }
        __syncthreads();
        const int mloc = tid & 127;
#pragma unroll 4
        for (int rep = 0; rep < 64; rep++) {
            const int nl = rep * 2 + (tid >> 7);
            oH[(size_t)(bn + nl) * M + bm + mloc] = __float2half(T[mloc * 130 + nl]);
        }
    }
}

// ---------------------------------------------------------------------------
// Row-attention scores + FUSED softmax: per head tile 64(i) x 256(j), K=512.
// ---------------------------------------------------------------------------
#define SC_SBYTES 40960u
#define SC_SMEM   (3 * SC_SBYTES)

__global__ void __launch_bounds__(256, 1)
gemm_scores(const __half* __restrict__ Q, const __half* __restrict__ Kt,
            __half* __restrict__ P)
{
    constexpr int K = 512;
    extern __shared__ char smem[];
    const uint32_t sb = smem_u32(smem);

    const int tid = threadIdx.x, wid = tid >> 5, lane = tid & 31;
    const int warpM = wid & 3;
    const int warpN = wid >> 2;
    const int bm = blockIdx.x * 64;
    const int h = blockIdx.z;
    const __half* A = Q  + (size_t)h * Lm * Dm;
    const __half* B = Kt + (size_t)h * Lm * Dm;

    auto load_stage = [&](int st, int it) {
        const uint32_t sbase = sb + st * SC_SBYTES;
        const int k0 = it << 6;
#pragma unroll
        for (int j = 0; j < 10; j++) {
            const int idx = tid + j * 256;
            if (idx < 512) {
                const int row = idx >> 3, c = idx & 7;
                const uint32_t soff = row * 128 + ((c * 16) ^ ((row & 7) << 4));
                cpasync16(sbase + soff, A + (size_t)(bm + row) * K + k0 + c * 8);
            } else {
                const int i2 = idx - 512;
                const int row = i2 >> 3, c = i2 & 7;
                const uint32_t soff = row * 128 + ((c * 16) ^ ((row & 7) << 4));
                cpasync16(sbase + 8192 + soff, B + (size_t)row * K + k0 + c * 8);
            }
        }
    };

    float acc[16][4];
#pragma unroll
    for (int j = 0; j < 16; j++)
#pragma unroll
        for (int v = 0; v < 4; v++) acc[j][v] = 0.f;

    load_stage(0, 0); cp_commit();
    load_stage(1, 1); cp_commit();

    const int rsub  = lane & 15;
    const int khalf = ((lane >> 4) & 1) * 16;
    const int rA = warpM * 16 + rsub;
    const int rBb = warpN * 128 + rsub;
    const uint32_t xs = (rsub & 7) << 4;

    for (int it = 0; it < 8; it++) {
        cp_wait<1>();
        __syncthreads();
        if (it + 2 < 8) load_stage((it + 2) % 3, it + 2);
        cp_commit();

        const uint32_t sbase = sb + (it % 3) * SC_SBYTES;
        const uint32_t pA = sbase +        rA  * 128;
        const uint32_t pB = sbase + 8192 + rBb * 128;

#pragma unroll
        for (int q = 0; q < 4; q++) {
            const uint32_t kb = q * 32 + khalf;
            uint32_t ah[4], bb[8][4];
            ldsm4(ah, pA + (kb ^ xs));
#pragma unroll
            for (int g = 0; g < 8; g++)
                ldsm4(bb[g], pB + g * 2048 + (kb ^ xs));
#pragma unroll
            for (int nt = 0; nt < 16; nt++) {
                const int g = nt >> 1, o = nt & 1;
                mma16816h(acc[nt], ah, bb[g][o], bb[g][o + 2]);
            }
        }
    }
    cp_wait<0>();
    __syncthreads();

    float* S = reinterpret_cast<float*>(smem);
    {
        const int r0 = warpM * 16 + (lane >> 2);
#pragma unroll
        for (int nt = 0; nt < 16; nt++) {
            const int c0 = warpN * 128 + nt * 8 + (lane & 3) * 2;
            float* d = acc[nt];
            S[r0 * 260 + c0]           = d[0];
            S[r0 * 260 + c0 + 1]       = d[1];
            S[(r0 + 8) * 260 + c0]     = d[2];
            S[(r0 + 8) * 260 + c0 + 1] = d[3];
        }
    }
    __syncthreads();

#pragma unroll
    for (int rr = 0; rr < 8; rr++) {
        const int r = wid * 8 + rr;
        float v[8];
#pragma unroll
        for (int k = 0; k < 8; k++) v[k] = S[r * 260 + lane + 32 * k];
        float m = v[0];
#pragma unroll
        for (int k = 1; k < 8; k++) m = fmaxf(m, v[k]);
#pragma unroll
        for (int o = 16; o; o >>= 1) m = fmaxf(m, __shfl_xor_sync(0xffffffffu, m, o));
        float s = 0.f;
#pragma unroll
        for (int k = 0; k < 8; k++) { v[k] = __expf(v[k] - m); s += v[k]; }
#pragma unroll
        for (int o = 16; o; o >>= 1) s += __shfl_xor_sync(0xffffffffu, s, o);
        const float inv = 1.f / s;
        __half* dst = P + ((size_t)h * Lm + bm + r) * Lm;
#pragma unroll
        for (int k = 0; k < 8; k++) dst[lane + 32 * k] = __float2half(v[k] * inv);
    }
}

// ---------------------------------------------------------------------------
// Row-attention output: per head, C[m=(c,s), i] = sum_j V[m,j] * P[i,j].
// ---------------------------------------------------------------------------
__global__ void __launch_bounds__(256, 2)
gemm_vp(const __half* __restrict__ V, const __half* __restrict__ P,
        float* __restrict__ O)
{
    constexpr int K = 256;
    extern __shared__ char smem[];
    const uint32_t sb = smem_u32(smem);

    const int tid = threadIdx.x, wid = tid >> 5, lane = tid & 31;
    const int warpM = wid & 3, warpN = wid >> 2;
    const int bm = blockIdx.x * 128, bn = blockIdx.y * 128;
    const int h = blockIdx.z;
    const __half* Av = V + (size_t)h * 8 * Pp;
    const __half* Bp = P + (size_t)h * Lm * Lm;
    float* C = O + (size_t)h * 8 * Pp;

    auto load_stage = [&](int st, int it) {
        const uint32_t sbase = sb + st * MM_SBYTES;
        const int k0 = it << 6;
#pragma unroll
        for (int j = 0; j < 4; j++) {
            const int idx = tid + j * 256;
            const int row = idx >> 3;
            const int c   = idx & 7;
            const uint32_t soff = row * 128 + ((c * 16) ^ ((row & 7) << 4));
            const int mrow = bm + row;
            const size_t ga = (size_t)(mrow >> 6) * Pp + (mrow & 63) * 256 + k0 + c * 8;
            cpasync16(sbase +         soff, Av + ga);
            cpasync16(sbase + 16384 + soff, Bp + (size_t)(bn + row) * K + k0 + c * 8);
        }
    };

    float acc[2][8][4];
#pragma unroll
    for (int i = 0; i < 2; i++)
#pragma unroll
        for (int j = 0; j < 8; j++)
#pragma unroll
            for (int v = 0; v < 4; v++) acc[i][j][v] = 0.f;

    load_stage(0, 0); cp_commit();
    load_stage(1, 1); cp_commit();

    const int rsub  = lane & 15;
    const int khalf = ((lane >> 4) & 1) * 16;
    const int rA = warpM * 32 + rsub;
    const int rB = warpN * 64 + rsub;
    const uint32_t xA = (rA & 7) << 4;
    const uint32_t xB = (rB & 7) << 4;

    for (int it = 0; it < 4; it++) {
        cp_wait<1>();
        __syncthreads();
        if (it + 2 < 4) load_stage((it + 2) % 3, it + 2);
        cp_commit();

        const uint32_t sbase = sb + (it % 3) * MM_SBYTES;
        const uint32_t pA = sbase +         rA * 128;
        const uint32_t pB = sbase + 16384 + rB * 128;

#pragma unroll
        for (int q = 0; q < 4; q++) {
            const uint32_t kb = q * 32 + khalf;
            uint32_t av[2][4], bb[4][4];
#pragma unroll
            for (int mt = 0; mt < 2; mt++)
                ldsm4(av[mt], pA + mt * 2048 + (kb ^ xA));
#pragma unroll
            for (int g = 0; g < 4; g++)
                ldsm4(bb[g], pB + g * 2048 + (kb ^ xB));
#pragma unroll
            for (int mt = 0; mt < 2; mt++)
#pragma unroll
                for (int nt = 0; nt < 8; nt++) {
                    const int g = nt >> 1, o = nt & 1;
                    mma16816h(acc[mt][nt], av[mt], bb[g][o], bb[g][o + 2]);
                }
        }
    }
    cp_wait<0>();
    __syncthreads();

#pragma unroll
    for (int mt = 0; mt < 2; mt++) {
        const int r0 = bm + warpM * 32 + mt * 16 + (lane >> 2);
        const int r1 = r0 + 8;
        const size_t a0 = (size_t)(r0 >> 6) * Pp + (r0 & 63) * 256;
        const size_t a1 = (size_t)(r1 >> 6) * Pp + (r1 & 63) * 256;
#pragma unroll
        for (int nt = 0; nt < 8; nt++) {
            const int c0 = bn + warpN * 64 + nt * 8 + (lane & 3) * 2;
            float* d = acc[mt][nt];
            *reinterpret_cast<float2*>(&C[a0 + c0]) = make_float2(d[0], d[1]);
            *reinterpret_cast<float2*>(&C[a1 + c0]) = make_float2(d[2], d[3]);
        }
    }
}

// ---------------------------------------------------------------------------
// Conversions
// ---------------------------------------------------------------------------
__global__ void convw1_kernel(const float* __restrict__ w, __half* __restrict__ oh, int n)
{
    int i = blockIdx.x * 256 + threadIdx.x;
    if (i < n) oh[i] = __float2half(w[i]);
}
__global__ void __launch_bounds__(256)
convt_kernel(const float* __restrict__ in, __half* __restrict__ oh, int K, int N)
{
    __shared__ float t[32][33];
    const int n0 = blockIdx.x * 32, k0 = blockIdx.y * 32;
    const int tx = threadIdx.x, ty = threadIdx.y;
#pragma unroll
    for (int i = 0; i < 4; i++)
        t[ty + 8 * i][tx] = in[(size_t)(k0 + ty + 8 * i) * N + n0 + tx];
    __syncthreads();
#pragma unroll
    for (int i = 0; i < 4; i++) {
        const int r = ty + 8 * i;
        oh[(size_t)(n0 + r) * K + k0 + tx] = __float2half(t[tx][r]);
    }
}
// Q/K per-head transpose (fp16 in, fp16 out): in (c,s)-rows of qkv16; out [h][l][k]
__global__ void __launch_bounds__(256)
convtqk_kernel(const __half* __restrict__ qkv,
               __half* __restrict__ qo, __half* __restrict__ ko)
{
    __shared__ __half t[32][34];
    const int h = blockIdx.z >> 1;
    const int isK = blockIdx.z & 1;
    const __half* in = qkv + (isK ? (size_t)Dm * Pp : 0) + (size_t)h * 8 * Pp;
    __half* o = (isK ? ko : qo) + (size_t)h * Lm * Dm;
    const int l0 = blockIdx.x * 32, k0 = blockIdx.y * 32;
    const int tx = threadIdx.x, ty = threadIdx.y;
#pragma unroll
    for (int i = 0; i < 4; i++) {
        const int k = k0 + ty + 8 * i;
        t[ty + 8 * i][tx] = in[(size_t)(k >> 6) * Pp + (k & 63) * 256 + l0 + tx];
    }
    __syncthreads();
#pragma unroll
    for (int i = 0; i < 4; i++) {
        const int r = ty + 8 * i;
        o[(size_t)(l0 + r) * Dm + k0 + tx] = t[tx][r];
    }
}

// ---------------------------------------------------------------------------
// Channel LayerNorm over D=512 (optional residual, optional transposed fp16 out)
// ---------------------------------------------------------------------------
__global__ __launch_bounds__(256)
void ln_kernel(const float* __restrict__ in, const float* __restrict__ res,
               const float* __restrict__ w, const float* __restrict__ b,
               float* __restrict__ out, __half* __restrict__ obt)
{
    __shared__ float ss[8][32], ss2[8][32];
    __shared__ __half tbuf[32][514];
    const int tx = threadIdx.x, ty = threadIdx.y;
    const int tid = ty * 32 + tx;
    const int pos0 = blockIdx.x * 32;
    const int pos = pos0 + tx;

    float s = 0.f, s2 = 0.f;
    if (res) {
        for (int c = ty; c < Dm; c += 8) {
            float v = in[(size_t)c * Pp + pos] + res[(size_t)c * Pp + pos];
            s += v; s2 += v * v;
        }
    } else {
        for (int c = ty; c < Dm; c += 8) {
            float v = in[(size_t)c * Pp + pos];
            s += v; s2 += v * v;
        }
    }
    ss[ty][tx] = s; ss2[ty][tx] = s2;
    __syncthreads();
    float st = 0.f, st2 = 0.f;
#pragma unroll
    for (int y = 0; y < 8; y++) { st += ss[y][tx]; st2 += ss2[y][tx]; }
    const float mean = st * (1.f / Dm);
    const float var  = st2 * (1.f / Dm) - mean * mean;
    const float rstd = rsqrtf(var + EPS);

    if (res) {
        for (int c = ty; c < Dm; c += 8) {
            float v = in[(size_t)c * Pp + pos] + res[(size_t)c * Pp + pos];
            const float o = (v - mean) * rstd * w[c] + b[c];
            out[(size_t)c * Pp + pos] = o;
            if (obt) tbuf[tx][c] = __float2half(o);
        }
    } else {
        for (int c = ty; c < Dm; c += 8) {
            float v = in[(size_t)c * Pp + pos];
            const float o = (v - mean) * rstd * w[c] + b[c];
            out[(size_t)c * Pp + pos] = o;
            if (obt) tbuf[tx][c] = __float2half(o);
        }
    }
    if (obt) {
        __syncthreads();
#pragma unroll 4
        for (int r = 0; r < 32; r++) {
            const uint32_t val = *reinterpret_cast<const uint32_t*>(&tbuf[r][tid * 2]);
            *reinterpret_cast<uint32_t*>(&obt[(size_t)(pos0 + r) * Dm + tid * 2]) = val;
        }
    }
}

// ---------------------------------------------------------------------------
// Column attention (fp16 qkv input) — K/V loads amortized over 4 i-rows.
// ---------------------------------------------------------------------------
__global__ __launch_bounds__(512)
void colattn_kernel(const __half* __restrict__ qkv, float* __restrict__ out)
{
    const int h = blockIdx.z;
    const int l = blockIdx.x * 32 + threadIdx.x;
    const int ty = threadIdx.y;
    const __half* Q  = qkv + (size_t)h * Cc * Pp;
    const __half* Kp = Q + (size_t)Dm * Pp;
    const __half* V  = Q + 2L * (size_t)Dm * Pp;

    float q[4][Cc];
#pragma unroll
    for (int ii = 0; ii < 4; ii++) {
        const int i = ty + 16 * ii;
#pragma unroll
        for (int c = 0; c < Cc; c++) q[ii][c] = __half2float(Q[(size_t)c * Pp + i * Lm + l]);
    }

    float d[4] = {0.f, 0.f, 0.f, 0.f};
    float acc[4][Cc];
#pragma unroll
    for (int ii = 0; ii < 4; ii++)
#pragma unroll
        for (int c = 0; c < Cc; c++) acc[ii][c] = 0.f;

    for (int j = 0; j < Sm; j++) {
        float kv[Cc], vv[Cc];
#pragma unroll
        for (int c = 0; c < Cc; c++) {
            kv[c] = __half2float(Kp[(size_t)c * Pp + j * Lm + l]);
            vv[c] = __half2float(V [(size_t)c * Pp + j * Lm + l]);
        }
#pragma unroll
        for (int ii = 0; ii < 4; ii++) {
            float sc = 0.f;
#pragma unroll
            for (int c = 0; c < Cc; c++) sc = fmaf(q[ii][c], kv[c], sc);
            const float e = __expf(sc);
            d[ii] += e;
#pragma unroll
            for (int c = 0; c < Cc; c++) acc[ii][c] = fmaf(e, vv[c], acc[ii][c]);
        }
    }
#pragma unroll
    for (int ii = 0; ii < 4; ii++) {
        const int i = ty + 16 * ii;
        const float inv = 1.f / d[ii];
#pragma unroll
        for (int c = 0; c < Cc; c++)
            out[(size_t)(h * Cc + c) * Pp + i * Lm + l] = acc[ii][c] * inv;
    }
}

// ---------------------------------------------------------------------------
// Host side
// ---------------------------------------------------------------------------
extern "C" void kernel_launch(void* const* d_in, const int* in_sizes, int n_in,
                              void* d_out, int out_size)
{
    const float* x     = (const float*)d_in[0];
    const float* w_row = (const float*)d_in[1];
    const float* b_row = (const float*)d_in[2];
    const float* w_col = (const float*)d_in[3];
    const float* b_col = (const float*)d_in[4];
    const float* w_an1 = (const float*)d_in[5];
    const float* b_an1 = (const float*)d_in[6];
    const float* w_an2 = (const float*)d_in[7];
    const float* b_an2 = (const float*)d_in[8];
    const float* w_ff1 = (const float*)d_in[9];
    const float* b_ff1 = (const float*)d_in[10];
    const float* w_ff2 = (const float*)d_in[11];
    const float* b_ff2 = (const float*)d_in[12];
    const float* w_ln1 = (const float*)d_in[13];
    const float* b_ln1 = (const float*)d_in[14];
    const float* w_ln2 = (const float*)d_in[15];
    const float* b_ln2 = (const float*)d_in[16];
    float* outp = (float*)d_out;

    float *tmp, *out1, *attn;
    __half *qkv16, *bt, *ff, *wr, *wc, *f1, *f2, *qt, *kt, *p16;
    cudaGetSymbolAddress((void**)&tmp,   g_tmp);
    cudaGetSymbolAddress((void**)&out1,  g_out1);
    cudaGetSymbolAddress((void**)&attn,  g_attn);
    cudaGetSymbolAddress((void**)&qkv16, g_qkv16);
    cudaGetSymbolAddress((void**)&bt,    g_bt);
    cudaGetSymbolAddress((void**)&ff,    g_ff);
    cudaGetSymbolAddress((void**)&wr,    g_wr);
    cudaGetSymbolAddress((void**)&wc,    g_wc);
    cudaGetSymbolAddress((void**)&f1,    g_f1);
    cudaGetSymbolAddress((void**)&f2,    g_f2);
    cudaGetSymbolAddress((void**)&qt,    g_qt);
    cudaGetSymbolAddress((void**)&kt,    g_kt);
    cudaGetSymbolAddress((void**)&p16,   g_p16);

    cudaFuncSetAttribute(gemm_mma<0>, cudaFuncAttributeMaxDynamicSharedMemorySize, MM_SMEM);
    cudaFuncSetAttribute(gemm_mma<1>, cudaFuncAttributeMaxDynamicSharedMemorySize, MM_SMEM);
    cudaFuncSetAttribute(gemm_mma<2>, cudaFuncAttributeMaxDynamicSharedMemorySize, MM_SMEM);
    cudaFuncSetAttribute(gemm_scores, cudaFuncAttributeMaxDynamicSharedMemorySize, SC_SMEM);
    cudaFuncSetAttribute(gemm_vp,     cudaFuncAttributeMaxDynamicSharedMemorySize, MM_SMEM);

    // weight conversions
    convw1_kernel<<<(3 * Dm * Dm + 255) / 256, 256>>>(w_row, wr, 3 * Dm * Dm);
    convw1_kernel<<<(3 * Dm * Dm + 255) / 256, 256>>>(w_col, wc, 3 * Dm * Dm);
    convw1_kernel<<<(Fm * Dm + 255) / 256, 256>>>(w_ff1, f1, Fm * Dm);
    convw1_kernel<<<(Dm * Fm + 255) / 256, 256>>>(w_ff2, f2, Dm * Fm);

    // x -> transposed fp16
    convt_kernel<<<dim3(Pp / 32, Dm / 32), dim3(32, 8)>>>(x, bt, Dm, Pp);

    // 1) row qkv = w_row @ x + b_row  -> fp16 [1536][16384]
    gemm_mma<2><<<dim3((3 * Dm) / 128, Pp / 128), 256, MM_SMEM>>>(
        wr, bt, b_row, nullptr, qkv16, 3 * Dm, Pp, Dm);

    // 2) Q/K transpose (fp16 -> fp16 per-head layout)
    convtqk_kernel<<<dim3(Lm / 32, Dm / 32, 2 * Hh), dim3(32, 8)>>>(qkv16, qt, kt);

    // 3) scores + fused softmax -> P fp16
    gemm_scores<<<dim3(Lm / 64, 1, Hh), 256, SC_SMEM>>>(qt, kt, p16);

    // 4) row_out = V * P^T (V = qkv16 section)
    gemm_vp<<<dim3(4, 2, Hh), 256, MM_SMEM>>>(qkv16 + 2L * Dm * Pp, p16, tmp);

    // 5) out1 = LN(x + row_out; an1), fused transposed fp16 -> bt
    ln_kernel<<<Pp / 32, dim3(32, 8)>>>(x, tmp, w_an1, b_an1, out1, bt);

    // 6) col qkv = w_col @ out1 + b_col -> fp16
    gemm_mma<2><<<dim3((3 * Dm) / 128, Pp / 128), 256, MM_SMEM>>>(
        wc, bt, b_col, nullptr, qkv16, 3 * Dm, Pp, Dm);

    // 7) column attention (fp16 in)
    colattn_kernel<<<dim3(Lm / 32, 1, Hh), dim3(32, 16)>>>(qkv16, tmp);

    // 8) attn_out = LN(out1 + col_out; an2)
    ln_kernel<<<Pp / 32, dim3(32, 8)>>>(out1, tmp, w_an2, b_an2, attn, nullptr);

    // 9) h = LN(attn_out; ln1), fused transposed fp16 -> bt
    ln_kernel<<<Pp / 32, dim3(32, 8)>>>(attn, nullptr, w_ln1, b_ln1, out1, bt);

    // 10) ff1: relu(w_ff1 @ h + b_ff1) -> fp16 transposed
    gemm_mma<1><<<dim3(Fm / 128, Pp / 128), 256, MM_SMEM>>>(
        f1, bt, b_ff1, nullptr, ff, Fm, Pp, Dm);

    // 11) ff2 = w_ff2 @ ff1 + b_ff2
    gemm_mma<0><<<dim3(Dm / 128, Pp / 128), 256, MM_SMEM>>>(
        f2, ff, b_ff2, tmp, nullptr, Dm, Pp, Fm);

    // 12) out = LN(h + ff2; ln2)
    ln_kernel<<<Pp / 32, dim3(32, 8)>>>(out1, tmp, w_ln2, b_ln2, outp, nullptr);
}

// round 10
// speedup vs baseline: 4.5750x; 1.0396x over previous
#include <cuda_runtime.h>
#include <cuda_fp16.h>
#include <math_constants.h>
#include <cstdint>
#include <cstddef>

// ---------------------------------------------------------------------------
// Problem constants
// ---------------------------------------------------------------------------
#define Dm   512
#define Sm   64
#define Lm   256
#define Fm   2048
#define Hh   64
#define Cc   8
#define Pp   (Sm * Lm)          // 16384 spatial positions
#define EPS  1e-5f

// ---------------------------------------------------------------------------
// Scratch buffers (static device globals -- allocation-free)
// ---------------------------------------------------------------------------
__device__ __align__(256) float g_tmp [(long)Dm * Pp];
__device__ __align__(256) float g_out1[(long)Dm * Pp];
__device__ __align__(256) float g_attn[(long)Dm * Pp];

// fp16 operands (all single-plane)
__device__ __align__(256) __half g_qkv16[3L * Dm * Pp];      // qkv fp16 [1536][16384]
__device__ __align__(256) __half g_bt [(long)Pp * Dm];       // act^T [Pp,512]
__device__ __align__(256) __half g_ff [(long)Pp * Fm];       // ff1^T [Pp,2048]
__device__ __align__(256) __half g_wr [3 * Dm * Dm];
__device__ __align__(256) __half g_wc [3 * Dm * Dm];
__device__ __align__(256) __half g_f1 [Fm * Dm];
__device__ __align__(256) __half g_f2 [Dm * Fm];
__device__ __align__(256) __half g_qt [(long)Hh * Lm * Dm];  // Q^T per head
__device__ __align__(256) __half g_kt [(long)Hh * Lm * Dm];  // K^T per head
__device__ __align__(256) __half g_p16[(long)Hh * Lm * Lm];  // P [h][i][j]

// ---------------------------------------------------------------------------
// PTX helpers
// ---------------------------------------------------------------------------
__device__ __forceinline__ uint32_t smem_u32(const void* p) {
    uint32_t a;
    asm("{ .reg .u64 t; cvta.to.shared.u64 t, %1; cvt.u32.u64 %0, t; }" : "=r"(a) : "l"(p));
    return a;
}
__device__ __forceinline__ void cpasync16(uint32_t dst, const void* src) {
    asm volatile("cp.async.cg.shared.global [%0], [%1], 16;" :: "r"(dst), "l"(src));
}
__device__ __forceinline__ void cp_commit() {
    asm volatile("cp.async.commit_group;" ::: "memory");
}
template<int N>
__device__ __forceinline__ void cp_wait() {
    asm volatile("cp.async.wait_group %0;" :: "n"(N) : "memory");
}
__device__ __forceinline__ void ldsm4(uint32_t* r, uint32_t addr) {
    asm volatile("ldmatrix.sync.aligned.m8n8.x4.shared.b16 {%0,%1,%2,%3}, [%4];"
                 : "=r"(r[0]), "=r"(r[1]), "=r"(r[2]), "=r"(r[3]) : "r"(addr));
}
__device__ __forceinline__ void mma16816h(float* d, const uint32_t* a, uint32_t b0, uint32_t b1) {
    asm volatile("mma.sync.aligned.m16n8k16.row.col.f32.f16.f16.f32 "
                 "{%0,%1,%2,%3}, {%4,%5,%6,%7}, {%8,%9}, {%0,%1,%2,%3};"
                 : "+f"(d[0]), "+f"(d[1]), "+f"(d[2]), "+f"(d[3])
                 : "r"(a[0]), "r"(a[1]), "r"(a[2]), "r"(a[3]), "r"(b0), "r"(b1));
}

// ---------------------------------------------------------------------------
// Big GEMM: C[M,N] = W[M,K] * B[N,K]^T (+bias), single fp16 pass.
// CTA tile 128x128, BK=64, 3-stage ring (96KB), 8 warps (4m x 2n), 2 CTAs/SM.
//   MODE 0: C fp32 [M,N] + bias.
//   MODE 1: relu(+bias) -> fp16 transposed [N,M].
//   MODE 2: fp16 [M,N] + bias (qkv chain).
// ---------------------------------------------------------------------------
#define MM_SBYTES 32768u
#define MM_SMEM   (3 * MM_SBYTES)

template<int MODE>
__global__ void __launch_bounds__(256, 2)
gemm_mma(const __half* __restrict__ A, const __half* __restrict__ B,
         const float* __restrict__ bias,
         float* __restrict__ C, __half* __restrict__ oH,
         int M, int N, int K)
{
    extern __shared__ char smem[];
    const uint32_t sb = smem_u32(smem);

    const int tid  = threadIdx.x;
    const int wid  = tid >> 5;
    const int lane = tid & 31;
    const int warpM = wid & 3;
    const int warpN = wid >> 2;
    const int bm = blockIdx.x * 128;
    const int bn = blockIdx.y * 128;

    auto load_stage = [&](int st, int it) {
        const uint32_t sbase = sb + st * MM_SBYTES;
        const int k0 = it << 6;
#pragma unroll
        for (int j = 0; j < 4; j++) {
            const int idx = tid + j * 256;
            const int row = idx >> 3;
            const int c   = idx & 7;
            const uint32_t soff = row * 128 + ((c * 16) ^ ((row & 7) << 4));
            cpasync16(sbase +         soff, A + (size_t)(bm + row) * K + k0 + c * 8);
            cpasync16(sbase + 16384 + soff, B + (size_t)(bn + row) * K + k0 + c * 8);
        }
    };

    float acc[2][8][4];
#pragma unroll
    for (int i = 0; i < 2; i++)
#pragma unroll
        for (int j = 0; j < 8; j++)
#pragma unroll
            for (int v = 0; v < 4; v++) acc[i][j][v] = 0.f;

    const int nIter = K >> 6;
    load_stage(0, 0); cp_commit();
    load_stage(1, 1); cp_commit();

    const int rsub  = lane & 15;
    const int khalf = ((lane >> 4) & 1) * 16;
    const int rA = warpM * 32 + rsub;
    const int rB = warpN * 64 + rsub;
    const uint32_t xA = (rA & 7) << 4;
    const uint32_t xB = (rB & 7) << 4;

    for (int it = 0; it < nIter; it++) {
        cp_wait<1>();
        __syncthreads();
        if (it + 2 < nIter) load_stage((it + 2) % 3, it + 2);
        cp_commit();

        const uint32_t sbase = sb + (it % 3) * MM_SBYTES;
        const uint32_t pA = sbase +         rA * 128;
        const uint32_t pB = sbase + 16384 + rB * 128;

#pragma unroll
        for (int q = 0; q < 4; q++) {
            const uint32_t kb = q * 32 + khalf;
            uint32_t ah[2][4], bb[4][4];
#pragma unroll
            for (int mt = 0; mt < 2; mt++)
                ldsm4(ah[mt], pA + mt * 2048 + (kb ^ xA));
#pragma unroll
            for (int g = 0; g < 4; g++)
                ldsm4(bb[g], pB + g * 2048 + (kb ^ xB));
#pragma unroll
            for (int mt = 0; mt < 2; mt++)
#pragma unroll
                for (int nt = 0; nt < 8; nt++) {
                    const int g = nt >> 1, o = nt & 1;
                    mma16816h(acc[mt][nt], ah[mt], bb[g][o], bb[g][o + 2]);
                }
        }
    }
    cp_wait<0>();
    __syncthreads();

    if (MODE == 0) {
#pragma unroll
        for (int mt = 0; mt < 2; mt++) {
            const int r0 = bm + warpM * 32 + mt * 16 + (lane >> 2);
            const float bv0 = bias[r0], bv1 = bias[r0 + 8];
#pragma unroll
            for (int nt = 0; nt < 8; nt++) {
                const int c0 = bn + warpN * 64 + nt * 8 + (lane & 3) * 2;
                float* d = acc[mt][nt];
                *reinterpret_cast<float2*>(&C[(size_t)r0 * N + c0])       = make_float2(d[0] + bv0, d[1] + bv0);
                *reinterpret_cast<float2*>(&C[(size_t)(r0 + 8) * N + c0]) = make_float2(d[2] + bv1, d[3] + bv1);
            }
        }
    } else if (MODE == 2) {
#pragma unroll
        for (int mt = 0; mt < 2; mt++) {
            const int r0 = bm + warpM * 32 + mt * 16 + (lane >> 2);
            const float bv0 = bias[r0], bv1 = bias[r0 + 8];
#pragma unroll
            for (int nt = 0; nt < 8; nt++) {
                const int c0 = bn + warpN * 64 + nt * 8 + (lane & 3) * 2;
                float* d = acc[mt][nt];
                *reinterpret_cast<__half2*>(&oH[(size_t)r0 * N + c0])       = __floats2half2_rn(d[0] + bv0, d[1] + bv0);
                *reinterpret_cast<__half2*>(&oH[(size_t)(r0 + 8) * N + c0]) = __floats2half2_rn(d[2] + bv1, d[3] + bv1);
            }
        }
    } else {
        float* T = reinterpret_cast<float*>(smem);   // [128][130]
#pragma unroll
        for (int mt = 0; mt < 2; mt++) {
            const int lr0 = warpM * 32 + mt * 16 + (lane >> 2);
            const float bv0 = bias[bm + lr0], bv1 = bias[bm + lr0 + 8];
#pragma unroll
            for (int nt = 0; nt < 8; nt++) {
                const int lc0 = warpN * 64 + nt * 8 + (lane & 3) * 2;
                float* d = acc[mt][nt];
                T[lr0 * 130 + lc0]           = fmaxf(d[0] + bv0, 0.f);
                T[lr0 * 130 + lc0 + 1]       = fmaxf(d[1] + bv0, 0.f);
                T[(lr0 + 8) * 130 + lc0]     = fmaxf(d[2] + bv1, 0.f);
                T[(lr0 + 8) * 130 + lc0 + 1] = fmaxf(d[3] + bv1, 0.f);
            }
        }
        __syncthreads();
        const int mloc = tid & 127;
#pragma unroll 4
        for (int rep = 0; rep < 64; rep++) {
            const int nl = rep * 2 + (tid >> 7);
            oH[(size_t)(bn + nl) * M + bm + mloc] = __float2half(T[mloc * 130 + nl]);
        }
    }
}

// ---------------------------------------------------------------------------
// Row-attention scores + FUSED softmax: per head tile 64(i) x 256(j), K=512.
// 2-stage ring (80KB) -> 2 CTAs/SM.
// ---------------------------------------------------------------------------
#define SC_SBYTES 40960u
#define SC_SMEM   (2 * SC_SBYTES)   // 80KB; softmax tile 64*260*4=66.5KB fits

__global__ void __launch_bounds__(256, 2)
gemm_scores(const __half* __restrict__ Q, const __half* __restrict__ Kt,
            __half* __restrict__ P)
{
    constexpr int K = 512;
    extern __shared__ char smem[];
    const uint32_t sb = smem_u32(smem);

    const int tid = threadIdx.x, wid = tid >> 5, lane = tid & 31;
    const int warpM = wid & 3;
    const int warpN = wid >> 2;
    const int bm = blockIdx.x * 64;
    const int h = blockIdx.z;
    const __half* A = Q  + (size_t)h * Lm * Dm;
    const __half* B = Kt + (size_t)h * Lm * Dm;

    auto load_stage = [&](int st, int it) {
        const uint32_t sbase = sb + st * SC_SBYTES;
        const int k0 = it << 6;
#pragma unroll
        for (int j = 0; j < 10; j++) {
            const int idx = tid + j * 256;
            if (idx < 512) {
                const int row = idx >> 3, c = idx & 7;
                const uint32_t soff = row * 128 + ((c * 16) ^ ((row & 7) << 4));
                cpasync16(sbase + soff, A + (size_t)(bm + row) * K + k0 + c * 8);
            } else {
                const int i2 = idx - 512;
                const int row = i2 >> 3, c = i2 & 7;
                const uint32_t soff = row * 128 + ((c * 16) ^ ((row & 7) << 4));
                cpasync16(sbase + 8192 + soff, B + (size_t)row * K + k0 + c * 8);
            }
        }
    };

    float acc[16][4];
#pragma unroll
    for (int j = 0; j < 16; j++)
#pragma unroll
        for (int v = 0; v < 4; v++) acc[j][v] = 0.f;

    load_stage(0, 0); cp_commit();
    load_stage(1, 1); cp_commit();

    const int rsub  = lane & 15;
    const int khalf = ((lane >> 4) & 1) * 16;
    const int rA = warpM * 16 + rsub;
    const int rBb = warpN * 128 + rsub;
    const uint32_t xs = (rsub & 7) << 4;

    for (int it = 0; it < 8; it++) {
        cp_wait<1>();
        __syncthreads();

        const uint32_t sbase = sb + (it & 1) * SC_SBYTES;
        const uint32_t pA = sbase +        rA  * 128;
        const uint32_t pB = sbase + 8192 + rBb * 128;

#pragma unroll
        for (int q = 0; q < 4; q++) {
            const uint32_t kb = q * 32 + khalf;
            uint32_t ah[4], bb[8][4];
            ldsm4(ah, pA + (kb ^ xs));
#pragma unroll
            for (int g = 0; g < 8; g++)
                ldsm4(bb[g], pB + g * 2048 + (kb ^ xs));
#pragma unroll
            for (int nt = 0; nt < 16; nt++) {
                const int g = nt >> 1, o = nt & 1;
                mma16816h(acc[nt], ah, bb[g][o], bb[g][o + 2]);
            }
        }
        __syncthreads();
        if (it + 2 < 8) { load_stage(it & 1, it + 2); }
        cp_commit();
    }
    cp_wait<0>();
    __syncthreads();

    float* S = reinterpret_cast<float*>(smem);
    {
        const int r0 = warpM * 16 + (lane >> 2);
#pragma unroll
        for (int nt = 0; nt < 16; nt++) {
            const int c0 = warpN * 128 + nt * 8 + (lane & 3) * 2;
            float* d = acc[nt];
            S[r0 * 260 + c0]           = d[0];
            S[r0 * 260 + c0 + 1]       = d[1];
            S[(r0 + 8) * 260 + c0]     = d[2];
            S[(r0 + 8) * 260 + c0 + 1] = d[3];
        }
    }
    __syncthreads();

#pragma unroll
    for (int rr = 0; rr < 8; rr++) {
        const int r = wid * 8 + rr;
        float v[8];
#pragma unroll
        for (int k = 0; k < 8; k++) v[k] = S[r * 260 + lane + 32 * k];
        float m = v[0];
#pragma unroll
        for (int k = 1; k < 8; k++) m = fmaxf(m, v[k]);
#pragma unroll
        for (int o = 16; o; o >>= 1) m = fmaxf(m, __shfl_xor_sync(0xffffffffu, m, o));
        float s = 0.f;
#pragma unroll
        for (int k = 0; k < 8; k++) { v[k] = __expf(v[k] - m); s += v[k]; }
#pragma unroll
        for (int o = 16; o; o >>= 1) s += __shfl_xor_sync(0xffffffffu, s, o);
        const float inv = 1.f / s;
        __half* dst = P + ((size_t)h * Lm + bm + r) * Lm;
#pragma unroll
        for (int k = 0; k < 8; k++) dst[lane + 32 * k] = __float2half(v[k] * inv);
    }
}

// ---------------------------------------------------------------------------
// Row-attention output: per head, C[m=(c,s), i] = sum_j V[m,j] * P[i,j].
// ---------------------------------------------------------------------------
__global__ void __launch_bounds__(256, 2)
gemm_vp(const __half* __restrict__ V, const __half* __restrict__ P,
        float* __restrict__ O)
{
    constexpr int K = 256;
    extern __shared__ char smem[];
    const uint32_t sb = smem_u32(smem);

    const int tid = threadIdx.x, wid = tid >> 5, lane = tid & 31;
    const int warpM = wid & 3, warpN = wid >> 2;
    const int bm = blockIdx.x * 128, bn = blockIdx.y * 128;
    const int h = blockIdx.z;
    const __half* Av = V + (size_t)h * 8 * Pp;
    const __half* Bp = P + (size_t)h * Lm * Lm;
    float* C = O + (size_t)h * 8 * Pp;

    auto load_stage = [&](int st, int it) {
        const uint32_t sbase = sb + st * MM_SBYTES;
        const int k0 = it << 6;
#pragma unroll
        for (int j = 0; j < 4; j++) {
            const int idx = tid + j * 256;
            const int row = idx >> 3;
            const int c   = idx & 7;
            const uint32_t soff = row * 128 + ((c * 16) ^ ((row & 7) << 4));
            const int mrow = bm + row;
            const size_t ga = (size_t)(mrow >> 6) * Pp + (mrow & 63) * 256 + k0 + c * 8;
            cpasync16(sbase +         soff, Av + ga);
            cpasync16(sbase + 16384 + soff, Bp + (size_t)(bn + row) * K + k0 + c * 8);
        }
    };

    float acc[2][8][4];
#pragma unroll
    for (int i = 0; i < 2; i++)
#pragma unroll
        for (int j = 0; j < 8; j++)
#pragma unroll
            for (int v = 0; v < 4; v++) acc[i][j][v] = 0.f;

    load_stage(0, 0); cp_commit();
    load_stage(1, 1); cp_commit();

    const int rsub  = lane & 15;
    const int khalf = ((lane >> 4) & 1) * 16;
    const int rA = warpM * 32 + rsub;
    const int rB = warpN * 64 + rsub;
    const uint32_t xA = (rA & 7) << 4;
    const uint32_t xB = (rB & 7) << 4;

    for (int it = 0; it < 4; it++) {
        cp_wait<1>();
        __syncthreads();
        if (it + 2 < 4) load_stage((it + 2) % 3, it + 2);
        cp_commit();

        const uint32_t sbase = sb + (it % 3) * MM_SBYTES;
        const uint32_t pA = sbase +         rA * 128;
        const uint32_t pB = sbase + 16384 + rB * 128;

#pragma unroll
        for (int q = 0; q < 4; q++) {
            const uint32_t kb = q * 32 + khalf;
            uint32_t av[2][4], bb[4][4];
#pragma unroll
            for (int mt = 0; mt < 2; mt++)
                ldsm4(av[mt], pA + mt * 2048 + (kb ^ xA));
#pragma unroll
            for (int g = 0; g < 4; g++)
                ldsm4(bb[g], pB + g * 2048 + (kb ^ xB));
#pragma unroll
            for (int mt = 0; mt < 2; mt++)
#pragma unroll
                for (int nt = 0; nt < 8; nt++) {
                    const int g = nt >> 1, o = nt & 1;
                    mma16816h(acc[mt][nt], av[mt], bb[g][o], bb[g][o + 2]);
                }
        }
    }
    cp_wait<0>();
    __syncthreads();

#pragma unroll
    for (int mt = 0; mt < 2; mt++) {
        const int r0 = bm + warpM * 32 + mt * 16 + (lane >> 2);
        const int r1 = r0 + 8;
        const size_t a0 = (size_t)(r0 >> 6) * Pp + (r0 & 63) * 256;
        const size_t a1 = (size_t)(r1 >> 6) * Pp + (r1 & 63) * 256;
#pragma unroll
        for (int nt = 0; nt < 8; nt++) {
            const int c0 = bn + warpN * 64 + nt * 8 + (lane & 3) * 2;
            float* d = acc[mt][nt];
            *reinterpret_cast<float2*>(&C[a0 + c0]) = make_float2(d[0], d[1]);
            *reinterpret_cast<float2*>(&C[a1 + c0]) = make_float2(d[2], d[3]);
        }
    }
}

// ---------------------------------------------------------------------------
// Merged weight conversion (all 4 weight matrices, float4-vectorized)
// ---------------------------------------------------------------------------
#define WN1 (3 * Dm * Dm)          // 786432
#define WN2 (2 * WN1)              // wc end
#define WN3 (WN2 + Fm * Dm)        // f1 end
#define WN4 (WN3 + Dm * Fm)        // f2 end (3670016)

__global__ void convw_all(const float* __restrict__ w_row, const float* __restrict__ w_col,
                          const float* __restrict__ wf1, const float* __restrict__ wf2,
                          __half* __restrict__ owr, __half* __restrict__ owc,
                          __half* __restrict__ of1, __half* __restrict__ of2)
{
    const long i = ((long)blockIdx.x * 256 + threadIdx.x) * 4;
    const float* src; __half* dst; long off;
    if (i < WN1)      { src = w_row; dst = owr; off = 0; }
    else if (i < WN2) { src = w_col; dst = owc; off = WN1; }
    else if (i < WN3) { src = wf1;   dst = of1; off = WN2; }
    else              { src = wf2;   dst = of2; off = WN3; }
    const long j = i - off;
    const float4 v = *reinterpret_cast<const float4*>(src + j);
    *reinterpret_cast<__half2*>(dst + j)     = __floats2half2_rn(v.x, v.y);
    *reinterpret_cast<__half2*>(dst + j + 2) = __floats2half2_rn(v.z, v.w);
}

// act fp32 [K, N] -> fp16 [N, K] (transposed) — only for the initial x
__global__ void __launch_bounds__(256)
convt_kernel(const float* __restrict__ in, __half* __restrict__ oh, int K, int N)
{
    __shared__ float t[32][33];
    const int n0 = blockIdx.x * 32, k0 = blockIdx.y * 32;
    const int tx = threadIdx.x, ty = threadIdx.y;
#pragma unroll
    for (int i = 0; i < 4; i++)
        t[ty + 8 * i][tx] = in[(size_t)(k0 + ty + 8 * i) * N + n0 + tx];
    __syncthreads();
#pragma unroll
    for (int i = 0; i < 4; i++) {
        const int r = ty + 8 * i;
        oh[(size_t)(n0 + r) * K + k0 + tx] = __float2half(t[tx][r]);
    }
}
// Q/K per-head transpose (fp16 in, fp16 out)
__global__ void __launch_bounds__(256)
convtqk_kernel(const __half* __restrict__ qkv,
               __half* __restrict__ qo, __half* __restrict__ ko)
{
    __shared__ __half t[32][34];
    const int h = blockIdx.z >> 1;
    const int isK = blockIdx.z & 1;
    const __half* in = qkv + (isK ? (size_t)Dm * Pp : 0) + (size_t)h * 8 * Pp;
    __half* o = (isK ? ko : qo) + (size_t)h * Lm * Dm;
    const int l0 = blockIdx.x * 32, k0 = blockIdx.y * 32;
    const int tx = threadIdx.x, ty = threadIdx.y;
#pragma unroll
    for (int i = 0; i < 4; i++) {
        const int k = k0 + ty + 8 * i;
        t[ty + 8 * i][tx] = in[(size_t)(k >> 6) * Pp + (k & 63) * 256 + l0 + tx];
    }
    __syncthreads();
#pragma unroll
    for (int i = 0; i < 4; i++) {
        const int r = ty + 8 * i;
        o[(size_t)(l0 + r) * Dm + k0 + tx] = t[tx][r];
    }
}

// ---------------------------------------------------------------------------
// Channel LayerNorm over D=512 (optional residual, optional transposed fp16 out)
// Values cached in registers (single global read pass).
// ---------------------------------------------------------------------------
__global__ __launch_bounds__(256)
void ln_kernel(const float* __restrict__ in, const float* __restrict__ res,
               const float* __restrict__ w, const float* __restrict__ b,
               float* __restrict__ out, __half* __restrict__ obt)
{
    __shared__ float ss[8][32], ss2[8][32];
    __shared__ __half tbuf[32][514];
    const int tx = threadIdx.x, ty = threadIdx.y;
    const int tid = ty * 32 + tx;
    const int pos0 = blockIdx.x * 32;
    const int pos = pos0 + tx;

    float vals[64];
    float s = 0.f, s2 = 0.f;
    if (res) {
#pragma unroll
        for (int i = 0; i < 64; i++) {
            const int c = ty + 8 * i;
            const float v = in[(size_t)c * Pp + pos] + res[(size_t)c * Pp + pos];
            vals[i] = v; s += v; s2 += v * v;
        }
    } else {
#pragma unroll
        for (int i = 0; i < 64; i++) {
            const int c = ty + 8 * i;
            const float v = in[(size_t)c * Pp + pos];
            vals[i] = v; s += v; s2 += v * v;
        }
    }
    ss[ty][tx] = s; ss2[ty][tx] = s2;
    __syncthreads();
    float st = 0.f, st2 = 0.f;
#pragma unroll
    for (int y = 0; y < 8; y++) { st += ss[y][tx]; st2 += ss2[y][tx]; }
    const float mean = st * (1.f / Dm);
    const float var  = st2 * (1.f / Dm) - mean * mean;
    const float rstd = rsqrtf(var + EPS);

#pragma unroll
    for (int i = 0; i < 64; i++) {
        const int c = ty + 8 * i;
        const float o = (vals[i] - mean) * rstd * w[c] + b[c];
        out[(size_t)c * Pp + pos] = o;
        if (obt) tbuf[tx][c] = __float2half(o);
    }
    if (obt) {
        __syncthreads();
#pragma unroll 4
        for (int r = 0; r < 32; r++) {
            const uint32_t val = *reinterpret_cast<const uint32_t*>(&tbuf[r][tid * 2]);
            *reinterpret_cast<uint32_t*>(&obt[(size_t)(pos0 + r) * Dm + tid * 2]) = val;
        }
    }
}

// ---------------------------------------------------------------------------
// Column attention (fp16 qkv input) — K/V loads amortized over 4 i-rows.
// ---------------------------------------------------------------------------
__global__ __launch_bounds__(512)
void colattn_kernel(const __half* __restrict__ qkv, float* __restrict__ out)
{
    const int h = blockIdx.z;
    const int l = blockIdx.x * 32 + threadIdx.x;
    const int ty = threadIdx.y;
    const __half* Q  = qkv + (size_t)h * Cc * Pp;
    const __half* Kp = Q + (size_t)Dm * Pp;
    const __half* V  = Q + 2L * (size_t)Dm * Pp;

    float q[4][Cc];
#pragma unroll
    for (int ii = 0; ii < 4; ii++) {
        const int i = ty + 16 * ii;
#pragma unroll
        for (int c = 0; c < Cc; c++) q[ii][c] = __half2float(Q[(size_t)c * Pp + i * Lm + l]);
    }

    float d[4] = {0.f, 0.f, 0.f, 0.f};
    float acc[4][Cc];
#pragma unroll
    for (int ii = 0; ii < 4; ii++)
#pragma unroll
        for (int c = 0; c < Cc; c++) acc[ii][c] = 0.f;

    for (int j = 0; j < Sm; j++) {
        float kv[Cc], vv[Cc];
#pragma unroll
        for (int c = 0; c < Cc; c++) {
            kv[c] = __half2float(Kp[(size_t)c * Pp + j * Lm + l]);
            vv[c] = __half2float(V [(size_t)c * Pp + j * Lm + l]);
        }
#pragma unroll
        for (int ii = 0; ii < 4; ii++) {
            float sc = 0.f;
#pragma unroll
            for (int c = 0; c < Cc; c++) sc = fmaf(q[ii][c], kv[c], sc);
            const float e = __expf(sc);
            d[ii] += e;
#pragma unroll
            for (int c = 0; c < Cc; c++) acc[ii][c] = fmaf(e, vv[c], acc[ii][c]);
        }
    }
#pragma unroll
    for (int ii = 0; ii < 4; ii++) {
        const int i = ty + 16 * ii;
        const float inv = 1.f / d[ii];
#pragma unroll
        for (int c = 0; c < Cc; c++)
            out[(size_t)(h * Cc + c) * Pp + i * Lm + l] = acc[ii][c] * inv;
    }
}

// ---------------------------------------------------------------------------
// Host side
// ---------------------------------------------------------------------------
extern "C" void kernel_launch(void* const* d_in, const int* in_sizes, int n_in,
                              void* d_out, int out_size)
{
    const float* x     = (const float*)d_in[0];
    const float* w_row = (const float*)d_in[1];
    const float* b_row = (const float*)d_in[2];
    const float* w_col = (const float*)d_in[3];
    const float* b_col = (const float*)d_in[4];
    const float* w_an1 = (const float*)d_in[5];
    const float* b_an1 = (const float*)d_in[6];
    const float* w_an2 = (const float*)d_in[7];
    const float* b_an2 = (const float*)d_in[8];
    const float* w_ff1 = (const float*)d_in[9];
    const float* b_ff1 = (const float*)d_in[10];
    const float* w_ff2 = (const float*)d_in[11];
    const float* b_ff2 = (const float*)d_in[12];
    const float* w_ln1 = (const float*)d_in[13];
    const float* b_ln1 = (const float*)d_in[14];
    const float* w_ln2 = (const float*)d_in[15];
    const float* b_ln2 = (const float*)d_in[16];
    float* outp = (float*)d_out;

    float *tmp, *out1, *attn;
    __half *qkv16, *bt, *ff, *wr, *wc, *f1, *f2, *qt, *kt, *p16;
    cudaGetSymbolAddress((void**)&tmp,   g_tmp);
    cudaGetSymbolAddress((void**)&out1,  g_out1);
    cudaGetSymbolAddress((void**)&attn,  g_attn);
    cudaGetSymbolAddress((void**)&qkv16, g_qkv16);
    cudaGetSymbolAddress((void**)&bt,    g_bt);
    cudaGetSymbolAddress((void**)&ff,    g_ff);
    cudaGetSymbolAddress((void**)&wr,    g_wr);
    cudaGetSymbolAddress((void**)&wc,    g_wc);
    cudaGetSymbolAddress((void**)&f1,    g_f1);
    cudaGetSymbolAddress((void**)&f2,    g_f2);
    cudaGetSymbolAddress((void**)&qt,    g_qt);
    cudaGetSymbolAddress((void**)&kt,    g_kt);
    cudaGetSymbolAddress((void**)&p16,   g_p16);

    cudaFuncSetAttribute(gemm_mma<0>, cudaFuncAttributeMaxDynamicSharedMemorySize, MM_SMEM);
    cudaFuncSetAttribute(gemm_mma<1>, cudaFuncAttributeMaxDynamicSharedMemorySize, MM_SMEM);
    cudaFuncSetAttribute(gemm_mma<2>, cudaFuncAttributeMaxDynamicSharedMemorySize, MM_SMEM);
    cudaFuncSetAttribute(gemm_scores, cudaFuncAttributeMaxDynamicSharedMemorySize, SC_SMEM);
    cudaFuncSetAttribute(gemm_vp,     cudaFuncAttributeMaxDynamicSharedMemorySize, MM_SMEM);

    // merged weight conversion (single launch)
    convw_all<<<WN4 / 1024, 256>>>(w_row, w_col, w_ff1, w_ff2, wr, wc, f1, f2);

    // x -> transposed fp16
    convt_kernel<<<dim3(Pp / 32, Dm / 32), dim3(32, 8)>>>(x, bt, Dm, Pp);

    // 1) row qkv = w_row @ x + b_row  -> fp16 [1536][16384]
    gemm_mma<2><<<dim3((3 * Dm) / 128, Pp / 128), 256, MM_SMEM>>>(
        wr, bt, b_row, nullptr, qkv16, 3 * Dm, Pp, Dm);

    // 2) Q/K transpose (fp16 -> per-head layout)
    convtqk_kernel<<<dim3(Lm / 32, Dm / 32, 2 * Hh), dim3(32, 8)>>>(qkv16, qt, kt);

    // 3) scores + fused softmax -> P fp16 (2 CTAs/SM)
    gemm_scores<<<dim3(Lm / 64, 1, Hh), 256, SC_SMEM>>>(qt, kt, p16);

    // 4) row_out = V * P^T
    gemm_vp<<<dim3(4, 2, Hh), 256, MM_SMEM>>>(qkv16 + 2L * Dm * Pp, p16, tmp);

    // 5) out1 = LN(x + row_out; an1), fused transposed fp16 -> bt
    ln_kernel<<<Pp / 32, dim3(32, 8)>>>(x, tmp, w_an1, b_an1, out1, bt);

    // 6) col qkv = w_col @ out1 + b_col -> fp16
    gemm_mma<2><<<dim3((3 * Dm) / 128, Pp / 128), 256, MM_SMEM>>>(
        wc, bt, b_col, nullptr, qkv16, 3 * Dm, Pp, Dm);

    // 7) column attention (fp16 in)
    colattn_kernel<<<dim3(Lm / 32, 1, Hh), dim3(32, 16)>>>(qkv16, tmp);

    // 8) attn_out = LN(out1 + col_out; an2)
    ln_kernel<<<Pp / 32, dim3(32, 8)>>>(out1, tmp, w_an2, b_an2, attn, nullptr);

    // 9) h = LN(attn_out; ln1), fused transposed fp16 -> bt
    ln_kernel<<<Pp / 32, dim3(32, 8)>>>(attn, nullptr, w_ln1, b_ln1, out1, bt);

    // 10) ff1: relu(w_ff1 @ h + b_ff1) -> fp16 transposed
    gemm_mma<1><<<dim3(Fm / 128, Pp / 128), 256, MM_SMEM>>>(
        f1, bt, b_ff1, nullptr, ff, Fm, Pp, Dm);

    // 11) ff2 = w_ff2 @ ff1 + b_ff2
    gemm_mma<0><<<dim3(Dm / 128, Pp / 128), 256, MM_SMEM>>>(
        f2, ff, b_ff2, tmp, nullptr, Dm, Pp, Fm);

    // 12) out = LN(h + ff2; ln2)
    ln_kernel<<<Pp / 32, dim3(32, 8)>>>(out1, tmp, w_ln2, b_ln2, outp, nullptr);
}

// round 11
// speedup vs baseline: 4.8130x; 1.0520x over previous
#include <cuda_runtime.h>
#include <cuda_fp16.h>
#include <math_constants.h>
#include <cstdint>
#include <cstddef>

// ---------------------------------------------------------------------------
// Problem constants
// ---------------------------------------------------------------------------
#define Dm   512
#define Sm   64
#define Lm   256
#define Fm   2048
#define Hh   64
#define Cc   8
#define Pp   (Sm * Lm)          // 16384 spatial positions
#define EPS  1e-5f

// ---------------------------------------------------------------------------
// Scratch buffers (static device globals -- allocation-free)
// ---------------------------------------------------------------------------
__device__ __align__(256) float  g_out1[(long)Dm * Pp];
__device__ __align__(256) __half g_tmph[(long)Dm * Pp];      // row_out / col_out / ff2 (fp16)

// fp16 operands (all single-plane)
__device__ __align__(256) __half g_qkv16[3L * Dm * Pp];      // qkv fp16 [1536][16384]
__device__ __align__(256) __half g_bt [(long)Pp * Dm];       // act^T [Pp,512]
__device__ __align__(256) __half g_ff [(long)Pp * Fm];       // ff1^T [Pp,2048]
__device__ __align__(256) __half g_wr [3 * Dm * Dm];
__device__ __align__(256) __half g_wc [3 * Dm * Dm];
__device__ __align__(256) __half g_f1 [Fm * Dm];
__device__ __align__(256) __half g_f2 [Dm * Fm];
__device__ __align__(256) __half g_qt [(long)Hh * Lm * Dm];  // Q^T per head
__device__ __align__(256) __half g_kt [(long)Hh * Lm * Dm];  // K^T per head
__device__ __align__(256) __half g_p16[(long)Hh * Lm * Lm];  // P [h][i][j]

// ---------------------------------------------------------------------------
// PTX helpers
// ---------------------------------------------------------------------------
__device__ __forceinline__ uint32_t smem_u32(const void* p) {
    uint32_t a;
    asm("{ .reg .u64 t; cvta.to.shared.u64 t, %1; cvt.u32.u64 %0, t; }" : "=r"(a) : "l"(p));
    return a;
}
__device__ __forceinline__ void cpasync16(uint32_t dst, const void* src) {
    asm volatile("cp.async.cg.shared.global [%0], [%1], 16;" :: "r"(dst), "l"(src));
}
__device__ __forceinline__ void cp_commit() {
    asm volatile("cp.async.commit_group;" ::: "memory");
}
template<int N>
__device__ __forceinline__ void cp_wait() {
    asm volatile("cp.async.wait_group %0;" :: "n"(N) : "memory");
}
__device__ __forceinline__ void ldsm4(uint32_t* r, uint32_t addr) {
    asm volatile("ldmatrix.sync.aligned.m8n8.x4.shared.b16 {%0,%1,%2,%3}, [%4];"
                 : "=r"(r[0]), "=r"(r[1]), "=r"(r[2]), "=r"(r[3]) : "r"(addr));
}
__device__ __forceinline__ void mma16816h(float* d, const uint32_t* a, uint32_t b0, uint32_t b1) {
    asm volatile("mma.sync.aligned.m16n8k16.row.col.f32.f16.f16.f32 "
                 "{%0,%1,%2,%3}, {%4,%5,%6,%7}, {%8,%9}, {%0,%1,%2,%3};"
                 : "+f"(d[0]), "+f"(d[1]), "+f"(d[2]), "+f"(d[3])
                 : "r"(a[0]), "r"(a[1]), "r"(a[2]), "r"(a[3]), "r"(b0), "r"(b1));
}

// ---------------------------------------------------------------------------
// Big GEMM: C[M,N] = W[M,K] * B[N,K]^T (+bias), single fp16 pass.
// CTA tile 128x128, BK=64, 3-stage ring (96KB), 8 warps (4m x 2n), 2 CTAs/SM.
//   MODE 0: C fp32 [M,N] + bias.
//   MODE 1: relu(+bias) -> fp16 transposed [N,M].
//   MODE 2: fp16 [M,N] + bias.
// ---------------------------------------------------------------------------
#define MM_SBYTES 32768u
#define MM_SMEM   (3 * MM_SBYTES)

template<int MODE>
__global__ void __launch_bounds__(256, 2)
gemm_mma(const __half* __restrict__ A, const __half* __restrict__ B,
         const float* __restrict__ bias,
         float* __restrict__ C, __half* __restrict__ oH,
         int M, int N, int K)
{
    extern __shared__ char smem[];
    const uint32_t sb = smem_u32(smem);

    const int tid  = threadIdx.x;
    const int wid  = tid >> 5;
    const int lane = tid & 31;
    const int warpM = wid & 3;
    const int warpN = wid >> 2;
    const int bm = blockIdx.x * 128;
    const int bn = blockIdx.y * 128;

    auto load_stage = [&](int st, int it) {
        const uint32_t sbase = sb + st * MM_SBYTES;
        const int k0 = it << 6;
#pragma unroll
        for (int j = 0; j < 4; j++) {
            const int idx = tid + j * 256;
            const int row = idx >> 3;
            const int c   = idx & 7;
            const uint32_t soff = row * 128 + ((c * 16) ^ ((row & 7) << 4));
            cpasync16(sbase +         soff, A + (size_t)(bm + row) * K + k0 + c * 8);
            cpasync16(sbase + 16384 + soff, B + (size_t)(bn + row) * K + k0 + c * 8);
        }
    };

    float acc[2][8][4];
#pragma unroll
    for (int i = 0; i < 2; i++)
#pragma unroll
        for (int j = 0; j < 8; j++)
#pragma unroll
            for (int v = 0; v < 4; v++) acc[i][j][v] = 0.f;

    const int nIter = K >> 6;
    load_stage(0, 0); cp_commit();
    load_stage(1, 1); cp_commit();

    const int rsub  = lane & 15;
    const int khalf = ((lane >> 4) & 1) * 16;
    const int rA = warpM * 32 + rsub;
    const int rB = warpN * 64 + rsub;
    const uint32_t xA = (rA & 7) << 4;
    const uint32_t xB = (rB & 7) << 4;

    for (int it = 0; it < nIter; it++) {
        cp_wait<1>();
        __syncthreads();
        if (it + 2 < nIter) load_stage((it + 2) % 3, it + 2);
        cp_commit();

        const uint32_t sbase = sb + (it % 3) * MM_SBYTES;
        const uint32_t pA = sbase +         rA * 128;
        const uint32_t pB = sbase + 16384 + rB * 128;

#pragma unroll
        for (int q = 0; q < 4; q++) {
            const uint32_t kb = q * 32 + khalf;
            uint32_t ah[2][4], bb[4][4];
#pragma unroll
            for (int mt = 0; mt < 2; mt++)
                ldsm4(ah[mt], pA + mt * 2048 + (kb ^ xA));
#pragma unroll
            for (int g = 0; g < 4; g++)
                ldsm4(bb[g], pB + g * 2048 + (kb ^ xB));
#pragma unroll
            for (int mt = 0; mt < 2; mt++)
#pragma unroll
                for (int nt = 0; nt < 8; nt++) {
                    const int g = nt >> 1, o = nt & 1;
                    mma16816h(acc[mt][nt], ah[mt], bb[g][o], bb[g][o + 2]);
                }
        }
    }
    cp_wait<0>();
    __syncthreads();

    if (MODE == 0) {
#pragma unroll
        for (int mt = 0; mt < 2; mt++) {
            const int r0 = bm + warpM * 32 + mt * 16 + (lane >> 2);
            const float bv0 = bias[r0], bv1 = bias[r0 + 8];
#pragma unroll
            for (int nt = 0; nt < 8; nt++) {
                const int c0 = bn + warpN * 64 + nt * 8 + (lane & 3) * 2;
                float* d = acc[mt][nt];
                *reinterpret_cast<float2*>(&C[(size_t)r0 * N + c0])       = make_float2(d[0] + bv0, d[1] + bv0);
                *reinterpret_cast<float2*>(&C[(size_t)(r0 + 8) * N + c0]) = make_float2(d[2] + bv1, d[3] + bv1);
            }
        }
    } else if (MODE == 2) {
#pragma unroll
        for (int mt = 0; mt < 2; mt++) {
            const int r0 = bm + warpM * 32 + mt * 16 + (lane >> 2);
            const float bv0 = bias[r0], bv1 = bias[r0 + 8];
#pragma unroll
            for (int nt = 0; nt < 8; nt++) {
                const int c0 = bn + warpN * 64 + nt * 8 + (lane & 3) * 2;
                float* d = acc[mt][nt];
                *reinterpret_cast<__half2*>(&oH[(size_t)r0 * N + c0])       = __floats2half2_rn(d[0] + bv0, d[1] + bv0);
                *reinterpret_cast<__half2*>(&oH[(size_t)(r0 + 8) * N + c0]) = __floats2half2_rn(d[2] + bv1, d[3] + bv1);
            }
        }
    } else {
        float* T = reinterpret_cast<float*>(smem);   // [128][130]
#pragma unroll
        for (int mt = 0; mt < 2; mt++) {
            const int lr0 = warpM * 32 + mt * 16 + (lane >> 2);
            const float bv0 = bias[bm + lr0], bv1 = bias[bm + lr0 + 8];
#pragma unroll
            for (int nt = 0; nt < 8; nt++) {
                const int lc0 = warpN * 64 + nt * 8 + (lane & 3) * 2;
                float* d = acc[mt][nt];
                T[lr0 * 130 + lc0]           = fmaxf(d[0] + bv0, 0.f);
                T[lr0 * 130 + lc0 + 1]       = fmaxf(d[1] + bv0, 0.f);
                T[(lr0 + 8) * 130 + lc0]     = fmaxf(d[2] + bv1, 0.f);
                T[(lr0 + 8) * 130 + lc0 + 1] = fmaxf(d[3] + bv1, 0.f);
            }
        }
        __syncthreads();
        const int mloc = tid & 127;
#pragma unroll 4
        for (int rep = 0; rep < 64; rep++) {
            const int nl = rep * 2 + (tid >> 7);
            oH[(size_t)(bn + nl) * M + bm + mloc] = __float2half(T[mloc * 130 + nl]);
        }
    }
}

// ---------------------------------------------------------------------------
// Row-attention scores + FUSED softmax: per head tile 64(i) x 256(j), K=512.
// 2-stage ring (80KB) -> 2 CTAs/SM.
// ---------------------------------------------------------------------------
#define SC_SBYTES 40960u
#define SC_SMEM   (2 * SC_SBYTES)

__global__ void __launch_bounds__(256, 2)
gemm_scores(const __half* __restrict__ Q, const __half* __restrict__ Kt,
            __half* __restrict__ P)
{
    constexpr int K = 512;
    extern __shared__ char smem[];
    const uint32_t sb = smem_u32(smem);

    const int tid = threadIdx.x, wid = tid >> 5, lane = tid & 31;
    const int warpM = wid & 3;
    const int warpN = wid >> 2;
    const int bm = blockIdx.x * 64;
    const int h = blockIdx.z;
    const __half* A = Q  + (size_t)h * Lm * Dm;
    const __half* B = Kt + (size_t)h * Lm * Dm;

    auto load_stage = [&](int st, int it) {
        const uint32_t sbase = sb + st * SC_SBYTES;
        const int k0 = it << 6;
#pragma unroll
        for (int j = 0; j < 10; j++) {
            const int idx = tid + j * 256;
            if (idx < 512) {
                const int row = idx >> 3, c = idx & 7;
                const uint32_t soff = row * 128 + ((c * 16) ^ ((row & 7) << 4));
                cpasync16(sbase + soff, A + (size_t)(bm + row) * K + k0 + c * 8);
            } else {
                const int i2 = idx - 512;
                const int row = i2 >> 3, c = i2 & 7;
                const uint32_t soff = row * 128 + ((c * 16) ^ ((row & 7) << 4));
                cpasync16(sbase + 8192 + soff, B + (size_t)row * K + k0 + c * 8);
            }
        }
    };

    float acc[16][4];
#pragma unroll
    for (int j = 0; j < 16; j++)
#pragma unroll
        for (int v = 0; v < 4; v++) acc[j][v] = 0.f;

    load_stage(0, 0); cp_commit();
    load_stage(1, 1); cp_commit();

    const int rsub  = lane & 15;
    const int khalf = ((lane >> 4) & 1) * 16;
    const int rA = warpM * 16 + rsub;
    const int rBb = warpN * 128 + rsub;
    const uint32_t xs = (rsub & 7) << 4;

    for (int it = 0; it < 8; it++) {
        cp_wait<1>();
        __syncthreads();

        const uint32_t sbase = sb + (it & 1) * SC_SBYTES;
        const uint32_t pA = sbase +        rA  * 128;
        const uint32_t pB = sbase + 8192 + rBb * 128;

#pragma unroll
        for (int q = 0; q < 4; q++) {
            const uint32_t kb = q * 32 + khalf;
            uint32_t ah[4], bb[8][4];
            ldsm4(ah, pA + (kb ^ xs));
#pragma unroll
            for (int g = 0; g < 8; g++)
                ldsm4(bb[g], pB + g * 2048 + (kb ^ xs));
#pragma unroll
            for (int nt = 0; nt < 16; nt++) {
                const int g = nt >> 1, o = nt & 1;
                mma16816h(acc[nt], ah, bb[g][o], bb[g][o + 2]);
            }
        }
        __syncthreads();
        if (it + 2 < 8) { load_stage(it & 1, it + 2); }
        cp_commit();
    }
    cp_wait<0>();
    __syncthreads();

    float* S = reinterpret_cast<float*>(smem);
    {
        const int r0 = warpM * 16 + (lane >> 2);
#pragma unroll
        for (int nt = 0; nt < 16; nt++) {
            const int c0 = warpN * 128 + nt * 8 + (lane & 3) * 2;
            float* d = acc[nt];
            S[r0 * 260 + c0]           = d[0];
            S[r0 * 260 + c0 + 1]       = d[1];
            S[(r0 + 8) * 260 + c0]     = d[2];
            S[(r0 + 8) * 260 + c0 + 1] = d[3];
        }
    }
    __syncthreads();

#pragma unroll
    for (int rr = 0; rr < 8; rr++) {
        const int r = wid * 8 + rr;
        float v[8];
#pragma unroll
        for (int k = 0; k < 8; k++) v[k] = S[r * 260 + lane + 32 * k];
        float m = v[0];
#pragma unroll
        for (int k = 1; k < 8; k++) m = fmaxf(m, v[k]);
#pragma unroll
        for (int o = 16; o; o >>= 1) m = fmaxf(m, __shfl_xor_sync(0xffffffffu, m, o));
        float s = 0.f;
#pragma unroll
        for (int k = 0; k < 8; k++) { v[k] = __expf(v[k] - m); s += v[k]; }
#pragma unroll
        for (int o = 16; o; o >>= 1) s += __shfl_xor_sync(0xffffffffu, s, o);
        const float inv = 1.f / s;
        __half* dst = P + ((size_t)h * Lm + bm + r) * Lm;
#pragma unroll
        for (int k = 0; k < 8; k++) dst[lane + 32 * k] = __float2half(v[k] * inv);
    }
}

// ---------------------------------------------------------------------------
// Row-attention output: per head, C[m=(c,s), i] = sum_j V[m,j] * P[i,j]. fp16 out.
// ---------------------------------------------------------------------------
__global__ void __launch_bounds__(256, 2)
gemm_vp(const __half* __restrict__ V, const __half* __restrict__ P,
        __half* __restrict__ O)
{
    constexpr int K = 256;
    extern __shared__ char smem[];
    const uint32_t sb = smem_u32(smem);

    const int tid = threadIdx.x, wid = tid >> 5, lane = tid & 31;
    const int warpM = wid & 3, warpN = wid >> 2;
    const int bm = blockIdx.x * 128, bn = blockIdx.y * 128;
    const int h = blockIdx.z;
    const __half* Av = V + (size_t)h * 8 * Pp;
    const __half* Bp = P + (size_t)h * Lm * Lm;
    __half* C = O + (size_t)h * 8 * Pp;

    auto load_stage = [&](int st, int it) {
        const uint32_t sbase = sb + st * MM_SBYTES;
        const int k0 = it << 6;
#pragma unroll
        for (int j = 0; j < 4; j++) {
            const int idx = tid + j * 256;
            const int row = idx >> 3;
            const int c   = idx & 7;
            const uint32_t soff = row * 128 + ((c * 16) ^ ((row & 7) << 4));
            const int mrow = bm + row;
            const size_t ga = (size_t)(mrow >> 6) * Pp + (mrow & 63) * 256 + k0 + c * 8;
            cpasync16(sbase +         soff, Av + ga);
            cpasync16(sbase + 16384 + soff, Bp + (size_t)(bn + row) * K + k0 + c * 8);
        }
    };

    float acc[2][8][4];
#pragma unroll
    for (int i = 0; i < 2; i++)
#pragma unroll
        for (int j = 0; j < 8; j++)
#pragma unroll
            for (int v = 0; v < 4; v++) acc[i][j][v] = 0.f;

    load_stage(0, 0); cp_commit();
    load_stage(1, 1); cp_commit();

    const int rsub  = lane & 15;
    const int khalf = ((lane >> 4) & 1) * 16;
    const int rA = warpM * 32 + rsub;
    const int rB = warpN * 64 + rsub;
    const uint32_t xA = (rA & 7) << 4;
    const uint32_t xB = (rB & 7) << 4;

    for (int it = 0; it < 4; it++) {
        cp_wait<1>();
        __syncthreads();
        if (it + 2 < 4) load_stage((it + 2) % 3, it + 2);
        cp_commit();

        const uint32_t sbase = sb + (it % 3) * MM_SBYTES;
        const uint32_t pA = sbase +         rA * 128;
        const uint32_t pB = sbase + 16384 + rB * 128;

#pragma unroll
        for (int q = 0; q < 4; q++) {
            const uint32_t kb = q * 32 + khalf;
            uint32_t av[2][4], bb[4][4];
#pragma unroll
            for (int mt = 0; mt < 2; mt++)
                ldsm4(av[mt], pA + mt * 2048 + (kb ^ xA));
#pragma unroll
            for (int g = 0; g < 4; g++)
                ldsm4(bb[g], pB + g * 2048 + (kb ^ xB));
#pragma unroll
            for (int mt = 0; mt < 2; mt++)
#pragma unroll
                for (int nt = 0; nt < 8; nt++) {
                    const int g = nt >> 1, o = nt & 1;
                    mma16816h(acc[mt][nt], av[mt], bb[g][o], bb[g][o + 2]);
                }
        }
    }
    cp_wait<0>();
    __syncthreads();

#pragma unroll
    for (int mt = 0; mt < 2; mt++) {
        const int r0 = bm + warpM * 32 + mt * 16 + (lane >> 2);
        const int r1 = r0 + 8;
        const size_t a0 = (size_t)(r0 >> 6) * Pp + (r0 & 63) * 256;
        const size_t a1 = (size_t)(r1 >> 6) * Pp + (r1 & 63) * 256;
#pragma unroll
        for (int nt = 0; nt < 8; nt++) {
            const int c0 = bn + warpN * 64 + nt * 8 + (lane & 3) * 2;
            float* d = acc[mt][nt];
            *reinterpret_cast<__half2*>(&C[a0 + c0]) = __floats2half2_rn(d[0], d[1]);
            *reinterpret_cast<__half2*>(&C[a1 + c0]) = __floats2half2_rn(d[2], d[3]);
        }
    }
}

// ---------------------------------------------------------------------------
// Merged weight conversion
// ---------------------------------------------------------------------------
#define WN1 (3 * Dm * Dm)
#define WN2 (2 * WN1)
#define WN3 (WN2 + Fm * Dm)
#define WN4 (WN3 + Dm * Fm)

__global__ void convw_all(const float* __restrict__ w_row, const float* __restrict__ w_col,
                          const float* __restrict__ wf1, const float* __restrict__ wf2,
                          __half* __restrict__ owr, __half* __restrict__ owc,
                          __half* __restrict__ of1, __half* __restrict__ of2)
{
    const long i = ((long)blockIdx.x * 256 + threadIdx.x) * 4;
    const float* src; __half* dst; long off;
    if (i < WN1)      { src = w_row; dst = owr; off = 0; }
    else if (i < WN2) { src = w_col; dst = owc; off = WN1; }
    else if (i < WN3) { src = wf1;   dst = of1; off = WN2; }
    else              { src = wf2;   dst = of2; off = WN3; }
    const long j = i - off;
    const float4 v = *reinterpret_cast<const float4*>(src + j);
    *reinterpret_cast<__half2*>(dst + j)     = __floats2half2_rn(v.x, v.y);
    *reinterpret_cast<__half2*>(dst + j + 2) = __floats2half2_rn(v.z, v.w);
}

// act fp32 [K, N] -> fp16 [N, K] (transposed) — only for the initial x
__global__ void __launch_bounds__(256)
convt_kernel(const float* __restrict__ in, __half* __restrict__ oh, int K, int N)
{
    __shared__ float t[32][33];
    const int n0 = blockIdx.x * 32, k0 = blockIdx.y * 32;
    const int tx = threadIdx.x, ty = threadIdx.y;
#pragma unroll
    for (int i = 0; i < 4; i++)
        t[ty + 8 * i][tx] = in[(size_t)(k0 + ty + 8 * i) * N + n0 + tx];
    __syncthreads();
#pragma unroll
    for (int i = 0; i < 4; i++) {
        const int r = ty + 8 * i;
        oh[(size_t)(n0 + r) * K + k0 + tx] = __float2half(t[tx][r]);
    }
}
// Q/K per-head transpose (fp16 in, fp16 out)
__global__ void __launch_bounds__(256)
convtqk_kernel(const __half* __restrict__ qkv,
               __half* __restrict__ qo, __half* __restrict__ ko)
{
    __shared__ __half t[32][34];
    const int h = blockIdx.z >> 1;
    const int isK = blockIdx.z & 1;
    const __half* in = qkv + (isK ? (size_t)Dm * Pp : 0) + (size_t)h * 8 * Pp;
    __half* o = (isK ? ko : qo) + (size_t)h * Lm * Dm;
    const int l0 = blockIdx.x * 32, k0 = blockIdx.y * 32;
    const int tx = threadIdx.x, ty = threadIdx.y;
#pragma unroll
    for (int i = 0; i < 4; i++) {
        const int k = k0 + ty + 8 * i;
        t[ty + 8 * i][tx] = in[(size_t)(k >> 6) * Pp + (k & 63) * 256 + l0 + tx];
    }
    __syncthreads();
#pragma unroll
    for (int i = 0; i < 4; i++) {
        const int r = ty + 8 * i;
        o[(size_t)(l0 + r) * Dm + k0 + tx] = t[tx][r];
    }
}

// ---------------------------------------------------------------------------
// Channel LayerNorm over D=512: vals = in(fp32) + res(fp16); LN(w1,b1);
// if DOUBLE, a second LN(w2,b2) on the result. Optional fp32 out + fp16^T out.
// ---------------------------------------------------------------------------
template<bool DOUBLE>
__global__ __launch_bounds__(256)
void ln_kernel(const float* __restrict__ in, const __half* __restrict__ res,
               const float* __restrict__ w1, const float* __restrict__ b1,
               const float* __restrict__ w2, const float* __restrict__ b2,
               float* __restrict__ out, __half* __restrict__ obt)
{
    __shared__ float ss[8][32], ss2[8][32];
    __shared__ __half tbuf[32][514];
    const int tx = threadIdx.x, ty = threadIdx.y;
    const int tid = ty * 32 + tx;
    const int pos0 = blockIdx.x * 32;
    const int pos = pos0 + tx;

    float vals[64];
    float s = 0.f, s2 = 0.f;
#pragma unroll
    for (int i = 0; i < 64; i++) {
        const int c = ty + 8 * i;
        float v = in[(size_t)c * Pp + pos];
        if (res) v += __half2float(res[(size_t)c * Pp + pos]);
        vals[i] = v; s += v; s2 += v * v;
    }
    ss[ty][tx] = s; ss2[ty][tx] = s2;
    __syncthreads();
    {
        float st = 0.f, st2 = 0.f;
#pragma unroll
        for (int y = 0; y < 8; y++) { st += ss[y][tx]; st2 += ss2[y][tx]; }
        const float mean = st * (1.f / Dm);
        const float var  = st2 * (1.f / Dm) - mean * mean;
        const float rstd = rsqrtf(var + EPS);
#pragma unroll
        for (int i = 0; i < 64; i++) {
            const int c = ty + 8 * i;
            vals[i] = (vals[i] - mean) * rstd * w1[c] + b1[c];
        }
    }
    if (DOUBLE) {
        float t = 0.f, t2 = 0.f;
#pragma unroll
        for (int i = 0; i < 64; i++) { t += vals[i]; t2 += vals[i] * vals[i]; }
        __syncthreads();
        ss[ty][tx] = t; ss2[ty][tx] = t2;
        __syncthreads();
        float st = 0.f, st2 = 0.f;
#pragma unroll
        for (int y = 0; y < 8; y++) { st += ss[y][tx]; st2 += ss2[y][tx]; }
        const float mean = st * (1.f / Dm);
        const float var  = st2 * (1.f / Dm) - mean * mean;
        const float rstd = rsqrtf(var + EPS);
#pragma unroll
        for (int i = 0; i < 64; i++) {
            const int c = ty + 8 * i;
            vals[i] = (vals[i] - mean) * rstd * w2[c] + b2[c];
        }
    }
#pragma unroll
    for (int i = 0; i < 64; i++) {
        const int c = ty + 8 * i;
        out[(size_t)c * Pp + pos] = vals[i];
        if (obt) tbuf[tx][c] = __float2half(vals[i]);
    }
    if (obt) {
        __syncthreads();
#pragma unroll 4
        for (int r = 0; r < 32; r++) {
            const uint32_t val = *reinterpret_cast<const uint32_t*>(&tbuf[r][tid * 2]);
            *reinterpret_cast<uint32_t*>(&obt[(size_t)(pos0 + r) * Dm + tid * 2]) = val;
        }
    }
}

// ---------------------------------------------------------------------------
// Column attention (fp16 qkv) — fp16 output.
// ---------------------------------------------------------------------------
__global__ __launch_bounds__(512)
void colattn_kernel(const __half* __restrict__ qkv, __half* __restrict__ out)
{
    const int h = blockIdx.z;
    const int l = blockIdx.x * 32 + threadIdx.x;
    const int ty = threadIdx.y;
    const __half* Q  = qkv + (size_t)h * Cc * Pp;
    const __half* Kp = Q + (size_t)Dm * Pp;
    const __half* V  = Q + 2L * (size_t)Dm * Pp;

    float q[4][Cc];
#pragma unroll
    for (int ii = 0; ii < 4; ii++) {
        const int i = ty + 16 * ii;
#pragma unroll
        for (int c = 0; c < Cc; c++) q[ii][c] = __half2float(Q[(size_t)c * Pp + i * Lm + l]);
    }

    float d[4] = {0.f, 0.f, 0.f, 0.f};
    float acc[4][Cc];
#pragma unroll
    for (int ii = 0; ii < 4; ii++)
#pragma unroll
        for (int c = 0; c < Cc; c++) acc[ii][c] = 0.f;

    for (int j = 0; j < Sm; j++) {
        float kv[Cc], vv[Cc];
#pragma unroll
        for (int c = 0; c < Cc; c++) {
            kv[c] = __half2float(Kp[(size_t)c * Pp + j * Lm + l]);
            vv[c] = __half2float(V [(size_t)c * Pp + j * Lm + l]);
        }
#pragma unroll
        for (int ii = 0; ii < 4; ii++) {
            float sc = 0.f;
#pragma unroll
            for (int c = 0; c < Cc; c++) sc = fmaf(q[ii][c], kv[c], sc);
            const float e = __expf(sc);
            d[ii] += e;
#pragma unroll
            for (int c = 0; c < Cc; c++) acc[ii][c] = fmaf(e, vv[c], acc[ii][c]);
        }
    }
#pragma unroll
    for (int ii = 0; ii < 4; ii++) {
        const int i = ty + 16 * ii;
        const float inv = 1.f / d[ii];
#pragma unroll
        for (int c = 0; c < Cc; c++)
            out[(size_t)(h * Cc + c) * Pp + i * Lm + l] = __float2half(acc[ii][c] * inv);
    }
}

// ---------------------------------------------------------------------------
// Host side
// ---------------------------------------------------------------------------
extern "C" void kernel_launch(void* const* d_in, const int* in_sizes, int n_in,
                              void* d_out, int out_size)
{
    const float* x     = (const float*)d_in[0];
    const float* w_row = (const float*)d_in[1];
    const float* b_row = (const float*)d_in[2];
    const float* w_col = (const float*)d_in[3];
    const float* b_col = (const float*)d_in[4];
    const float* w_an1 = (const float*)d_in[5];
    const float* b_an1 = (const float*)d_in[6];
    const float* w_an2 = (const float*)d_in[7];
    const float* b_an2 = (const float*)d_in[8];
    const float* w_ff1 = (const float*)d_in[9];
    const float* b_ff1 = (const float*)d_in[10];
    const float* w_ff2 = (const float*)d_in[11];
    const float* b_ff2 = (const float*)d_in[12];
    const float* w_ln1 = (const float*)d_in[13];
    const float* b_ln1 = (const float*)d_in[14];
    const float* w_ln2 = (const float*)d_in[15];
    const float* b_ln2 = (const float*)d_in[16];
    float* outp = (float*)d_out;

    float *out1;
    __half *tmph, *qkv16, *bt, *ff, *wr, *wc, *f1, *f2, *qt, *kt, *p16;
    cudaGetSymbolAddress((void**)&out1,  g_out1);
    cudaGetSymbolAddress((void**)&tmph,  g_tmph);
    cudaGetSymbolAddress((void**)&qkv16, g_qkv16);
    cudaGetSymbolAddress((void**)&bt,    g_bt);
    cudaGetSymbolAddress((void**)&ff,    g_ff);
    cudaGetSymbolAddress((void**)&wr,    g_wr);
    cudaGetSymbolAddress((void**)&wc,    g_wc);
    cudaGetSymbolAddress((void**)&f1,    g_f1);
    cudaGetSymbolAddress((void**)&f2,    g_f2);
    cudaGetSymbolAddress((void**)&qt,    g_qt);
    cudaGetSymbolAddress((void**)&kt,    g_kt);
    cudaGetSymbolAddress((void**)&p16,   g_p16);

    cudaFuncSetAttribute(gemm_mma<0>, cudaFuncAttributeMaxDynamicSharedMemorySize, MM_SMEM);
    cudaFuncSetAttribute(gemm_mma<1>, cudaFuncAttributeMaxDynamicSharedMemorySize, MM_SMEM);
    cudaFuncSetAttribute(gemm_mma<2>, cudaFuncAttributeMaxDynamicSharedMemorySize, MM_SMEM);
    cudaFuncSetAttribute(gemm_scores, cudaFuncAttributeMaxDynamicSharedMemorySize, SC_SMEM);
    cudaFuncSetAttribute(gemm_vp,     cudaFuncAttributeMaxDynamicSharedMemorySize, MM_SMEM);

    // merged weight conversion
    convw_all<<<WN4 / 1024, 256>>>(w_row, w_col, w_ff1, w_ff2, wr, wc, f1, f2);

    // x -> transposed fp16
    convt_kernel<<<dim3(Pp / 32, Dm / 32), dim3(32, 8)>>>(x, bt, Dm, Pp);

    // 1) row qkv -> fp16
    gemm_mma<2><<<dim3((3 * Dm) / 128, Pp / 128), 256, MM_SMEM>>>(
        wr, bt, b_row, nullptr, qkv16, 3 * Dm, Pp, Dm);

    // 2) Q/K transpose
    convtqk_kernel<<<dim3(Lm / 32, Dm / 32, 2 * Hh), dim3(32, 8)>>>(qkv16, qt, kt);

    // 3) scores + fused softmax -> P fp16
    gemm_scores<<<dim3(Lm / 64, 1, Hh), 256, SC_SMEM>>>(qt, kt, p16);

    // 4) row_out = V * P^T -> fp16 tmph
    gemm_vp<<<dim3(4, 2, Hh), 256, MM_SMEM>>>(qkv16 + 2L * Dm * Pp, p16, tmph);

    // 5) out1 = LN(x + row_out; an1), + bt
    ln_kernel<false><<<Pp / 32, dim3(32, 8)>>>(x, tmph, w_an1, b_an1, nullptr, nullptr, out1, bt);

    // 6) col qkv -> fp16
    gemm_mma<2><<<dim3((3 * Dm) / 128, Pp / 128), 256, MM_SMEM>>>(
        wc, bt, b_col, nullptr, qkv16, 3 * Dm, Pp, Dm);

    // 7) column attention -> fp16 tmph
    colattn_kernel<<<dim3(Lm / 32, 1, Hh), dim3(32, 16)>>>(qkv16, tmph);

    // 8+9) h = LN(LN(out1 + col_out; an2); ln1) fused, + bt. out1 overwritten with h.
    ln_kernel<true><<<Pp / 32, dim3(32, 8)>>>(out1, tmph, w_an2, b_an2, w_ln1, b_ln1, out1, bt);

    // 10) ff1: relu(w_ff1 @ h + b_ff1) -> fp16 transposed
    gemm_mma<1><<<dim3(Fm / 128, Pp / 128), 256, MM_SMEM>>>(
        f1, bt, b_ff1, nullptr, ff, Fm, Pp, Dm);

    // 11) ff2 -> fp16 tmph
    gemm_mma<2><<<dim3(Dm / 128, Pp / 128), 256, MM_SMEM>>>(
        f2, ff, b_ff2, nullptr, tmph, Dm, Pp, Fm);

    // 12) out = LN(h + ff2; ln2)
    ln_kernel<false><<<Pp / 32, dim3(32, 8)>>>(out1, tmph, w_ln2, b_ln2, nullptr, nullptr, outp, nullptr);
}